// round 2
// baseline (speedup 1.0000x reference)
#include <cuda_runtime.h>

#define N_NODES 10000
#define N_EDGES 160000
#define HID 256
#define NBOND 6
#define NATOM 62
#define NLAYERS 6

// Scratch (device globals — no allocation allowed)
__device__ float g_x[N_NODES * HID];
__device__ float g_xa[N_NODES * HID];
__device__ float g_xb[N_NODES * HID];
__device__ float g_agg[N_NODES * HID];
__device__ float g_t1[N_NODES * HID];
__device__ float g_h[N_NODES * HID];

// ---------------------------------------------------------------------------
// Embed: x = atom @ embed_w + embed_b   [10000,62]x[62,256]
// ---------------------------------------------------------------------------
#define EMB_NODES 16
__global__ void __launch_bounds__(256) embed_kernel(
    const float* __restrict__ atom, const float* __restrict__ w,
    const float* __restrict__ b)
{
    __shared__ float s_af[EMB_NODES][NATOM];
    int n0 = blockIdx.x * EMB_NODES;
    int tid = threadIdx.x;
    for (int i = tid; i < EMB_NODES * NATOM; i += 256) {
        int r = i / NATOM, c = i % NATOM;
        int n = n0 + r;
        s_af[r][c] = (n < N_NODES) ? atom[(size_t)n * NATOM + c] : 0.f;
    }
    __syncthreads();
    int j = tid;  // output column 0..255
    float acc[EMB_NODES];
    float bj = b[j];
#pragma unroll
    for (int r = 0; r < EMB_NODES; r++) acc[r] = bj;
    for (int k = 0; k < NATOM; k++) {
        float wv = w[k * HID + j];
#pragma unroll
        for (int r = 0; r < EMB_NODES; r++) acc[r] = fmaf(s_af[r][k], wv, acc[r]);
    }
#pragma unroll
    for (int r = 0; r < EMB_NODES; r++) {
        int n = n0 + r;
        if (n < N_NODES) g_x[(size_t)n * HID + j] = acc[r];
    }
}

// ---------------------------------------------------------------------------
// Generic SGEMM: C[M,N] = op(A[M,256] @ W[256,N] (+bias) (+Cprev)), opt ReLU
// BM=128, BN=128, BK=16, 256 threads, 8x8 per-thread microtile (4+4 split).
// ---------------------------------------------------------------------------
template <bool RELU, bool ADDC, bool HASBIAS>
__global__ void __launch_bounds__(256) gemm256(
    const float* __restrict__ A, const float* __restrict__ W,
    const float* __restrict__ bias, const float* __restrict__ Cprev,
    float* __restrict__ C, int M, int N)
{
    __shared__ float As[16][128];  // [k][m]
    __shared__ float Ws[16][128];  // [k][n]
    const int K = 256;
    int col0 = blockIdx.x * 128, row0 = blockIdx.y * 128;
    int tid = threadIdx.x;
    int tx = tid & 15, ty = tid >> 4;

    float acc[8][8];
#pragma unroll
    for (int i = 0; i < 8; i++)
#pragma unroll
        for (int j = 0; j < 8; j++) acc[i][j] = 0.f;

    int ar = tid >> 2;           // 0..63 (+64)
    int ac = (tid & 3) << 2;     // 0,4,8,12
    int wr = tid >> 5;           // 0..7 (+8)
    int wc = (tid & 31) << 2;    // 0..124

    for (int kt = 0; kt < K; kt += 16) {
#pragma unroll
        for (int i = 0; i < 2; i++) {
            int r = ar + i * 64;
            int grow = row0 + r;
            float4 v = make_float4(0.f, 0.f, 0.f, 0.f);
            if (grow < M) v = *(const float4*)(A + (size_t)grow * K + kt + ac);
            As[ac + 0][r] = v.x; As[ac + 1][r] = v.y;
            As[ac + 2][r] = v.z; As[ac + 3][r] = v.w;
        }
#pragma unroll
        for (int i = 0; i < 2; i++) {
            int r = wr + i * 8;
            *(float4*)&Ws[r][wc] =
                *(const float4*)(W + (size_t)(kt + r) * N + col0 + wc);
        }
        __syncthreads();
#pragma unroll
        for (int kk = 0; kk < 16; kk++) {
            float4 a0 = *(const float4*)&As[kk][ty * 4];
            float4 a1 = *(const float4*)&As[kk][64 + ty * 4];
            float4 w0 = *(const float4*)&Ws[kk][tx * 4];
            float4 w1 = *(const float4*)&Ws[kk][64 + tx * 4];
            float af[8] = {a0.x, a0.y, a0.z, a0.w, a1.x, a1.y, a1.z, a1.w};
            float wf[8] = {w0.x, w0.y, w0.z, w0.w, w1.x, w1.y, w1.z, w1.w};
#pragma unroll
            for (int i = 0; i < 8; i++)
#pragma unroll
                for (int j = 0; j < 8; j++)
                    acc[i][j] = fmaf(af[i], wf[j], acc[i][j]);
        }
        __syncthreads();
    }

    int rbase[2] = {row0 + ty * 4, row0 + 64 + ty * 4};
    int cbase[2] = {col0 + tx * 4, col0 + 64 + tx * 4};
#pragma unroll
    for (int ih = 0; ih < 2; ih++)
#pragma unroll
        for (int i = 0; i < 4; i++) {
            int grow = rbase[ih] + i;
            if (grow < M) {
#pragma unroll
                for (int jh = 0; jh < 2; jh++)
#pragma unroll
                    for (int j = 0; j < 4; j++) {
                        int gcol = cbase[jh] + j;
                        float v = acc[ih * 4 + i][jh * 4 + j];
                        if (HASBIAS) v += bias[gcol];
                        if (ADDC) v += Cprev[(size_t)grow * N + gcol];
                        if (RELU) v = fmaxf(v, 0.f);
                        C[(size_t)grow * N + gcol] = v;
                    }
            }
        }
}

// ---------------------------------------------------------------------------
// Fused edge message GEMM + scatter:
//   A[e,:] = relu(xa[src[e]] + xb[dst[e]] + ef[e]@W1c + b1)   (built on the fly)
//   C      = A @ W2 + b2 ; atomicAdd into agg[dst[e]]
// Tile: 128 edges x 128 cols, K=256.
// ---------------------------------------------------------------------------
__global__ void __launch_bounds__(256) edge_msg_gemm(
    const float* __restrict__ xa, const float* __restrict__ xb,
    const int* __restrict__ src, const int* __restrict__ dst,
    const float* __restrict__ ef,
    const float* __restrict__ w1c,  // [6,256]
    const float* __restrict__ b1,   // [256]
    const float* __restrict__ w2,   // [256,256]
    const float* __restrict__ b2,   // [256]
    float* __restrict__ agg)
{
    __shared__ float As[16][128];
    __shared__ float Ws[16][128];
    __shared__ int s_src[128], s_dst[128];
    __shared__ float s_ef[128][NBOND];
    __shared__ float s_w1c[NBOND][256];
    __shared__ float s_b1[256];

    int e0 = blockIdx.y * 128;
    int col0 = blockIdx.x * 128;
    int tid = threadIdx.x;
    int tx = tid & 15, ty = tid >> 4;

    if (tid < 128) {
        s_src[tid] = src[e0 + tid];
        s_dst[tid] = dst[e0 + tid];
    }
    for (int i = tid; i < 128 * NBOND; i += 256)
        s_ef[i / NBOND][i % NBOND] = ef[(size_t)e0 * NBOND + i];
    for (int i = tid; i < NBOND * 256; i += 256)
        s_w1c[i >> 8][i & 255] = w1c[i];
    s_b1[tid] = b1[tid];
    __syncthreads();

    float acc[8][8];
#pragma unroll
    for (int i = 0; i < 8; i++)
#pragma unroll
        for (int j = 0; j < 8; j++) acc[i][j] = 0.f;

    int ar = tid >> 2;
    int ac = (tid & 3) << 2;
    int wr = tid >> 5;
    int wc = (tid & 31) << 2;

    for (int kt = 0; kt < 256; kt += 16) {
#pragma unroll
        for (int i = 0; i < 2; i++) {
            int r = ar + i * 64;
            int k = kt + ac;
            float4 va = *(const float4*)(xa + (size_t)s_src[r] * HID + k);
            float4 vb = *(const float4*)(xb + (size_t)s_dst[r] * HID + k);
            float4 ec = *(const float4*)&s_b1[k];
#pragma unroll
            for (int q = 0; q < NBOND; q++) {
                float e = s_ef[r][q];
                float4 wv = *(const float4*)&s_w1c[q][k];
                ec.x = fmaf(e, wv.x, ec.x);
                ec.y = fmaf(e, wv.y, ec.y);
                ec.z = fmaf(e, wv.z, ec.z);
                ec.w = fmaf(e, wv.w, ec.w);
            }
            As[ac + 0][r] = fmaxf(va.x + vb.x + ec.x, 0.f);
            As[ac + 1][r] = fmaxf(va.y + vb.y + ec.y, 0.f);
            As[ac + 2][r] = fmaxf(va.z + vb.z + ec.z, 0.f);
            As[ac + 3][r] = fmaxf(va.w + vb.w + ec.w, 0.f);
        }
#pragma unroll
        for (int i = 0; i < 2; i++) {
            int r = wr + i * 8;
            *(float4*)&Ws[r][wc] =
                *(const float4*)(w2 + (size_t)(kt + r) * 256 + col0 + wc);
        }
        __syncthreads();
#pragma unroll
        for (int kk = 0; kk < 16; kk++) {
            float4 a0 = *(const float4*)&As[kk][ty * 4];
            float4 a1 = *(const float4*)&As[kk][64 + ty * 4];
            float4 w0 = *(const float4*)&Ws[kk][tx * 4];
            float4 w1 = *(const float4*)&Ws[kk][64 + tx * 4];
            float af[8] = {a0.x, a0.y, a0.z, a0.w, a1.x, a1.y, a1.z, a1.w};
            float wf[8] = {w0.x, w0.y, w0.z, w0.w, w1.x, w1.y, w1.z, w1.w};
#pragma unroll
            for (int i = 0; i < 8; i++)
#pragma unroll
                for (int j = 0; j < 8; j++)
                    acc[i][j] = fmaf(af[i], wf[j], acc[i][j]);
        }
        __syncthreads();
    }

    // epilogue: + b2, scatter-add into agg[dst]
    int rloc[2] = {ty * 4, 64 + ty * 4};
    int cbase[2] = {col0 + tx * 4, col0 + 64 + tx * 4};
    float bv[2][4];
#pragma unroll
    for (int jh = 0; jh < 2; jh++)
#pragma unroll
        for (int j = 0; j < 4; j++) bv[jh][j] = b2[cbase[jh] + j];

#pragma unroll
    for (int ih = 0; ih < 2; ih++)
#pragma unroll
        for (int i = 0; i < 4; i++) {
            int r = rloc[ih] + i;
            float* arow = agg + (size_t)s_dst[r] * HID;
#pragma unroll
            for (int jh = 0; jh < 2; jh++)
#pragma unroll
                for (int j = 0; j < 4; j++) {
                    atomicAdd(arow + cbase[jh] + j,
                              acc[ih * 4 + i][jh * 4 + j] + bv[jh][j]);
                }
        }
}

// ---------------------------------------------------------------------------
// Readout final: out = mean_n( r2[n,:] . w3 + b3 )
// ---------------------------------------------------------------------------
__global__ void __launch_bounds__(256) readout_final(
    const float* __restrict__ r2, const float* __restrict__ w3,
    const float* __restrict__ b3, float* __restrict__ out)
{
    __shared__ float sred[256];
    int n = blockIdx.x * 256 + threadIdx.x;
    float v = 0.f;
    if (n < N_NODES) {
        const float* row = r2 + (size_t)n * 128;
        float s = 0.f;
#pragma unroll
        for (int k = 0; k < 128; k += 4) {
            float4 rv = *(const float4*)(row + k);
            float4 wv = *(const float4*)(w3 + k);
            s += rv.x * wv.x + rv.y * wv.y + rv.z * wv.z + rv.w * wv.w;
        }
        v = (s + b3[0]) * (1.0f / N_NODES);
    }
    sred[threadIdx.x] = v;
    __syncthreads();
    for (int st = 128; st > 0; st >>= 1) {
        if (threadIdx.x < st) sred[threadIdx.x] += sred[threadIdx.x + st];
        __syncthreads();
    }
    if (threadIdx.x == 0) atomicAdd(out, sred[0]);
}

// ---------------------------------------------------------------------------
// Launch
// ---------------------------------------------------------------------------
extern "C" void kernel_launch(void* const* d_in, const int* in_sizes, int n_in,
                              void* d_out, int out_size)
{
    const float* atom = (const float*)d_in[0];
    const int*   eidx = (const int*)d_in[1];
    const float* ef   = (const float*)d_in[2];
    const float* embw = (const float*)d_in[3];
    const float* embb = (const float*)d_in[4];
    const float* mw1  = (const float*)d_in[5];
    const float* mb1  = (const float*)d_in[6];
    const float* mw2  = (const float*)d_in[7];
    const float* mb2  = (const float*)d_in[8];
    const float* uw1  = (const float*)d_in[9];
    const float* ub1  = (const float*)d_in[10];
    const float* uw2  = (const float*)d_in[11];
    const float* ub2  = (const float*)d_in[12];
    const float* rw1  = (const float*)d_in[13];
    const float* rb1  = (const float*)d_in[14];
    const float* rw2  = (const float*)d_in[15];
    const float* rb2  = (const float*)d_in[16];
    const float* rw3  = (const float*)d_in[17];
    const float* rb3  = (const float*)d_in[18];

    const int* src = eidx;
    const int* dst = eidx + N_EDGES;

    float *px, *pxa, *pxb, *pagg, *pt1, *ph;
    cudaGetSymbolAddress((void**)&px,   g_x);
    cudaGetSymbolAddress((void**)&pxa,  g_xa);
    cudaGetSymbolAddress((void**)&pxb,  g_xb);
    cudaGetSymbolAddress((void**)&pagg, g_agg);
    cudaGetSymbolAddress((void**)&pt1,  g_t1);
    cudaGetSymbolAddress((void**)&ph,   g_h);

    embed_kernel<<<(N_NODES + EMB_NODES - 1) / EMB_NODES, 256>>>(atom, embw, embb);

    dim3 gN(2, (N_NODES + 127) / 128);   // 2 x 79
    dim3 gE(2, N_EDGES / 128);           // 2 x 1250

    for (int l = 0; l < NLAYERS; l++) {
        const float* W1 = mw1 + (size_t)l * 518 * HID;   // [518,256] row-major
        const float* U1 = uw1 + (size_t)l * 512 * HID;   // [512,256] row-major

        // xa = x @ W1[0:256], xb = x @ W1[256:512]
        gemm256<false, false, false><<<gN, 256>>>(px, W1, nullptr, nullptr,
                                                  pxa, N_NODES, HID);
        gemm256<false, false, false><<<gN, 256>>>(px, W1 + 256 * HID, nullptr,
                                                  nullptr, pxb, N_NODES, HID);
        cudaMemsetAsync(pagg, 0, sizeof(float) * N_NODES * HID);

        edge_msg_gemm<<<gE, 256>>>(pxa, pxb, src, dst, ef,
                                   W1 + 512 * HID, mb1 + (size_t)l * HID,
                                   mw2 + (size_t)l * HID * HID,
                                   mb2 + (size_t)l * HID, pagg);

        // t1 = x @ U1[0:256]
        gemm256<false, false, false><<<gN, 256>>>(px, U1, nullptr, nullptr,
                                                  pt1, N_NODES, HID);
        // h = relu(agg @ U1[256:512] + ub1 + t1)
        gemm256<true, true, true><<<gN, 256>>>(pagg, U1 + 256 * HID,
                                               ub1 + (size_t)l * HID, pt1,
                                               ph, N_NODES, HID);
        // x = h @ U2 + ub2
        gemm256<false, false, true><<<gN, 256>>>(ph,
                                                 uw2 + (size_t)l * HID * HID,
                                                 ub2 + (size_t)l * HID, nullptr,
                                                 px, N_NODES, HID);
    }

    // readout
    gemm256<true, false, true><<<gN, 256>>>(px, rw1, rb1, nullptr, pt1,
                                            N_NODES, HID);
    dim3 gR(1, (N_NODES + 127) / 128);
    gemm256<true, false, true><<<gR, 256>>>(pt1, rw2, rb2, nullptr, ph,
                                            N_NODES, 128);

    cudaMemsetAsync(d_out, 0, sizeof(float));
    readout_final<<<(N_NODES + 255) / 256, 256>>>(ph, rw3, rb3, (float*)d_out);
}

// round 4
// speedup vs baseline: 2.4175x; 2.4175x over previous
#include <cuda_runtime.h>

#define N_NODES 10000
#define N_EDGES 160000
#define HID 256
#define NBOND 6
#define NATOM 62
#define NLAYERS 6

// Scratch (device globals — no allocation allowed)
__device__ float g_x[N_NODES * HID];
__device__ float g_xa[N_NODES * HID];
__device__ float g_xb[N_NODES * HID];
__device__ float g_agg[N_NODES * HID];
__device__ float g_t1[N_NODES * HID];
__device__ float g_h[N_NODES * HID];

// CSR scratch
__device__ int   g_deg[N_NODES];
__device__ int   g_rowptr[N_NODES + 1];
__device__ int   g_cursor[N_NODES];
__device__ int   g_ssrc[N_EDGES];        // src sorted by dst
__device__ float g_sef[N_EDGES * NBOND]; // edge features sorted by dst
__device__ float g_degf[N_NODES];

// ---------------------------------------------------------------------------
// Embed: x = atom @ embed_w + embed_b   [10000,62]x[62,256]
// ---------------------------------------------------------------------------
#define EMB_NODES 16
__global__ void __launch_bounds__(256) embed_kernel(
    const float* __restrict__ atom, const float* __restrict__ w,
    const float* __restrict__ b)
{
    __shared__ float s_af[EMB_NODES][NATOM];
    int n0 = blockIdx.x * EMB_NODES;
    int tid = threadIdx.x;
    for (int i = tid; i < EMB_NODES * NATOM; i += 256) {
        int r = i / NATOM, c = i % NATOM;
        int n = n0 + r;
        s_af[r][c] = (n < N_NODES) ? atom[(size_t)n * NATOM + c] : 0.f;
    }
    __syncthreads();
    int j = tid;
    float acc[EMB_NODES];
    float bj = b[j];
#pragma unroll
    for (int r = 0; r < EMB_NODES; r++) acc[r] = bj;
    for (int k = 0; k < NATOM; k++) {
        float wv = w[k * HID + j];
#pragma unroll
        for (int r = 0; r < EMB_NODES; r++) acc[r] = fmaf(s_af[r][k], wv, acc[r]);
    }
#pragma unroll
    for (int r = 0; r < EMB_NODES; r++) {
        int n = n0 + r;
        if (n < N_NODES) g_x[(size_t)n * HID + j] = acc[r];
    }
}

// ---------------------------------------------------------------------------
// CSR build
// ---------------------------------------------------------------------------
__global__ void count_kernel(const int* __restrict__ dst)
{
    int e = blockIdx.x * blockDim.x + threadIdx.x;
    if (e < N_EDGES) atomicAdd(&g_deg[dst[e]], 1);
}

__global__ void __launch_bounds__(1024) scan_kernel()
{
    __shared__ int s[1024];
    __shared__ int s_carry;
    int tid = threadIdx.x;
    if (tid == 0) { s_carry = 0; g_rowptr[0] = 0; }
    __syncthreads();
    for (int base = 0; base < N_NODES; base += 1024) {
        int idx = base + tid;
        int v = (idx < N_NODES) ? g_deg[idx] : 0;
        s[tid] = v;
        __syncthreads();
        for (int off = 1; off < 1024; off <<= 1) {
            int t = (tid >= off) ? s[tid - off] : 0;
            __syncthreads();
            s[tid] += t;
            __syncthreads();
        }
        int incl = s[tid];
        int carry = s_carry;
        if (idx < N_NODES) {
            g_rowptr[idx + 1] = carry + incl;
            g_cursor[idx] = carry + incl - v;  // exclusive
            g_degf[idx] = (float)v;
        }
        __syncthreads();
        if (tid == 1023) s_carry = carry + s[1023];
        __syncthreads();
    }
}

__global__ void fill_kernel(const int* __restrict__ src,
                            const int* __restrict__ dst,
                            const float* __restrict__ ef)
{
    int e = blockIdx.x * blockDim.x + threadIdx.x;
    if (e >= N_EDGES) return;
    int d = dst[e];
    int pos = atomicAdd(&g_cursor[d], 1);
    g_ssrc[pos] = src[e];
#pragma unroll
    for (int q = 0; q < NBOND; q++)
        g_sef[(size_t)pos * NBOND + q] = ef[(size_t)e * NBOND + q];
}

// ---------------------------------------------------------------------------
// Aggregate: ragg[n] = sum over in-edges e of relu(xa[src_e] + xb[n] + ef_e@W1c + b1)
// One CTA per node, 256 threads = 256 columns. Atomic-free via CSR.
// ---------------------------------------------------------------------------
#define CH 16
__global__ void __launch_bounds__(256) aggregate_kernel(
    const float* __restrict__ xa, const float* __restrict__ xb,
    const float* __restrict__ w1c,  // [6,256]
    const float* __restrict__ b1,   // [256]
    float* __restrict__ ragg)
{
    __shared__ float s_w[NBOND][256];
    __shared__ float s_ef[CH][NBOND];
    __shared__ int s_src[CH];

    int n = blockIdx.x;
    int c = threadIdx.x;
    for (int i = c; i < NBOND * 256; i += 256)
        s_w[i >> 8][i & 255] = w1c[i];

    float base_v = b1[c] + xb[(size_t)n * HID + c];
    int beg = g_rowptr[n], end = g_rowptr[n + 1];
    float acc = 0.f;
    __syncthreads();

    for (int b0 = beg; b0 < end; b0 += CH) {
        int m = min(CH, end - b0);
        __syncthreads();
        if (c < m) s_src[c] = g_ssrc[b0 + c];
        if (c < m * NBOND) s_ef[c / NBOND][c % NBOND] = g_sef[(size_t)b0 * NBOND + c];
        __syncthreads();
        for (int j = 0; j < m; j++) {
            float t = base_v + xa[(size_t)s_src[j] * HID + c];
#pragma unroll
            for (int q = 0; q < NBOND; q++)
                t = fmaf(s_ef[j][q], s_w[q][c], t);
            acc += fmaxf(t, 0.f);
        }
    }
    ragg[(size_t)n * HID + c] = acc;
}

// ---------------------------------------------------------------------------
// Generic SGEMM: C[M,N] = op(A[M,256] @ W[256,N] (+bias | +rowscale*bias) (+Cprev)), opt ReLU
// BM=128, BN=128, BK=16, 256 threads, 8x8 per-thread microtile (4+4 split).
// ---------------------------------------------------------------------------
template <bool RELU, bool ADDC, bool HASBIAS, bool ROWB>
__global__ void __launch_bounds__(256) gemm256(
    const float* __restrict__ A, const float* __restrict__ W,
    const float* __restrict__ bias, const float* __restrict__ Cprev,
    const float* __restrict__ rowscale,
    float* __restrict__ C, int M, int N)
{
    __shared__ float As[16][128];
    __shared__ float Ws[16][128];
    const int K = 256;
    int col0 = blockIdx.x * 128, row0 = blockIdx.y * 128;
    int tid = threadIdx.x;
    int tx = tid & 15, ty = tid >> 4;

    float acc[8][8];
#pragma unroll
    for (int i = 0; i < 8; i++)
#pragma unroll
        for (int j = 0; j < 8; j++) acc[i][j] = 0.f;

    int ar = tid >> 2;
    int ac = (tid & 3) << 2;
    int wr = tid >> 5;
    int wc = (tid & 31) << 2;

    for (int kt = 0; kt < K; kt += 16) {
#pragma unroll
        for (int i = 0; i < 2; i++) {
            int r = ar + i * 64;
            int grow = row0 + r;
            float4 v = make_float4(0.f, 0.f, 0.f, 0.f);
            if (grow < M) v = *(const float4*)(A + (size_t)grow * K + kt + ac);
            As[ac + 0][r] = v.x; As[ac + 1][r] = v.y;
            As[ac + 2][r] = v.z; As[ac + 3][r] = v.w;
        }
#pragma unroll
        for (int i = 0; i < 2; i++) {
            int r = wr + i * 8;
            *(float4*)&Ws[r][wc] =
                *(const float4*)(W + (size_t)(kt + r) * N + col0 + wc);
        }
        __syncthreads();
#pragma unroll
        for (int kk = 0; kk < 16; kk++) {
            float4 a0 = *(const float4*)&As[kk][ty * 4];
            float4 a1 = *(const float4*)&As[kk][64 + ty * 4];
            float4 w0 = *(const float4*)&Ws[kk][tx * 4];
            float4 w1 = *(const float4*)&Ws[kk][64 + tx * 4];
            float af[8] = {a0.x, a0.y, a0.z, a0.w, a1.x, a1.y, a1.z, a1.w};
            float wf[8] = {w0.x, w0.y, w0.z, w0.w, w1.x, w1.y, w1.z, w1.w};
#pragma unroll
            for (int i = 0; i < 8; i++)
#pragma unroll
                for (int j = 0; j < 8; j++)
                    acc[i][j] = fmaf(af[i], wf[j], acc[i][j]);
        }
        __syncthreads();
    }

    int rbase[2] = {row0 + ty * 4, row0 + 64 + ty * 4};
    int cbase[2] = {col0 + tx * 4, col0 + 64 + tx * 4};
#pragma unroll
    for (int ih = 0; ih < 2; ih++)
#pragma unroll
        for (int i = 0; i < 4; i++) {
            int grow = rbase[ih] + i;
            if (grow < M) {
                float rs = ROWB ? rowscale[grow] : 0.f;
#pragma unroll
                for (int jh = 0; jh < 2; jh++)
#pragma unroll
                    for (int j = 0; j < 4; j++) {
                        int gcol = cbase[jh] + j;
                        float v = acc[ih * 4 + i][jh * 4 + j];
                        if (HASBIAS) v += bias[gcol];
                        if (ROWB) v = fmaf(rs, bias[gcol], v);  // deg * b2
                        if (ADDC) v += Cprev[(size_t)grow * N + gcol];
                        if (RELU) v = fmaxf(v, 0.f);
                        C[(size_t)grow * N + gcol] = v;
                    }
            }
        }
}

// ---------------------------------------------------------------------------
// Batched 3-GEMM on shared A (z selects weight/output): xa, xb, t1 from x
// ---------------------------------------------------------------------------
__global__ void __launch_bounds__(256) gemm3(
    const float* __restrict__ A,
    const float* __restrict__ W0, const float* __restrict__ W1p,
    const float* __restrict__ W2p,
    float* __restrict__ C0, float* __restrict__ C1, float* __restrict__ C2)
{
    const float* W = (blockIdx.z == 0) ? W0 : (blockIdx.z == 1 ? W1p : W2p);
    float* C = (blockIdx.z == 0) ? C0 : (blockIdx.z == 1 ? C1 : C2);

    __shared__ float As[16][128];
    __shared__ float Ws[16][128];
    const int K = 256, N = 256, M = N_NODES;
    int col0 = blockIdx.x * 128, row0 = blockIdx.y * 128;
    int tid = threadIdx.x;
    int tx = tid & 15, ty = tid >> 4;

    float acc[8][8];
#pragma unroll
    for (int i = 0; i < 8; i++)
#pragma unroll
        for (int j = 0; j < 8; j++) acc[i][j] = 0.f;

    int ar = tid >> 2;
    int ac = (tid & 3) << 2;
    int wr = tid >> 5;
    int wc = (tid & 31) << 2;

    for (int kt = 0; kt < K; kt += 16) {
#pragma unroll
        for (int i = 0; i < 2; i++) {
            int r = ar + i * 64;
            int grow = row0 + r;
            float4 v = make_float4(0.f, 0.f, 0.f, 0.f);
            if (grow < M) v = *(const float4*)(A + (size_t)grow * K + kt + ac);
            As[ac + 0][r] = v.x; As[ac + 1][r] = v.y;
            As[ac + 2][r] = v.z; As[ac + 3][r] = v.w;
        }
#pragma unroll
        for (int i = 0; i < 2; i++) {
            int r = wr + i * 8;
            *(float4*)&Ws[r][wc] =
                *(const float4*)(W + (size_t)(kt + r) * N + col0 + wc);
        }
        __syncthreads();
#pragma unroll
        for (int kk = 0; kk < 16; kk++) {
            float4 a0 = *(const float4*)&As[kk][ty * 4];
            float4 a1 = *(const float4*)&As[kk][64 + ty * 4];
            float4 w0 = *(const float4*)&Ws[kk][tx * 4];
            float4 w1 = *(const float4*)&Ws[kk][64 + tx * 4];
            float af[8] = {a0.x, a0.y, a0.z, a0.w, a1.x, a1.y, a1.z, a1.w};
            float wf[8] = {w0.x, w0.y, w0.z, w0.w, w1.x, w1.y, w1.z, w1.w};
#pragma unroll
            for (int i = 0; i < 8; i++)
#pragma unroll
                for (int j = 0; j < 8; j++)
                    acc[i][j] = fmaf(af[i], wf[j], acc[i][j]);
        }
        __syncthreads();
    }

    int rbase[2] = {row0 + ty * 4, row0 + 64 + ty * 4};
    int cbase[2] = {col0 + tx * 4, col0 + 64 + tx * 4};
#pragma unroll
    for (int ih = 0; ih < 2; ih++)
#pragma unroll
        for (int i = 0; i < 4; i++) {
            int grow = rbase[ih] + i;
            if (grow < M) {
#pragma unroll
                for (int jh = 0; jh < 2; jh++)
#pragma unroll
                    for (int j = 0; j < 4; j++)
                        C[(size_t)grow * N + cbase[jh] + j] =
                            acc[ih * 4 + i][jh * 4 + j];
            }
        }
}

// ---------------------------------------------------------------------------
// Readout final: out = mean_n( r2[n,:] . w3 + b3 )
// ---------------------------------------------------------------------------
__global__ void __launch_bounds__(256) readout_final(
    const float* __restrict__ r2, const float* __restrict__ w3,
    const float* __restrict__ b3, float* __restrict__ out)
{
    __shared__ float sred[256];
    int n = blockIdx.x * 256 + threadIdx.x;
    float v = 0.f;
    if (n < N_NODES) {
        const float* row = r2 + (size_t)n * 128;
        float s = 0.f;
#pragma unroll
        for (int k = 0; k < 128; k += 4) {
            float4 rv = *(const float4*)(row + k);
            float4 wv = *(const float4*)(w3 + k);
            s += rv.x * wv.x + rv.y * wv.y + rv.z * wv.z + rv.w * wv.w;
        }
        v = (s + b3[0]) * (1.0f / N_NODES);
    }
    sred[threadIdx.x] = v;
    __syncthreads();
    for (int st = 128; st > 0; st >>= 1) {
        if (threadIdx.x < st) sred[threadIdx.x] += sred[threadIdx.x + st];
        __syncthreads();
    }
    if (threadIdx.x == 0) atomicAdd(out, sred[0]);
}

// ---------------------------------------------------------------------------
// Launch
// ---------------------------------------------------------------------------
extern "C" void kernel_launch(void* const* d_in, const int* in_sizes, int n_in,
                              void* d_out, int out_size)
{
    const float* atom = (const float*)d_in[0];
    const int*   eidx = (const int*)d_in[1];
    const float* ef   = (const float*)d_in[2];
    const float* embw = (const float*)d_in[3];
    const float* embb = (const float*)d_in[4];
    const float* mw1  = (const float*)d_in[5];
    const float* mb1  = (const float*)d_in[6];
    const float* mw2  = (const float*)d_in[7];
    const float* mb2  = (const float*)d_in[8];
    const float* uw1  = (const float*)d_in[9];
    const float* ub1  = (const float*)d_in[10];
    const float* uw2  = (const float*)d_in[11];
    const float* ub2  = (const float*)d_in[12];
    const float* rw1  = (const float*)d_in[13];
    const float* rb1  = (const float*)d_in[14];
    const float* rw2  = (const float*)d_in[15];
    const float* rb2  = (const float*)d_in[16];
    const float* rw3  = (const float*)d_in[17];
    const float* rb3  = (const float*)d_in[18];

    const int* src = eidx;
    const int* dst = eidx + N_EDGES;

    float *px, *pxa, *pxb, *pagg, *pt1, *ph, *pdegf;
    int* pdeg;
    cudaGetSymbolAddress((void**)&px,    g_x);
    cudaGetSymbolAddress((void**)&pxa,   g_xa);
    cudaGetSymbolAddress((void**)&pxb,   g_xb);
    cudaGetSymbolAddress((void**)&pagg,  g_agg);
    cudaGetSymbolAddress((void**)&pt1,   g_t1);
    cudaGetSymbolAddress((void**)&ph,    g_h);
    cudaGetSymbolAddress((void**)&pdeg,  g_deg);
    cudaGetSymbolAddress((void**)&pdegf, g_degf);

    // Embed + CSR build (CSR reused across all layers)
    embed_kernel<<<(N_NODES + EMB_NODES - 1) / EMB_NODES, 256>>>(atom, embw, embb);
    cudaMemsetAsync(pdeg, 0, sizeof(int) * N_NODES);
    count_kernel<<<(N_EDGES + 255) / 256, 256>>>(dst);
    scan_kernel<<<1, 1024>>>();
    fill_kernel<<<(N_EDGES + 255) / 256, 256>>>(src, dst, ef);

    dim3 gN(2, (N_NODES + 127) / 128);      // 2 x 79
    dim3 gN3(2, (N_NODES + 127) / 128, 3);  // 2 x 79 x 3

    for (int l = 0; l < NLAYERS; l++) {
        const float* W1 = mw1 + (size_t)l * 518 * HID;   // [518,256] row-major
        const float* U1 = uw1 + (size_t)l * 512 * HID;   // [512,256] row-major

        // xa = x@W1a, xb = x@W1b, t1 = x@U1a (batched, shared A)
        gemm3<<<gN3, 256>>>(px, W1, W1 + 256 * HID, U1, pxa, pxb, pt1);

        // ragg[n] = sum relu(xa[src]+xb[n]+ef@W1c+b1)  (atomic-free CSR)
        aggregate_kernel<<<N_NODES, 256>>>(pxa, pxb, W1 + 512 * HID,
                                           mb1 + (size_t)l * HID, pagg);

        // agg = ragg@W2 + deg*b2   (segment_sum commutes with W2)
        gemm256<false, false, false, true><<<gN, 256>>>(
            pagg, mw2 + (size_t)l * HID * HID, mb2 + (size_t)l * HID,
            nullptr, pdegf, ph, N_NODES, HID);

        // h = relu(agg@U1b + ub1 + t1)
        gemm256<true, true, true, false><<<gN, 256>>>(
            ph, U1 + 256 * HID, ub1 + (size_t)l * HID, pt1, nullptr,
            pagg, N_NODES, HID);

        // x = h@U2 + ub2
        gemm256<false, false, true, false><<<gN, 256>>>(
            pagg, uw2 + (size_t)l * HID * HID, ub2 + (size_t)l * HID,
            nullptr, nullptr, px, N_NODES, HID);
    }

    // readout
    gemm256<true, false, true, false><<<gN, 256>>>(px, rw1, rb1, nullptr,
                                                   nullptr, pt1, N_NODES, HID);
    dim3 gR(1, (N_NODES + 127) / 128);
    gemm256<true, false, true, false><<<gR, 256>>>(pt1, rw2, rb2, nullptr,
                                                   nullptr, ph, N_NODES, 128);

    cudaMemsetAsync(d_out, 0, sizeof(float));
    readout_final<<<(N_NODES + 255) / 256, 256>>>(ph, rw3, rb3, (float*)d_out);
}

// round 6
// speedup vs baseline: 4.0982x; 1.6953x over previous
#include <cuda_runtime.h>
#include <cuda_bf16.h>
#include <cstdint>

#define N_NODES 10000
#define N_EDGES 160000
#define HID 256
#define NBOND 6
#define NATOM 62
#define NLAYERS 6
#define NSLOTS 38

// ---------------- scratch (device globals; no allocation allowed) ----------
__device__ float g_x[N_NODES * HID];
__device__ float g_xa[N_NODES * HID];
__device__ float g_xb[N_NODES * HID];
__device__ float g_agg[N_NODES * HID];
__device__ float g_t1[N_NODES * HID];
__device__ float g_h[N_NODES * HID];

__device__ int   g_deg[N_NODES];
__device__ int   g_rowptr[N_NODES + 1];
__device__ int   g_cursor[N_NODES];
__device__ int   g_ssrc[N_EDGES];
__device__ float g_sef[N_EDGES * NBOND];
__device__ float g_degf[N_NODES];

// transposed+split weight pools: [slot][n][k] bf16, slot stride 256*256
__device__ __nv_bfloat16 g_wth[NSLOTS * 256 * 256];
__device__ __nv_bfloat16 g_wtl[NSLOTS * 256 * 256];

// ---------------- helpers ---------------------------------------------------
__device__ __forceinline__ uint32_t smem_u32(const void* p) {
    uint32_t a;
    asm("{ .reg .u64 t; cvta.to.shared.u64 t, %1; cvt.u32.u64 %0, t; }"
        : "=r"(a) : "l"(p));
    return a;
}
__device__ __forceinline__ void ldm_x4(uint32_t* r, uint32_t addr) {
    asm volatile("ldmatrix.sync.aligned.m8n8.x4.shared.b16 {%0,%1,%2,%3}, [%4];"
                 : "=r"(r[0]), "=r"(r[1]), "=r"(r[2]), "=r"(r[3]) : "r"(addr));
}
__device__ __forceinline__ void mma_bf16(float* c, const uint32_t* a,
                                         uint32_t b0, uint32_t b1) {
    asm volatile(
        "mma.sync.aligned.m16n8k16.row.col.f32.bf16.bf16.f32 "
        "{%0,%1,%2,%3}, {%4,%5,%6,%7}, {%8,%9}, {%0,%1,%2,%3};"
        : "+f"(c[0]), "+f"(c[1]), "+f"(c[2]), "+f"(c[3])
        : "r"(a[0]), "r"(a[1]), "r"(a[2]), "r"(a[3]), "r"(b0), "r"(b1));
}

// ---------------------------------------------------------------------------
// Weight transpose + bf16 split: pool[z][n][k] = split(W_z[k][n])
// grid (8, 8, 38), block (32, 8)
// ---------------------------------------------------------------------------
__global__ void wsplit_kernel(
    const float* __restrict__ mw1, const float* __restrict__ uw1,
    const float* __restrict__ mw2, const float* __restrict__ uw2,
    const float* __restrict__ rw1, const float* __restrict__ rw2,
    __nv_bfloat16* __restrict__ wth, __nv_bfloat16* __restrict__ wtl)
{
    int z = blockIdx.z;
    const float* W;
    int N = 256;
    if (z < 36) {
        int l = z / 6, i = z % 6;
        switch (i) {
            case 0:  W = mw1 + (size_t)l * 518 * 256; break;
            case 1:  W = mw1 + (size_t)l * 518 * 256 + 256 * 256; break;
            case 2:  W = uw1 + (size_t)l * 512 * 256; break;
            case 3:  W = mw2 + (size_t)l * 256 * 256; break;
            case 4:  W = uw1 + (size_t)l * 512 * 256 + 256 * 256; break;
            default: W = uw2 + (size_t)l * 256 * 256; break;
        }
    } else if (z == 36) { W = rw1; }
    else { W = rw2; N = 128; }

    int k0 = blockIdx.x * 32, n0 = blockIdx.y * 32;
    if (n0 >= N) return;
    __shared__ float t[32][33];
    for (int i = threadIdx.y; i < 32; i += 8)
        t[i][threadIdx.x] = W[(size_t)(k0 + i) * N + n0 + threadIdx.x];
    __syncthreads();
    size_t base = (size_t)z * 65536;
    for (int i = threadIdx.y; i < 32; i += 8) {
        float v = t[threadIdx.x][i];  // = W[k0+tx][n0+i]
        __nv_bfloat16 h = __float2bfloat16(v);
        __nv_bfloat16 lo = __float2bfloat16(v - __bfloat162float(h));
        size_t o = base + (size_t)(n0 + i) * 256 + k0 + threadIdx.x;
        wth[o] = h;
        wtl[o] = lo;
    }
}

// ---------------------------------------------------------------------------
// bf16 split-precision GEMM via mma.sync:
//   C[M, N tile] = op(A[M,256] @ Wt_slot^T), 3-term: ah*wh + al*wh + ah*wl
// 128x128 tile per CTA, BK=32, 8 warps (2x4), warp tile 64x32.
// flags: 1=RELU 2=ADDC(Cprev, stride 256) 4=BIAS 8=ROWB(rowscale*bias)
// blockIdx.z selects (slot, C) among up to 3 (shared A).
// ---------------------------------------------------------------------------
#define STRD 40   // smem row stride in bf16 elems (32 + 8 pad) = 80 bytes
__global__ void __launch_bounds__(256, 2) tgemm(
    const float* __restrict__ A,
    const __nv_bfloat16* __restrict__ wth, const __nv_bfloat16* __restrict__ wtl,
    int s0, int s1, int s2,
    const float* __restrict__ bias, const float* __restrict__ Cprev,
    const float* __restrict__ rowscale,
    float* C0, float* C1, float* C2,
    int M, int ldc, int flags)
{
    extern __shared__ __align__(16) char smem[];
    const int AH = 0, AL = 10240, WH = 20480, WL = 30720;  // byte offsets

    int bz = blockIdx.z;
    int slot = (bz == 0) ? s0 : (bz == 1 ? s1 : s2);
    float* C = (bz == 0) ? C0 : (bz == 1 ? C1 : C2);
    const __nv_bfloat16* Wh = wth + (size_t)slot * 65536;
    const __nv_bfloat16* Wl = wtl + (size_t)slot * 65536;

    uint32_t sb = smem_u32(smem);
    int tid = threadIdx.x;
    int lane = tid & 31, wid = tid >> 5;
    int wr = wid >> 2, wc = wid & 3;           // warp grid 2 x 4
    int row0 = blockIdx.y * 128, col0 = blockIdx.x * 128;

    float acc[4][4][4];
#pragma unroll
    for (int i = 0; i < 4; i++)
#pragma unroll
        for (int j = 0; j < 4; j++)
#pragma unroll
            for (int k = 0; k < 4; k++) acc[i][j][k] = 0.f;

    // per-lane ldmatrix address components
    int a_row = lane & 15;
    int a_kh = (lane >> 4) * 8;
    int bg = lane >> 3;
    int b_n = (lane & 7) + (bg >> 1) * 8;
    int b_kh = (bg & 1) * 8;

    // load mapping: thread covers one row, one k-half of 16
    int lrow = tid >> 1;
    int lhalf = tid & 1;

    for (int ch = 0; ch < 8; ch++) {
        if (ch) __syncthreads();
        // ---- A chunk [128 x 32] fp32 -> bf16 hi/lo ----
        {
            int grow = row0 + lrow;
            float4 v[4];
            if (grow < M) {
                const float* Ap = A + (size_t)grow * 256 + ch * 32 + lhalf * 16;
#pragma unroll
                for (int q = 0; q < 4; q++) v[q] = *(const float4*)(Ap + q * 4);
            } else {
#pragma unroll
                for (int q = 0; q < 4; q++)
                    v[q] = make_float4(0.f, 0.f, 0.f, 0.f);
            }
            uint32_t soff = (uint32_t)(lrow * (STRD * 2) + lhalf * 32);
#pragma unroll
            for (int q = 0; q < 4; q++) {
                float f[4] = {v[q].x, v[q].y, v[q].z, v[q].w};
                __nv_bfloat16 h[4], l[4];
#pragma unroll
                for (int j = 0; j < 4; j++) {
                    h[j] = __float2bfloat16(f[j]);
                    l[j] = __float2bfloat16(f[j] - __bfloat162float(h[j]));
                }
                union { __nv_bfloat16 b[4]; uint2 u; } ph, pl;
#pragma unroll
                for (int j = 0; j < 4; j++) { ph.b[j] = h[j]; pl.b[j] = l[j]; }
                *(uint2*)(smem + AH + soff + q * 8) = ph.u;
                *(uint2*)(smem + AL + soff + q * 8) = pl.u;
            }
        }
        // ---- W chunk [128 x 32] bf16 hi/lo ----
        {
            size_t goff = (size_t)(col0 + lrow) * 256 + ch * 32 + lhalf * 16;
            uint32_t soff = (uint32_t)(lrow * (STRD * 2) + lhalf * 32);
            *(uint4*)(smem + WH + soff)      = *(const uint4*)(Wh + goff);
            *(uint4*)(smem + WH + soff + 16) = *(const uint4*)(Wh + goff + 8);
            *(uint4*)(smem + WL + soff)      = *(const uint4*)(Wl + goff);
            *(uint4*)(smem + WL + soff + 16) = *(const uint4*)(Wl + goff + 8);
        }
        __syncthreads();

        // ---- compute: 2 k16-steps per chunk ----
#pragma unroll
        for (int ks = 0; ks < 2; ks++) {
            uint32_t Ahf[4][4], Alf[4][4], Bhf[2][4], Blf[2][4];
#pragma unroll
            for (int mi = 0; mi < 4; mi++) {
                uint32_t r = wr * 64 + mi * 16 + a_row;
                uint32_t cofs = (uint32_t)(r * (STRD * 2) +
                                           (ks * 16 + a_kh) * 2);
                ldm_x4(Ahf[mi], sb + AH + cofs);
                ldm_x4(Alf[mi], sb + AL + cofs);
            }
#pragma unroll
            for (int nj = 0; nj < 2; nj++) {
                uint32_t n = wc * 32 + nj * 16 + b_n;
                uint32_t cofs = (uint32_t)(n * (STRD * 2) +
                                           (ks * 16 + b_kh) * 2);
                ldm_x4(Bhf[nj], sb + WH + cofs);
                ldm_x4(Blf[nj], sb + WL + cofs);
            }
#pragma unroll
            for (int mi = 0; mi < 4; mi++)
#pragma unroll
                for (int ni = 0; ni < 4; ni++) {
                    int nj = ni >> 1, off = (ni & 1) * 2;
                    mma_bf16(acc[mi][ni], Ahf[mi], Bhf[nj][off],
                             Bhf[nj][off + 1]);
                    mma_bf16(acc[mi][ni], Alf[mi], Bhf[nj][off],
                             Bhf[nj][off + 1]);
                    mma_bf16(acc[mi][ni], Ahf[mi], Blf[nj][off],
                             Blf[nj][off + 1]);
                }
        }
    }

    // ---- epilogue: regs -> gmem with flags ----
#pragma unroll
    for (int mi = 0; mi < 4; mi++) {
        int m0 = row0 + wr * 64 + mi * 16 + (lane >> 2);
        int m1 = m0 + 8;
        float rs0 = 0.f, rs1 = 0.f;
        if (flags & 8) {
            if (m0 < M) rs0 = rowscale[m0];
            if (m1 < M) rs1 = rowscale[m1];
        }
#pragma unroll
        for (int ni = 0; ni < 4; ni++) {
            int nc = col0 + wc * 32 + ni * 8 + (lane & 3) * 2;
            float b0 = 0.f, b1 = 0.f;
            if (flags & 4) { b0 = bias[nc]; b1 = bias[nc + 1]; }
            if (flags & 8) { b0 = bias[nc]; b1 = bias[nc + 1]; }
            float* a = acc[mi][ni];
            if (m0 < M) {
                float v0 = a[0], v1 = a[1];
                if (flags & 4) { v0 += b0; v1 += b1; }
                if (flags & 8) { v0 = fmaf(rs0, b0, v0); v1 = fmaf(rs0, b1, v1); }
                if (flags & 2) {
                    v0 += Cprev[(size_t)m0 * 256 + nc];
                    v1 += Cprev[(size_t)m0 * 256 + nc + 1];
                }
                if (flags & 1) { v0 = fmaxf(v0, 0.f); v1 = fmaxf(v1, 0.f); }
                *(float2*)(C + (size_t)m0 * ldc + nc) = make_float2(v0, v1);
            }
            if (m1 < M) {
                float v0 = a[2], v1 = a[3];
                if (flags & 4) { v0 += b0; v1 += b1; }
                if (flags & 8) { v0 = fmaf(rs1, b0, v0); v1 = fmaf(rs1, b1, v1); }
                if (flags & 2) {
                    v0 += Cprev[(size_t)m1 * 256 + nc];
                    v1 += Cprev[(size_t)m1 * 256 + nc + 1];
                }
                if (flags & 1) { v0 = fmaxf(v0, 0.f); v1 = fmaxf(v1, 0.f); }
                *(float2*)(C + (size_t)m1 * ldc + nc) = make_float2(v0, v1);
            }
        }
    }
}

// ---------------------------------------------------------------------------
// Embed: x = atom @ embed_w + embed_b
// ---------------------------------------------------------------------------
#define EMB_NODES 16
__global__ void __launch_bounds__(256) embed_kernel(
    const float* __restrict__ atom, const float* __restrict__ w,
    const float* __restrict__ b)
{
    __shared__ float s_af[EMB_NODES][NATOM];
    int n0 = blockIdx.x * EMB_NODES;
    int tid = threadIdx.x;
    for (int i = tid; i < EMB_NODES * NATOM; i += 256) {
        int r = i / NATOM, c = i % NATOM;
        int n = n0 + r;
        s_af[r][c] = (n < N_NODES) ? atom[(size_t)n * NATOM + c] : 0.f;
    }
    __syncthreads();
    int j = tid;
    float acc[EMB_NODES];
    float bj = b[j];
#pragma unroll
    for (int r = 0; r < EMB_NODES; r++) acc[r] = bj;
    for (int k = 0; k < NATOM; k++) {
        float wv = w[k * HID + j];
#pragma unroll
        for (int r = 0; r < EMB_NODES; r++) acc[r] = fmaf(s_af[r][k], wv, acc[r]);
    }
#pragma unroll
    for (int r = 0; r < EMB_NODES; r++) {
        int n = n0 + r;
        if (n < N_NODES) g_x[(size_t)n * HID + j] = acc[r];
    }
}

// ---------------------------------------------------------------------------
// CSR build
// ---------------------------------------------------------------------------
__global__ void count_kernel(const int* __restrict__ dst)
{
    int e = blockIdx.x * blockDim.x + threadIdx.x;
    if (e < N_EDGES) atomicAdd(&g_deg[dst[e]], 1);
}

__global__ void __launch_bounds__(1024) scan_kernel()
{
    __shared__ int s[1024];
    __shared__ int s_carry;
    int tid = threadIdx.x;
    if (tid == 0) { s_carry = 0; g_rowptr[0] = 0; }
    __syncthreads();
    for (int base = 0; base < N_NODES; base += 1024) {
        int idx = base + tid;
        int v = (idx < N_NODES) ? g_deg[idx] : 0;
        s[tid] = v;
        __syncthreads();
        for (int off = 1; off < 1024; off <<= 1) {
            int t = (tid >= off) ? s[tid - off] : 0;
            __syncthreads();
            s[tid] += t;
            __syncthreads();
        }
        int incl = s[tid];
        int carry = s_carry;
        if (idx < N_NODES) {
            g_rowptr[idx + 1] = carry + incl;
            g_cursor[idx] = carry + incl - v;
            g_degf[idx] = (float)v;
        }
        __syncthreads();
        if (tid == 1023) s_carry = carry + s[1023];
        __syncthreads();
    }
}

__global__ void fill_kernel(const int* __restrict__ src,
                            const int* __restrict__ dst,
                            const float* __restrict__ ef)
{
    int e = blockIdx.x * blockDim.x + threadIdx.x;
    if (e >= N_EDGES) return;
    int d = dst[e];
    int pos = atomicAdd(&g_cursor[d], 1);
    g_ssrc[pos] = src[e];
#pragma unroll
    for (int q = 0; q < NBOND; q++)
        g_sef[(size_t)pos * NBOND + q] = ef[(size_t)e * NBOND + q];
}

// ---------------------------------------------------------------------------
// Aggregate: ragg[n] = sum_{e in-edges} relu(xa[src_e] + xb[n] + ef_e@W1c + b1)
// ---------------------------------------------------------------------------
#define CH 16
__global__ void __launch_bounds__(256) aggregate_kernel(
    const float* __restrict__ xa, const float* __restrict__ xb,
    const float* __restrict__ w1c, const float* __restrict__ b1,
    float* __restrict__ ragg)
{
    __shared__ float s_w[NBOND][256];
    __shared__ float s_ef[CH][NBOND];
    __shared__ int s_src[CH];

    int n = blockIdx.x;
    int c = threadIdx.x;
    for (int i = c; i < NBOND * 256; i += 256)
        s_w[i >> 8][i & 255] = w1c[i];

    float base_v = b1[c] + xb[(size_t)n * HID + c];
    int beg = g_rowptr[n], end = g_rowptr[n + 1];
    float acc = 0.f;
    __syncthreads();

    for (int b0 = beg; b0 < end; b0 += CH) {
        int m = min(CH, end - b0);
        __syncthreads();
        if (c < m) s_src[c] = g_ssrc[b0 + c];
        if (c < m * NBOND) s_ef[c / NBOND][c % NBOND] = g_sef[(size_t)b0 * NBOND + c];
        __syncthreads();
        for (int j = 0; j < m; j++) {
            float t = base_v + xa[(size_t)s_src[j] * HID + c];
#pragma unroll
            for (int q = 0; q < NBOND; q++)
                t = fmaf(s_ef[j][q], s_w[q][c], t);
            acc += fmaxf(t, 0.f);
        }
    }
    ragg[(size_t)n * HID + c] = acc;
}

// ---------------------------------------------------------------------------
// Readout final: out = mean_n( r2[n,:] . w3 + b3 )
// ---------------------------------------------------------------------------
__global__ void __launch_bounds__(256) readout_final(
    const float* __restrict__ r2, const float* __restrict__ w3,
    const float* __restrict__ b3, float* __restrict__ out)
{
    __shared__ float sred[256];
    int n = blockIdx.x * 256 + threadIdx.x;
    float v = 0.f;
    if (n < N_NODES) {
        const float* row = r2 + (size_t)n * 128;
        float s = 0.f;
#pragma unroll
        for (int k = 0; k < 128; k += 4) {
            float4 rv = *(const float4*)(row + k);
            float4 wv = *(const float4*)(w3 + k);
            s += rv.x * wv.x + rv.y * wv.y + rv.z * wv.z + rv.w * wv.w;
        }
        v = (s + b3[0]) * (1.0f / N_NODES);
    }
    sred[threadIdx.x] = v;
    __syncthreads();
    for (int st = 128; st > 0; st >>= 1) {
        if (threadIdx.x < st) sred[threadIdx.x] += sred[threadIdx.x + st];
        __syncthreads();
    }
    if (threadIdx.x == 0) atomicAdd(out, sred[0]);
}

// ---------------------------------------------------------------------------
// Launch
// ---------------------------------------------------------------------------
extern "C" void kernel_launch(void* const* d_in, const int* in_sizes, int n_in,
                              void* d_out, int out_size)
{
    const float* atom = (const float*)d_in[0];
    const int*   eidx = (const int*)d_in[1];
    const float* ef   = (const float*)d_in[2];
    const float* embw = (const float*)d_in[3];
    const float* embb = (const float*)d_in[4];
    const float* mw1  = (const float*)d_in[5];
    const float* mb1  = (const float*)d_in[6];
    const float* mw2  = (const float*)d_in[7];
    const float* mb2  = (const float*)d_in[8];
    const float* uw1  = (const float*)d_in[9];
    const float* ub1  = (const float*)d_in[10];
    const float* uw2  = (const float*)d_in[11];
    const float* ub2  = (const float*)d_in[12];
    const float* rw1  = (const float*)d_in[13];
    const float* rb1  = (const float*)d_in[14];
    const float* rw2  = (const float*)d_in[15];
    const float* rb2  = (const float*)d_in[16];
    const float* rw3  = (const float*)d_in[17];
    const float* rb3  = (const float*)d_in[18];

    const int* src = eidx;
    const int* dst = eidx + N_EDGES;

    float *px, *pxa, *pxb, *pagg, *pt1, *ph, *pdegf;
    int* pdeg;
    __nv_bfloat16 *pwth, *pwtl;
    cudaGetSymbolAddress((void**)&px,    g_x);
    cudaGetSymbolAddress((void**)&pxa,   g_xa);
    cudaGetSymbolAddress((void**)&pxb,   g_xb);
    cudaGetSymbolAddress((void**)&pagg,  g_agg);
    cudaGetSymbolAddress((void**)&pt1,   g_t1);
    cudaGetSymbolAddress((void**)&ph,    g_h);
    cudaGetSymbolAddress((void**)&pdeg,  g_deg);
    cudaGetSymbolAddress((void**)&pdegf, g_degf);
    cudaGetSymbolAddress((void**)&pwth,  g_wth);
    cudaGetSymbolAddress((void**)&pwtl,  g_wtl);

    const int TG_SMEM = 40960;
    cudaFuncSetAttribute(tgemm, cudaFuncAttributeMaxDynamicSharedMemorySize,
                         TG_SMEM);

    // weight transform (once), embed, CSR
    wsplit_kernel<<<dim3(8, 8, NSLOTS), dim3(32, 8)>>>(mw1, uw1, mw2, uw2,
                                                       rw1, rw2, pwth, pwtl);
    embed_kernel<<<(N_NODES + EMB_NODES - 1) / EMB_NODES, 256>>>(atom, embw, embb);
    cudaMemsetAsync(pdeg, 0, sizeof(int) * N_NODES);
    count_kernel<<<(N_EDGES + 255) / 256, 256>>>(dst);
    scan_kernel<<<1, 1024>>>();
    fill_kernel<<<(N_EDGES + 255) / 256, 256>>>(src, dst, ef);

    dim3 gG(2, (N_NODES + 127) / 128, 1);   // 2 x 79
    dim3 gG3(2, (N_NODES + 127) / 128, 3);  // 2 x 79 x 3

    for (int l = 0; l < NLAYERS; l++) {
        const float* W1 = mw1 + (size_t)l * 518 * HID;

        // xa = x@W1a, xb = x@W1b, t1 = x@U1a
        tgemm<<<gG3, 256, TG_SMEM>>>(px, pwth, pwtl, l * 6 + 0, l * 6 + 1,
                                     l * 6 + 2, nullptr, nullptr, nullptr,
                                     pxa, pxb, pt1, N_NODES, 256, 0);

        // ragg[n] = sum relu(xa[src]+xb[n]+ef@W1c+b1)
        aggregate_kernel<<<N_NODES, 256>>>(pxa, pxb, W1 + 512 * HID,
                                           mb1 + (size_t)l * HID, pagg);

        // agg = ragg@W2 + deg*b2
        tgemm<<<gG, 256, TG_SMEM>>>(pagg, pwth, pwtl, l * 6 + 3, 0, 0,
                                    mb2 + (size_t)l * HID, nullptr, pdegf,
                                    ph, nullptr, nullptr, N_NODES, 256, 8);

        // h = relu(agg@U1b + ub1 + t1)
        tgemm<<<gG, 256, TG_SMEM>>>(ph, pwth, pwtl, l * 6 + 4, 0, 0,
                                    ub1 + (size_t)l * HID, pt1, nullptr,
                                    pagg, nullptr, nullptr, N_NODES, 256, 7);

        // x = h@U2 + ub2
        tgemm<<<gG, 256, TG_SMEM>>>(pagg, pwth, pwtl, l * 6 + 5, 0, 0,
                                    ub2 + (size_t)l * HID, nullptr, nullptr,
                                    px, nullptr, nullptr, N_NODES, 256, 4);
    }

    // readout
    tgemm<<<gG, 256, TG_SMEM>>>(px, pwth, pwtl, 36, 0, 0, rb1, nullptr,
                                nullptr, pt1, nullptr, nullptr, N_NODES, 256, 5);
    dim3 gR(1, (N_NODES + 127) / 128, 1);
    tgemm<<<gR, 256, TG_SMEM>>>(pt1, pwth, pwtl, 37, 0, 0, rb2, nullptr,
                                nullptr, ph, nullptr, nullptr, N_NODES, 128, 5);

    cudaMemsetAsync(d_out, 0, sizeof(float));
    readout_final<<<(N_NODES + 255) / 256, 256>>>(ph, rw3, rb3, (float*)d_out);
}

// round 7
// speedup vs baseline: 4.1341x; 1.0087x over previous
#include <cuda_runtime.h>
#include <cuda_bf16.h>
#include <cstdint>

#define N_NODES 10000
#define N_EDGES 160000
#define HID 256
#define NBOND 6
#define NATOM 62
#define NLAYERS 6
#define NSLOTS 38

// ---------------- scratch (device globals; no allocation allowed) ----------
__device__ float g_x[N_NODES * HID];
__device__ float g_xa[N_NODES * HID];
__device__ float g_xb[N_NODES * HID];
__device__ float g_agg[N_NODES * HID];
__device__ float g_t1[N_NODES * HID];
__device__ float g_h[N_NODES * HID];

__device__ int   g_deg[N_NODES];
__device__ int   g_rowptr[N_NODES + 1];
__device__ int   g_cursor[N_NODES];
__device__ int   g_ssrc[N_EDGES];
__device__ float g_sef[N_EDGES * NBOND];
__device__ float g_degf[N_NODES];

// transposed+split weight pools: [slot][n][k] bf16, slot stride 256*256
__device__ __nv_bfloat16 g_wth[NSLOTS * 256 * 256];
__device__ __nv_bfloat16 g_wtl[NSLOTS * 256 * 256];

// ---------------- helpers ---------------------------------------------------
__device__ __forceinline__ uint32_t smem_u32(const void* p) {
    uint32_t a;
    asm("{ .reg .u64 t; cvta.to.shared.u64 t, %1; cvt.u32.u64 %0, t; }"
        : "=r"(a) : "l"(p));
    return a;
}
__device__ __forceinline__ void ldm_x4(uint32_t* r, uint32_t addr) {
    asm volatile("ldmatrix.sync.aligned.m8n8.x4.shared.b16 {%0,%1,%2,%3}, [%4];"
                 : "=r"(r[0]), "=r"(r[1]), "=r"(r[2]), "=r"(r[3]) : "r"(addr));
}
__device__ __forceinline__ void mma_bf16(float* c, const uint32_t* a,
                                         uint32_t b0, uint32_t b1) {
    asm volatile(
        "mma.sync.aligned.m16n8k16.row.col.f32.bf16.bf16.f32 "
        "{%0,%1,%2,%3}, {%4,%5,%6,%7}, {%8,%9}, {%0,%1,%2,%3};"
        : "+f"(c[0]), "+f"(c[1]), "+f"(c[2]), "+f"(c[3])
        : "r"(a[0]), "r"(a[1]), "r"(a[2]), "r"(a[3]), "r"(b0), "r"(b1));
}
__device__ __forceinline__ void cp16(uint32_t dst, const void* src) {
    asm volatile("cp.async.cg.shared.global [%0], [%1], 16;"
                 :: "r"(dst), "l"(src));
}
__device__ __forceinline__ void cp_commit() {
    asm volatile("cp.async.commit_group;" ::: "memory");
}
__device__ __forceinline__ void cp_wait0() {
    asm volatile("cp.async.wait_group 0;" ::: "memory");
}

// ---------------------------------------------------------------------------
// Weight transpose + bf16 split: pool[z][n][k] = split(W_z[k][n])
// grid (8, 8, 38), block (32, 8)
// ---------------------------------------------------------------------------
__global__ void wsplit_kernel(
    const float* __restrict__ mw1, const float* __restrict__ uw1,
    const float* __restrict__ mw2, const float* __restrict__ uw2,
    const float* __restrict__ rw1, const float* __restrict__ rw2,
    __nv_bfloat16* __restrict__ wth, __nv_bfloat16* __restrict__ wtl)
{
    int z = blockIdx.z;
    const float* W;
    int N = 256;
    if (z < 36) {
        int l = z / 6, i = z % 6;
        switch (i) {
            case 0:  W = mw1 + (size_t)l * 518 * 256; break;
            case 1:  W = mw1 + (size_t)l * 518 * 256 + 256 * 256; break;
            case 2:  W = uw1 + (size_t)l * 512 * 256; break;
            case 3:  W = mw2 + (size_t)l * 256 * 256; break;
            case 4:  W = uw1 + (size_t)l * 512 * 256 + 256 * 256; break;
            default: W = uw2 + (size_t)l * 256 * 256; break;
        }
    } else if (z == 36) { W = rw1; }
    else { W = rw2; N = 128; }

    int k0 = blockIdx.x * 32, n0 = blockIdx.y * 32;
    if (n0 >= N) return;
    __shared__ float t[32][33];
    for (int i = threadIdx.y; i < 32; i += 8)
        t[i][threadIdx.x] = W[(size_t)(k0 + i) * N + n0 + threadIdx.x];
    __syncthreads();
    size_t base = (size_t)z * 65536;
    for (int i = threadIdx.y; i < 32; i += 8) {
        float v = t[threadIdx.x][i];  // = W[k0+tx][n0+i]
        __nv_bfloat16 h = __float2bfloat16(v);
        __nv_bfloat16 lo = __float2bfloat16(v - __bfloat162float(h));
        size_t o = base + (size_t)(n0 + i) * 256 + k0 + threadIdx.x;
        wth[o] = h;
        wtl[o] = lo;
    }
}

// ---------------------------------------------------------------------------
// bf16 split-precision GEMM via mma.sync, double-buffered + cp.async:
//   C[M, N tile] = op(A[M,256] @ Wt_slot^T), 3-term: ah*wh + al*wh + ah*wl
// 128x128 tile per CTA, BK=32, 8 warps (2x4), warp tile 64x32.
// flags: 1=RELU 2=ADDC(Cprev, stride 256) 4=BIAS 8=ROWB(rowscale*bias)
// blockIdx.z selects (slot, C) among up to 3 (shared A).
// smem: 2 buffers x 40960 B; per buffer: AH 0, AL 10240, WH 20480, WL 30720.
// row stride 80 B (32 bf16 + 8 pad) — conflict-free ldmatrix.
// ---------------------------------------------------------------------------
#define BUFSZ 40960
__global__ void __launch_bounds__(256, 2) tgemm(
    const float* __restrict__ A,
    const __nv_bfloat16* __restrict__ wth, const __nv_bfloat16* __restrict__ wtl,
    int s0, int s1, int s2,
    const float* __restrict__ bias, const float* __restrict__ Cprev,
    const float* __restrict__ rowscale,
    float* C0, float* C1, float* C2,
    int M, int ldc, int flags)
{
    extern __shared__ __align__(16) char smem[];

    int bz = blockIdx.z;
    int slot = (bz == 0) ? s0 : (bz == 1 ? s1 : s2);
    float* C = (bz == 0) ? C0 : (bz == 1 ? C1 : C2);
    const __nv_bfloat16* Wh = wth + (size_t)slot * 65536;
    const __nv_bfloat16* Wl = wtl + (size_t)slot * 65536;

    uint32_t sb = smem_u32(smem);
    int tid = threadIdx.x;
    int lane = tid & 31, wid = tid >> 5;
    int wr = wid >> 2, wc = wid & 3;           // warp grid 2 x 4
    int row0 = blockIdx.y * 128, col0 = blockIdx.x * 128;

    float acc[4][4][4];
#pragma unroll
    for (int i = 0; i < 4; i++)
#pragma unroll
        for (int j = 0; j < 4; j++)
#pragma unroll
            for (int k = 0; k < 4; k++) acc[i][j][k] = 0.f;

    // ldmatrix lane address components
    int a_row = lane & 15;
    int a_kh = (lane >> 4) * 8;
    int bg = lane >> 3;
    int b_n = (lane & 7) + (bg >> 1) * 8;
    int b_kh = (bg & 1) * 8;

    // load mapping: thread covers one row, one 16-elem k-half
    int lrow = tid >> 1;
    int lhalf = tid & 1;
    int grow = row0 + lrow;
    const float* Arow = A + (size_t)grow * 256 + lhalf * 16;
    size_t wgoff = (size_t)(col0 + lrow) * 256 + lhalf * 16;
    uint32_t soff = (uint32_t)(lrow * 80 + lhalf * 32);

    float4 av[4];

#define LOAD_A(ch)                                                         \
    do {                                                                   \
        if (grow < M) {                                                    \
            const float* p_ = Arow + (ch) * 32;                            \
            av[0] = *(const float4*)(p_);                                  \
            av[1] = *(const float4*)(p_ + 4);                              \
            av[2] = *(const float4*)(p_ + 8);                              \
            av[3] = *(const float4*)(p_ + 12);                             \
        } else {                                                           \
            av[0] = av[1] = av[2] = av[3] = make_float4(0.f, 0.f, 0.f, 0.f); \
        }                                                                  \
    } while (0)

#define STORE_A(buf)                                                       \
    do {                                                                   \
        char* bp_ = smem + (buf) * BUFSZ + soff;                           \
        _Pragma("unroll")                                                  \
        for (int q = 0; q < 4; q++) {                                      \
            float f_[4] = {av[q].x, av[q].y, av[q].z, av[q].w};            \
            union { __nv_bfloat16 b[4]; uint2 u; } ph_, pl_;               \
            _Pragma("unroll")                                              \
            for (int j = 0; j < 4; j++) {                                  \
                __nv_bfloat16 h_ = __float2bfloat16(f_[j]);                \
                ph_.b[j] = h_;                                             \
                pl_.b[j] = __float2bfloat16(f_[j] - __bfloat162float(h_)); \
            }                                                              \
            *(uint2*)(bp_ + q * 8) = ph_.u;                                \
            *(uint2*)(bp_ + 10240 + q * 8) = pl_.u;                        \
        }                                                                  \
    } while (0)

#define ISSUE_W(ch, buf)                                                   \
    do {                                                                   \
        uint32_t b_ = sb + (buf) * BUFSZ + soff;                           \
        const __nv_bfloat16* ph_ = Wh + wgoff + (ch) * 32;                 \
        const __nv_bfloat16* pl_ = Wl + wgoff + (ch) * 32;                 \
        cp16(b_ + 20480, ph_);                                             \
        cp16(b_ + 20480 + 16, ph_ + 8);                                    \
        cp16(b_ + 30720, pl_);                                             \
        cp16(b_ + 30720 + 16, pl_ + 8);                                    \
    } while (0)

    // prologue: chunk 0 into buffer 0
    ISSUE_W(0, 0);
    cp_commit();
    LOAD_A(0);
    STORE_A(0);
    cp_wait0();
    __syncthreads();

#pragma unroll 2
    for (int ch = 0; ch < 8; ch++) {
        int buf = ch & 1;
        if (ch < 7) {
            ISSUE_W(ch + 1, buf ^ 1);
            cp_commit();
            LOAD_A(ch + 1);
        }
        // ---- compute on buf: 2 k16-steps, term-sequential ----
        uint32_t base = sb + buf * BUFSZ;
#pragma unroll
        for (int ks = 0; ks < 2; ks++) {
            uint32_t Af[4][4], Bf[2][4];
            uint32_t acol = (uint32_t)((ks * 16 + a_kh) * 2);
            uint32_t bcol = (uint32_t)((ks * 16 + b_kh) * 2);
            // term 1: Al x Wh
#pragma unroll
            for (int mi = 0; mi < 4; mi++)
                ldm_x4(Af[mi], base + 10240 +
                               (uint32_t)((wr * 64 + mi * 16 + a_row) * 80) + acol);
#pragma unroll
            for (int nj = 0; nj < 2; nj++)
                ldm_x4(Bf[nj], base + 20480 +
                               (uint32_t)((wc * 32 + nj * 16 + b_n) * 80) + bcol);
#pragma unroll
            for (int mi = 0; mi < 4; mi++)
#pragma unroll
                for (int ni = 0; ni < 4; ni++) {
                    int nj = ni >> 1, off = (ni & 1) * 2;
                    mma_bf16(acc[mi][ni], Af[mi], Bf[nj][off], Bf[nj][off + 1]);
                }
            // term 2: Ah x Wh (reload A hi over Af)
#pragma unroll
            for (int mi = 0; mi < 4; mi++)
                ldm_x4(Af[mi], base +
                               (uint32_t)((wr * 64 + mi * 16 + a_row) * 80) + acol);
#pragma unroll
            for (int mi = 0; mi < 4; mi++)
#pragma unroll
                for (int ni = 0; ni < 4; ni++) {
                    int nj = ni >> 1, off = (ni & 1) * 2;
                    mma_bf16(acc[mi][ni], Af[mi], Bf[nj][off], Bf[nj][off + 1]);
                }
            // term 3: Ah x Wl (reload B lo over Bf)
#pragma unroll
            for (int nj = 0; nj < 2; nj++)
                ldm_x4(Bf[nj], base + 30720 +
                               (uint32_t)((wc * 32 + nj * 16 + b_n) * 80) + bcol);
#pragma unroll
            for (int mi = 0; mi < 4; mi++)
#pragma unroll
                for (int ni = 0; ni < 4; ni++) {
                    int nj = ni >> 1, off = (ni & 1) * 2;
                    mma_bf16(acc[mi][ni], Af[mi], Bf[nj][off], Bf[nj][off + 1]);
                }
        }
        if (ch < 7) {
            STORE_A(buf ^ 1);
            cp_wait0();
            __syncthreads();
        }
    }

    // ---- epilogue: regs -> gmem with flags ----
#pragma unroll
    for (int mi = 0; mi < 4; mi++) {
        int m0 = row0 + wr * 64 + mi * 16 + (lane >> 2);
        int m1 = m0 + 8;
        float rs0 = 0.f, rs1 = 0.f;
        if (flags & 8) {
            if (m0 < M) rs0 = rowscale[m0];
            if (m1 < M) rs1 = rowscale[m1];
        }
#pragma unroll
        for (int ni = 0; ni < 4; ni++) {
            int nc = col0 + wc * 32 + ni * 8 + (lane & 3) * 2;
            float b0 = 0.f, b1 = 0.f;
            if (flags & 12) { b0 = bias[nc]; b1 = bias[nc + 1]; }
            float* a = acc[mi][ni];
            if (m0 < M) {
                float v0 = a[0], v1 = a[1];
                if (flags & 4) { v0 += b0; v1 += b1; }
                if (flags & 8) { v0 = fmaf(rs0, b0, v0); v1 = fmaf(rs0, b1, v1); }
                if (flags & 2) {
                    v0 += Cprev[(size_t)m0 * 256 + nc];
                    v1 += Cprev[(size_t)m0 * 256 + nc + 1];
                }
                if (flags & 1) { v0 = fmaxf(v0, 0.f); v1 = fmaxf(v1, 0.f); }
                *(float2*)(C + (size_t)m0 * ldc + nc) = make_float2(v0, v1);
            }
            if (m1 < M) {
                float v0 = a[2], v1 = a[3];
                if (flags & 4) { v0 += b0; v1 += b1; }
                if (flags & 8) { v0 = fmaf(rs1, b0, v0); v1 = fmaf(rs1, b1, v1); }
                if (flags & 2) {
                    v0 += Cprev[(size_t)m1 * 256 + nc];
                    v1 += Cprev[(size_t)m1 * 256 + nc + 1];
                }
                if (flags & 1) { v0 = fmaxf(v0, 0.f); v1 = fmaxf(v1, 0.f); }
                *(float2*)(C + (size_t)m1 * ldc + nc) = make_float2(v0, v1);
            }
        }
    }
#undef LOAD_A
#undef STORE_A
#undef ISSUE_W
}

// ---------------------------------------------------------------------------
// Embed: x = atom @ embed_w + embed_b
// ---------------------------------------------------------------------------
#define EMB_NODES 16
__global__ void __launch_bounds__(256) embed_kernel(
    const float* __restrict__ atom, const float* __restrict__ w,
    const float* __restrict__ b)
{
    __shared__ float s_af[EMB_NODES][NATOM];
    int n0 = blockIdx.x * EMB_NODES;
    int tid = threadIdx.x;
    for (int i = tid; i < EMB_NODES * NATOM; i += 256) {
        int r = i / NATOM, c = i % NATOM;
        int n = n0 + r;
        s_af[r][c] = (n < N_NODES) ? atom[(size_t)n * NATOM + c] : 0.f;
    }
    __syncthreads();
    int j = tid;
    float acc[EMB_NODES];
    float bj = b[j];
#pragma unroll
    for (int r = 0; r < EMB_NODES; r++) acc[r] = bj;
    for (int k = 0; k < NATOM; k++) {
        float wv = w[k * HID + j];
#pragma unroll
        for (int r = 0; r < EMB_NODES; r++) acc[r] = fmaf(s_af[r][k], wv, acc[r]);
    }
#pragma unroll
    for (int r = 0; r < EMB_NODES; r++) {
        int n = n0 + r;
        if (n < N_NODES) g_x[(size_t)n * HID + j] = acc[r];
    }
}

// ---------------------------------------------------------------------------
// CSR build
// ---------------------------------------------------------------------------
__global__ void count_kernel(const int* __restrict__ dst)
{
    int e = blockIdx.x * blockDim.x + threadIdx.x;
    if (e < N_EDGES) atomicAdd(&g_deg[dst[e]], 1);
}

// one block, 1024 threads, 10 elems/thread; shuffle-based scan
__global__ void __launch_bounds__(1024) scan_kernel()
{
    __shared__ int warpsum[32];
    int tid = threadIdx.x;
    int base = tid * 10;
    int v[10];
    int tot = 0;
#pragma unroll
    for (int i = 0; i < 10; i++) {
        int idx = base + i;
        int d = (idx < N_NODES) ? g_deg[idx] : 0;
        v[i] = d;
        tot += d;
    }
    int lane = tid & 31, wid = tid >> 5;
    int x = tot;
#pragma unroll
    for (int off = 1; off < 32; off <<= 1) {
        int y = __shfl_up_sync(~0u, x, off);
        if (lane >= off) x += y;
    }
    if (lane == 31) warpsum[wid] = x;
    __syncthreads();
    if (wid == 0) {
        int w = warpsum[lane];
#pragma unroll
        for (int off = 1; off < 32; off <<= 1) {
            int y = __shfl_up_sync(~0u, w, off);
            if (lane >= off) w += y;
        }
        warpsum[lane] = w;
    }
    __syncthreads();
    int run = x - tot + (wid ? warpsum[wid - 1] : 0);
    if (tid == 0) g_rowptr[0] = 0;
#pragma unroll
    for (int i = 0; i < 10; i++) {
        int idx = base + i;
        if (idx < N_NODES) {
            g_cursor[idx] = run;
            run += v[i];
            g_rowptr[idx + 1] = run;
            g_degf[idx] = (float)v[i];
        }
    }
}

__global__ void fill_kernel(const int* __restrict__ src,
                            const int* __restrict__ dst,
                            const float* __restrict__ ef)
{
    int e = blockIdx.x * blockDim.x + threadIdx.x;
    if (e >= N_EDGES) return;
    int d = dst[e];
    int pos = atomicAdd(&g_cursor[d], 1);
    g_ssrc[pos] = src[e];
#pragma unroll
    for (int q = 0; q < NBOND; q++)
        g_sef[(size_t)pos * NBOND + q] = ef[(size_t)e * NBOND + q];
}

// ---------------------------------------------------------------------------
// Aggregate: ragg[n] = sum_{e in-edges} relu(xa[src_e] + xb[n] + ef_e@W1c + b1)
// ---------------------------------------------------------------------------
#define CH 16
__global__ void __launch_bounds__(256) aggregate_kernel(
    const float* __restrict__ xa, const float* __restrict__ xb,
    const float* __restrict__ w1c, const float* __restrict__ b1,
    float* __restrict__ ragg)
{
    __shared__ float s_w[NBOND][256];
    __shared__ float s_ef[CH][NBOND];
    __shared__ int s_src[CH];

    int n = blockIdx.x;
    int c = threadIdx.x;
    for (int i = c; i < NBOND * 256; i += 256)
        s_w[i >> 8][i & 255] = w1c[i];

    float base_v = b1[c] + xb[(size_t)n * HID + c];
    int beg = g_rowptr[n], end = g_rowptr[n + 1];
    float acc = 0.f;
    __syncthreads();

    for (int b0 = beg; b0 < end; b0 += CH) {
        int m = min(CH, end - b0);
        __syncthreads();
        if (c < m) s_src[c] = g_ssrc[b0 + c];
        if (c < m * NBOND) s_ef[c / NBOND][c % NBOND] = g_sef[(size_t)b0 * NBOND + c];
        __syncthreads();
        for (int j = 0; j < m; j++) {
            float t = base_v + xa[(size_t)s_src[j] * HID + c];
#pragma unroll
            for (int q = 0; q < NBOND; q++)
                t = fmaf(s_ef[j][q], s_w[q][c], t);
            acc += fmaxf(t, 0.f);
        }
    }
    ragg[(size_t)n * HID + c] = acc;
}

// ---------------------------------------------------------------------------
// Readout final: out = mean_n( r2[n,:] . w3 + b3 )
// ---------------------------------------------------------------------------
__global__ void __launch_bounds__(256) readout_final(
    const float* __restrict__ r2, const float* __restrict__ w3,
    const float* __restrict__ b3, float* __restrict__ out)
{
    __shared__ float sred[256];
    int n = blockIdx.x * 256 + threadIdx.x;
    float v = 0.f;
    if (n < N_NODES) {
        const float* row = r2 + (size_t)n * 128;
        float s = 0.f;
#pragma unroll
        for (int k = 0; k < 128; k += 4) {
            float4 rv = *(const float4*)(row + k);
            float4 wv = *(const float4*)(w3 + k);
            s += rv.x * wv.x + rv.y * wv.y + rv.z * wv.z + rv.w * wv.w;
        }
        v = (s + b3[0]) * (1.0f / N_NODES);
    }
    sred[threadIdx.x] = v;
    __syncthreads();
    for (int st = 128; st > 0; st >>= 1) {
        if (threadIdx.x < st) sred[threadIdx.x] += sred[threadIdx.x + st];
        __syncthreads();
    }
    if (threadIdx.x == 0) atomicAdd(out, sred[0]);
}

// ---------------------------------------------------------------------------
// Launch
// ---------------------------------------------------------------------------
extern "C" void kernel_launch(void* const* d_in, const int* in_sizes, int n_in,
                              void* d_out, int out_size)
{
    const float* atom = (const float*)d_in[0];
    const int*   eidx = (const int*)d_in[1];
    const float* ef   = (const float*)d_in[2];
    const float* embw = (const float*)d_in[3];
    const float* embb = (const float*)d_in[4];
    const float* mw1  = (const float*)d_in[5];
    const float* mb1  = (const float*)d_in[6];
    const float* mw2  = (const float*)d_in[7];
    const float* mb2  = (const float*)d_in[8];
    const float* uw1  = (const float*)d_in[9];
    const float* ub1  = (const float*)d_in[10];
    const float* uw2  = (const float*)d_in[11];
    const float* ub2  = (const float*)d_in[12];
    const float* rw1  = (const float*)d_in[13];
    const float* rb1  = (const float*)d_in[14];
    const float* rw2  = (const float*)d_in[15];
    const float* rb2  = (const float*)d_in[16];
    const float* rw3  = (const float*)d_in[17];
    const float* rb3  = (const float*)d_in[18];

    const int* src = eidx;
    const int* dst = eidx + N_EDGES;

    float *px, *pxa, *pxb, *pagg, *pt1, *ph, *pdegf;
    int* pdeg;
    __nv_bfloat16 *pwth, *pwtl;
    cudaGetSymbolAddress((void**)&px,    g_x);
    cudaGetSymbolAddress((void**)&pxa,   g_xa);
    cudaGetSymbolAddress((void**)&pxb,   g_xb);
    cudaGetSymbolAddress((void**)&pagg,  g_agg);
    cudaGetSymbolAddress((void**)&pt1,   g_t1);
    cudaGetSymbolAddress((void**)&ph,    g_h);
    cudaGetSymbolAddress((void**)&pdeg,  g_deg);
    cudaGetSymbolAddress((void**)&pdegf, g_degf);
    cudaGetSymbolAddress((void**)&pwth,  g_wth);
    cudaGetSymbolAddress((void**)&pwtl,  g_wtl);

    const int TG_SMEM = 2 * BUFSZ;  // 81920
    cudaFuncSetAttribute(tgemm, cudaFuncAttributeMaxDynamicSharedMemorySize,
                         TG_SMEM);

    // weight transform (once), embed, CSR
    wsplit_kernel<<<dim3(8, 8, NSLOTS), dim3(32, 8)>>>(mw1, uw1, mw2, uw2,
                                                       rw1, rw2, pwth, pwtl);
    embed_kernel<<<(N_NODES + EMB_NODES - 1) / EMB_NODES, 256>>>(atom, embw, embb);
    cudaMemsetAsync(pdeg, 0, sizeof(int) * N_NODES);
    count_kernel<<<(N_EDGES + 255) / 256, 256>>>(dst);
    scan_kernel<<<1, 1024>>>();
    fill_kernel<<<(N_EDGES + 255) / 256, 256>>>(src, dst, ef);

    dim3 gG(2, (N_NODES + 127) / 128, 1);   // 2 x 79
    dim3 gG3(2, (N_NODES + 127) / 128, 3);  // 2 x 79 x 3

    for (int l = 0; l < NLAYERS; l++) {
        const float* W1 = mw1 + (size_t)l * 518 * HID;

        // xa = x@W1a, xb = x@W1b, t1 = x@U1a
        tgemm<<<gG3, 256, TG_SMEM>>>(px, pwth, pwtl, l * 6 + 0, l * 6 + 1,
                                     l * 6 + 2, nullptr, nullptr, nullptr,
                                     pxa, pxb, pt1, N_NODES, 256, 0);

        // ragg[n] = sum relu(xa[src]+xb[n]+ef@W1c+b1)
        aggregate_kernel<<<N_NODES, 256>>>(pxa, pxb, W1 + 512 * HID,
                                           mb1 + (size_t)l * HID, pagg);

        // agg = ragg@W2 + deg*b2
        tgemm<<<gG, 256, TG_SMEM>>>(pagg, pwth, pwtl, l * 6 + 3, 0, 0,
                                    mb2 + (size_t)l * HID, nullptr, pdegf,
                                    ph, nullptr, nullptr, N_NODES, 256, 8);

        // h = relu(agg@U1b + ub1 + t1)
        tgemm<<<gG, 256, TG_SMEM>>>(ph, pwth, pwtl, l * 6 + 4, 0, 0,
                                    ub1 + (size_t)l * HID, pt1, nullptr,
                                    pagg, nullptr, nullptr, N_NODES, 256, 7);

        // x = h@U2 + ub2
        tgemm<<<gG, 256, TG_SMEM>>>(pagg, pwth, pwtl, l * 6 + 5, 0, 0,
                                    ub2 + (size_t)l * HID, nullptr, nullptr,
                                    px, nullptr, nullptr, N_NODES, 256, 4);
    }

    // readout
    tgemm<<<gG, 256, TG_SMEM>>>(px, pwth, pwtl, 36, 0, 0, rb1, nullptr,
                                nullptr, pt1, nullptr, nullptr, N_NODES, 256, 5);
    dim3 gR(1, (N_NODES + 127) / 128, 1);
    tgemm<<<gR, 256, TG_SMEM>>>(pt1, pwth, pwtl, 37, 0, 0, rb2, nullptr,
                                nullptr, ph, nullptr, nullptr, N_NODES, 128, 5);

    cudaMemsetAsync(d_out, 0, sizeof(float));
    readout_final<<<(N_NODES + 255) / 256, 256>>>(ph, rw3, rb3, (float*)d_out);
}

// round 8
// speedup vs baseline: 4.8689x; 1.1778x over previous
#include <cuda_runtime.h>
#include <cuda_fp16.h>
#include <cstdint>

#define N_NODES 10000
#define N_EDGES 160000
#define HID 256
#define NBOND 6
#define NATOM 62
#define NLAYERS 6
#define NSLOTS 38

// ---------------- scratch (device globals; no allocation allowed) ----------
__device__ float g_x[N_NODES * HID];
__device__ float g_xa[N_NODES * HID];
__device__ float g_xb[N_NODES * HID];
__device__ float g_agg[N_NODES * HID];
__device__ float g_t1[N_NODES * HID];
__device__ float g_h[N_NODES * HID];

__device__ int   g_deg[N_NODES];
__device__ int   g_rowptr[N_NODES + 1];
__device__ int   g_cursor[N_NODES];
__device__ int   g_ssrc[N_EDGES];
__device__ float g_sef[N_EDGES * NBOND];
__device__ float g_degf[N_NODES];

// transposed fp16 weight pool: [slot][n][k], slot stride 256*256
__device__ __half g_wt[NSLOTS * 256 * 256];

// ---------------- helpers ---------------------------------------------------
__device__ __forceinline__ uint32_t smem_u32(const void* p) {
    uint32_t a;
    asm("{ .reg .u64 t; cvta.to.shared.u64 t, %1; cvt.u32.u64 %0, t; }"
        : "=r"(a) : "l"(p));
    return a;
}
__device__ __forceinline__ void ldm_x4(uint32_t* r, uint32_t addr) {
    asm volatile("ldmatrix.sync.aligned.m8n8.x4.shared.b16 {%0,%1,%2,%3}, [%4];"
                 : "=r"(r[0]), "=r"(r[1]), "=r"(r[2]), "=r"(r[3]) : "r"(addr));
}
__device__ __forceinline__ void mma_f16(float* c, const uint32_t* a,
                                        uint32_t b0, uint32_t b1) {
    asm volatile(
        "mma.sync.aligned.m16n8k16.row.col.f32.f16.f16.f32 "
        "{%0,%1,%2,%3}, {%4,%5,%6,%7}, {%8,%9}, {%0,%1,%2,%3};"
        : "+f"(c[0]), "+f"(c[1]), "+f"(c[2]), "+f"(c[3])
        : "r"(a[0]), "r"(a[1]), "r"(a[2]), "r"(a[3]), "r"(b0), "r"(b1));
}
__device__ __forceinline__ void cp16(uint32_t dst, const void* src) {
    asm volatile("cp.async.cg.shared.global [%0], [%1], 16;"
                 :: "r"(dst), "l"(src));
}
__device__ __forceinline__ void cp_commit() {
    asm volatile("cp.async.commit_group;" ::: "memory");
}
__device__ __forceinline__ void cp_wait0() {
    asm volatile("cp.async.wait_group 0;" ::: "memory");
}

// ---------------------------------------------------------------------------
// Weight transpose to fp16: pool[z][n][k] = fp16(W_z[k][n])
// grid (8, 8, 38), block (32, 8)
// ---------------------------------------------------------------------------
__global__ void wsplit_kernel(
    const float* __restrict__ mw1, const float* __restrict__ uw1,
    const float* __restrict__ mw2, const float* __restrict__ uw2,
    const float* __restrict__ rw1, const float* __restrict__ rw2,
    __half* __restrict__ wt)
{
    int z = blockIdx.z;
    const float* W;
    int N = 256;
    if (z < 36) {
        int l = z / 6, i = z % 6;
        switch (i) {
            case 0:  W = mw1 + (size_t)l * 518 * 256; break;
            case 1:  W = mw1 + (size_t)l * 518 * 256 + 256 * 256; break;
            case 2:  W = uw1 + (size_t)l * 512 * 256; break;
            case 3:  W = mw2 + (size_t)l * 256 * 256; break;
            case 4:  W = uw1 + (size_t)l * 512 * 256 + 256 * 256; break;
            default: W = uw2 + (size_t)l * 256 * 256; break;
        }
    } else if (z == 36) { W = rw1; }
    else { W = rw2; N = 128; }

    int k0 = blockIdx.x * 32, n0 = blockIdx.y * 32;
    if (n0 >= N) return;
    __shared__ float t[32][33];
    for (int i = threadIdx.y; i < 32; i += 8)
        t[i][threadIdx.x] = W[(size_t)(k0 + i) * N + n0 + threadIdx.x];
    __syncthreads();
    size_t base = (size_t)z * 65536;
    for (int i = threadIdx.y; i < 32; i += 8) {
        float v = t[threadIdx.x][i];  // = W[k0+tx][n0+i]
        wt[base + (size_t)(n0 + i) * 256 + k0 + threadIdx.x] = __float2half(v);
    }
}

// ---------------------------------------------------------------------------
// fp16 split-precision GEMM via mma.sync, double-buffered + cp.async:
//   C[M, N tile] = op(A[M,256] @ Wt_slot^T), 2-term: ah*w + al*w
//   (A = ah + al exact to ~2^-22; W rounded once to fp16, err ~2^-11)
// 128x128 tile per CTA, BK=32, 8 warps (2x4), warp tile 64x32.
// flags: 1=RELU 2=ADDC(Cprev, stride 256) 4=BIAS 8=ROWB(rowscale*bias)
// blockIdx.z selects (slot, C) among up to 3 (shared A).
// smem: 2 buffers x 30720 B; per buffer: AH 0, AL 10240, W 20480.
// row stride 80 B (32 fp16 + 8 pad) — conflict-free ldmatrix.
// ---------------------------------------------------------------------------
#define BUFSZ 30720
__global__ void __launch_bounds__(256, 2) tgemm(
    const float* __restrict__ A,
    const __half* __restrict__ wt,
    int s0, int s1, int s2,
    const float* __restrict__ bias, const float* __restrict__ Cprev,
    const float* __restrict__ rowscale,
    float* C0, float* C1, float* C2,
    int M, int ldc, int flags)
{
    extern __shared__ __align__(16) char smem[];

    int bz = blockIdx.z;
    int slot = (bz == 0) ? s0 : (bz == 1 ? s1 : s2);
    float* C = (bz == 0) ? C0 : (bz == 1 ? C1 : C2);
    const __half* Wp = wt + (size_t)slot * 65536;

    uint32_t sb = smem_u32(smem);
    int tid = threadIdx.x;
    int lane = tid & 31, wid = tid >> 5;
    int wr = wid >> 2, wc = wid & 3;           // warp grid 2 x 4
    int row0 = blockIdx.y * 128, col0 = blockIdx.x * 128;

    float acc[4][4][4];
#pragma unroll
    for (int i = 0; i < 4; i++)
#pragma unroll
        for (int j = 0; j < 4; j++)
#pragma unroll
            for (int k = 0; k < 4; k++) acc[i][j][k] = 0.f;

    // ldmatrix lane address components
    int a_row = lane & 15;
    int a_kh = (lane >> 4) * 8;
    int bg = lane >> 3;
    int b_n = (lane & 7) + (bg >> 1) * 8;
    int b_kh = (bg & 1) * 8;

    // load mapping: thread covers one row, one 16-elem k-half
    int lrow = tid >> 1;
    int lhalf = tid & 1;
    int grow = row0 + lrow;
    const float* Arow = A + (size_t)grow * 256 + lhalf * 16;
    size_t wgoff = (size_t)(col0 + lrow) * 256 + lhalf * 16;
    uint32_t soff = (uint32_t)(lrow * 80 + lhalf * 32);

    float4 av[4];

#define LOAD_A(ch)                                                         \
    do {                                                                   \
        if (grow < M) {                                                    \
            const float* p_ = Arow + (ch) * 32;                            \
            av[0] = *(const float4*)(p_);                                  \
            av[1] = *(const float4*)(p_ + 4);                              \
            av[2] = *(const float4*)(p_ + 8);                              \
            av[3] = *(const float4*)(p_ + 12);                             \
        } else {                                                           \
            av[0] = av[1] = av[2] = av[3] = make_float4(0.f, 0.f, 0.f, 0.f); \
        }                                                                  \
    } while (0)

#define STORE_A(buf)                                                       \
    do {                                                                   \
        char* bp_ = smem + (buf) * BUFSZ + soff;                           \
        _Pragma("unroll")                                                  \
        for (int q = 0; q < 4; q++) {                                      \
            float f_[4] = {av[q].x, av[q].y, av[q].z, av[q].w};            \
            union { __half b[4]; uint2 u; } ph_, pl_;                      \
            _Pragma("unroll")                                              \
            for (int j = 0; j < 4; j++) {                                  \
                __half h_ = __float2half(f_[j]);                           \
                ph_.b[j] = h_;                                             \
                pl_.b[j] = __float2half(f_[j] - __half2float(h_));         \
            }                                                              \
            *(uint2*)(bp_ + q * 8) = ph_.u;                                \
            *(uint2*)(bp_ + 10240 + q * 8) = pl_.u;                        \
        }                                                                  \
    } while (0)

#define ISSUE_W(ch, buf)                                                   \
    do {                                                                   \
        uint32_t b_ = sb + (buf) * BUFSZ + soff;                           \
        const __half* pw_ = Wp + wgoff + (ch) * 32;                        \
        cp16(b_ + 20480, pw_);                                             \
        cp16(b_ + 20480 + 16, pw_ + 8);                                    \
    } while (0)

    // prologue: chunk 0 into buffer 0
    ISSUE_W(0, 0);
    cp_commit();
    LOAD_A(0);
    STORE_A(0);
    cp_wait0();
    __syncthreads();

#pragma unroll 2
    for (int ch = 0; ch < 8; ch++) {
        int buf = ch & 1;
        if (ch < 7) {
            ISSUE_W(ch + 1, buf ^ 1);
            cp_commit();
            LOAD_A(ch + 1);
        }
        // ---- compute on buf: 2 k16-steps, term-sequential ----
        uint32_t base = sb + buf * BUFSZ;
#pragma unroll
        for (int ks = 0; ks < 2; ks++) {
            uint32_t Af[4][4], Bf[2][4];
            uint32_t acol = (uint32_t)((ks * 16 + a_kh) * 2);
            uint32_t bcol = (uint32_t)((ks * 16 + b_kh) * 2);
            // B fragments (W fp16)
#pragma unroll
            for (int nj = 0; nj < 2; nj++)
                ldm_x4(Bf[nj], base + 20480 +
                               (uint32_t)((wc * 32 + nj * 16 + b_n) * 80) + bcol);
            // term 1: Al x W
#pragma unroll
            for (int mi = 0; mi < 4; mi++)
                ldm_x4(Af[mi], base + 10240 +
                               (uint32_t)((wr * 64 + mi * 16 + a_row) * 80) + acol);
#pragma unroll
            for (int mi = 0; mi < 4; mi++)
#pragma unroll
                for (int ni = 0; ni < 4; ni++) {
                    int nj = ni >> 1, off = (ni & 1) * 2;
                    mma_f16(acc[mi][ni], Af[mi], Bf[nj][off], Bf[nj][off + 1]);
                }
            // term 2: Ah x W (reload A hi over Af)
#pragma unroll
            for (int mi = 0; mi < 4; mi++)
                ldm_x4(Af[mi], base +
                               (uint32_t)((wr * 64 + mi * 16 + a_row) * 80) + acol);
#pragma unroll
            for (int mi = 0; mi < 4; mi++)
#pragma unroll
                for (int ni = 0; ni < 4; ni++) {
                    int nj = ni >> 1, off = (ni & 1) * 2;
                    mma_f16(acc[mi][ni], Af[mi], Bf[nj][off], Bf[nj][off + 1]);
                }
        }
        if (ch < 7) {
            STORE_A(buf ^ 1);
            cp_wait0();
            __syncthreads();
        }
    }

    // ---- epilogue: regs -> gmem with flags ----
#pragma unroll
    for (int mi = 0; mi < 4; mi++) {
        int m0 = row0 + wr * 64 + mi * 16 + (lane >> 2);
        int m1 = m0 + 8;
        float rs0 = 0.f, rs1 = 0.f;
        if (flags & 8) {
            if (m0 < M) rs0 = rowscale[m0];
            if (m1 < M) rs1 = rowscale[m1];
        }
#pragma unroll
        for (int ni = 0; ni < 4; ni++) {
            int nc = col0 + wc * 32 + ni * 8 + (lane & 3) * 2;
            float b0 = 0.f, b1 = 0.f;
            if (flags & 12) { b0 = bias[nc]; b1 = bias[nc + 1]; }
            float* a = acc[mi][ni];
            if (m0 < M) {
                float v0 = a[0], v1 = a[1];
                if (flags & 4) { v0 += b0; v1 += b1; }
                if (flags & 8) { v0 = fmaf(rs0, b0, v0); v1 = fmaf(rs0, b1, v1); }
                if (flags & 2) {
                    v0 += Cprev[(size_t)m0 * 256 + nc];
                    v1 += Cprev[(size_t)m0 * 256 + nc + 1];
                }
                if (flags & 1) { v0 = fmaxf(v0, 0.f); v1 = fmaxf(v1, 0.f); }
                *(float2*)(C + (size_t)m0 * ldc + nc) = make_float2(v0, v1);
            }
            if (m1 < M) {
                float v0 = a[2], v1 = a[3];
                if (flags & 4) { v0 += b0; v1 += b1; }
                if (flags & 8) { v0 = fmaf(rs1, b0, v0); v1 = fmaf(rs1, b1, v1); }
                if (flags & 2) {
                    v0 += Cprev[(size_t)m1 * 256 + nc];
                    v1 += Cprev[(size_t)m1 * 256 + nc + 1];
                }
                if (flags & 1) { v0 = fmaxf(v0, 0.f); v1 = fmaxf(v1, 0.f); }
                *(float2*)(C + (size_t)m1 * ldc + nc) = make_float2(v0, v1);
            }
        }
    }
#undef LOAD_A
#undef STORE_A
#undef ISSUE_W
}

// ---------------------------------------------------------------------------
// Embed: x = atom @ embed_w + embed_b
// ---------------------------------------------------------------------------
#define EMB_NODES 16
__global__ void __launch_bounds__(256) embed_kernel(
    const float* __restrict__ atom, const float* __restrict__ w,
    const float* __restrict__ b)
{
    __shared__ float s_af[EMB_NODES][NATOM];
    int n0 = blockIdx.x * EMB_NODES;
    int tid = threadIdx.x;
    for (int i = tid; i < EMB_NODES * NATOM; i += 256) {
        int r = i / NATOM, c = i % NATOM;
        int n = n0 + r;
        s_af[r][c] = (n < N_NODES) ? atom[(size_t)n * NATOM + c] : 0.f;
    }
    __syncthreads();
    int j = tid;
    float acc[EMB_NODES];
    float bj = b[j];
#pragma unroll
    for (int r = 0; r < EMB_NODES; r++) acc[r] = bj;
    for (int k = 0; k < NATOM; k++) {
        float wv = w[k * HID + j];
#pragma unroll
        for (int r = 0; r < EMB_NODES; r++) acc[r] = fmaf(s_af[r][k], wv, acc[r]);
    }
#pragma unroll
    for (int r = 0; r < EMB_NODES; r++) {
        int n = n0 + r;
        if (n < N_NODES) g_x[(size_t)n * HID + j] = acc[r];
    }
}

// ---------------------------------------------------------------------------
// CSR build
// ---------------------------------------------------------------------------
__global__ void count_kernel(const int* __restrict__ dst)
{
    int e = blockIdx.x * blockDim.x + threadIdx.x;
    if (e < N_EDGES) atomicAdd(&g_deg[dst[e]], 1);
}

// one block, 1024 threads, 10 elems/thread; shuffle-based scan
__global__ void __launch_bounds__(1024) scan_kernel()
{
    __shared__ int warpsum[32];
    int tid = threadIdx.x;
    int base = tid * 10;
    int v[10];
    int tot = 0;
#pragma unroll
    for (int i = 0; i < 10; i++) {
        int idx = base + i;
        int d = (idx < N_NODES) ? g_deg[idx] : 0;
        v[i] = d;
        tot += d;
    }
    int lane = tid & 31, wid = tid >> 5;
    int x = tot;
#pragma unroll
    for (int off = 1; off < 32; off <<= 1) {
        int y = __shfl_up_sync(~0u, x, off);
        if (lane >= off) x += y;
    }
    if (lane == 31) warpsum[wid] = x;
    __syncthreads();
    if (wid == 0) {
        int w = warpsum[lane];
#pragma unroll
        for (int off = 1; off < 32; off <<= 1) {
            int y = __shfl_up_sync(~0u, w, off);
            if (lane >= off) w += y;
        }
        warpsum[lane] = w;
    }
    __syncthreads();
    int run = x - tot + (wid ? warpsum[wid - 1] : 0);
    if (tid == 0) g_rowptr[0] = 0;
#pragma unroll
    for (int i = 0; i < 10; i++) {
        int idx = base + i;
        if (idx < N_NODES) {
            g_cursor[idx] = run;
            run += v[i];
            g_rowptr[idx + 1] = run;
            g_degf[idx] = (float)v[i];
        }
    }
}

__global__ void fill_kernel(const int* __restrict__ src,
                            const int* __restrict__ dst,
                            const float* __restrict__ ef)
{
    int e = blockIdx.x * blockDim.x + threadIdx.x;
    if (e >= N_EDGES) return;
    int d = dst[e];
    int pos = atomicAdd(&g_cursor[d], 1);
    g_ssrc[pos] = src[e];
#pragma unroll
    for (int q = 0; q < NBOND; q++)
        g_sef[(size_t)pos * NBOND + q] = ef[(size_t)e * NBOND + q];
}

// ---------------------------------------------------------------------------
// Aggregate: ragg[n] = sum_{e in-edges} relu(xa[src_e] + xb[n] + ef_e@W1c + b1)
// ---------------------------------------------------------------------------
#define CH 16
__global__ void __launch_bounds__(256) aggregate_kernel(
    const float* __restrict__ xa, const float* __restrict__ xb,
    const float* __restrict__ w1c, const float* __restrict__ b1,
    float* __restrict__ ragg)
{
    __shared__ float s_w[NBOND][256];
    __shared__ float s_ef[CH][NBOND];
    __shared__ int s_src[CH];

    int n = blockIdx.x;
    int c = threadIdx.x;
    for (int i = c; i < NBOND * 256; i += 256)
        s_w[i >> 8][i & 255] = w1c[i];

    float base_v = b1[c] + xb[(size_t)n * HID + c];
    int beg = g_rowptr[n], end = g_rowptr[n + 1];
    float acc = 0.f;
    __syncthreads();

    for (int b0 = beg; b0 < end; b0 += CH) {
        int m = min(CH, end - b0);
        __syncthreads();
        if (c < m) s_src[c] = g_ssrc[b0 + c];
        if (c < m * NBOND) s_ef[c / NBOND][c % NBOND] = g_sef[(size_t)b0 * NBOND + c];
        __syncthreads();
        for (int j = 0; j < m; j++) {
            float t = base_v + xa[(size_t)s_src[j] * HID + c];
#pragma unroll
            for (int q = 0; q < NBOND; q++)
                t = fmaf(s_ef[j][q], s_w[q][c], t);
            acc += fmaxf(t, 0.f);
        }
    }
    ragg[(size_t)n * HID + c] = acc;
}

// ---------------------------------------------------------------------------
// Readout final: out = mean_n( r2[n,:] . w3 + b3 )
// ---------------------------------------------------------------------------
__global__ void __launch_bounds__(256) readout_final(
    const float* __restrict__ r2, const float* __restrict__ w3,
    const float* __restrict__ b3, float* __restrict__ out)
{
    __shared__ float sred[256];
    int n = blockIdx.x * 256 + threadIdx.x;
    float v = 0.f;
    if (n < N_NODES) {
        const float* row = r2 + (size_t)n * 128;
        float s = 0.f;
#pragma unroll
        for (int k = 0; k < 128; k += 4) {
            float4 rv = *(const float4*)(row + k);
            float4 wv = *(const float4*)(w3 + k);
            s += rv.x * wv.x + rv.y * wv.y + rv.z * wv.z + rv.w * wv.w;
        }
        v = (s + b3[0]) * (1.0f / N_NODES);
    }
    sred[threadIdx.x] = v;
    __syncthreads();
    for (int st = 128; st > 0; st >>= 1) {
        if (threadIdx.x < st) sred[threadIdx.x] += sred[threadIdx.x + st];
        __syncthreads();
    }
    if (threadIdx.x == 0) atomicAdd(out, sred[0]);
}

// ---------------------------------------------------------------------------
// Launch
// ---------------------------------------------------------------------------
extern "C" void kernel_launch(void* const* d_in, const int* in_sizes, int n_in,
                              void* d_out, int out_size)
{
    const float* atom = (const float*)d_in[0];
    const int*   eidx = (const int*)d_in[1];
    const float* ef   = (const float*)d_in[2];
    const float* embw = (const float*)d_in[3];
    const float* embb = (const float*)d_in[4];
    const float* mw1  = (const float*)d_in[5];
    const float* mb1  = (const float*)d_in[6];
    const float* mw2  = (const float*)d_in[7];
    const float* mb2  = (const float*)d_in[8];
    const float* uw1  = (const float*)d_in[9];
    const float* ub1  = (const float*)d_in[10];
    const float* uw2  = (const float*)d_in[11];
    const float* ub2  = (const float*)d_in[12];
    const float* rw1  = (const float*)d_in[13];
    const float* rb1  = (const float*)d_in[14];
    const float* rw2  = (const float*)d_in[15];
    const float* rb2  = (const float*)d_in[16];
    const float* rw3  = (const float*)d_in[17];
    const float* rb3  = (const float*)d_in[18];

    const int* src = eidx;
    const int* dst = eidx + N_EDGES;

    float *px, *pxa, *pxb, *pagg, *pt1, *ph, *pdegf;
    int* pdeg;
    __half* pwt;
    cudaGetSymbolAddress((void**)&px,    g_x);
    cudaGetSymbolAddress((void**)&pxa,   g_xa);
    cudaGetSymbolAddress((void**)&pxb,   g_xb);
    cudaGetSymbolAddress((void**)&pagg,  g_agg);
    cudaGetSymbolAddress((void**)&pt1,   g_t1);
    cudaGetSymbolAddress((void**)&ph,    g_h);
    cudaGetSymbolAddress((void**)&pdeg,  g_deg);
    cudaGetSymbolAddress((void**)&pdegf, g_degf);
    cudaGetSymbolAddress((void**)&pwt,   g_wt);

    const int TG_SMEM = 2 * BUFSZ;  // 61440
    cudaFuncSetAttribute(tgemm, cudaFuncAttributeMaxDynamicSharedMemorySize,
                         TG_SMEM);

    // weight transform (once), embed, CSR
    wsplit_kernel<<<dim3(8, 8, NSLOTS), dim3(32, 8)>>>(mw1, uw1, mw2, uw2,
                                                       rw1, rw2, pwt);
    embed_kernel<<<(N_NODES + EMB_NODES - 1) / EMB_NODES, 256>>>(atom, embw, embb);
    cudaMemsetAsync(pdeg, 0, sizeof(int) * N_NODES);
    count_kernel<<<(N_EDGES + 255) / 256, 256>>>(dst);
    scan_kernel<<<1, 1024>>>();
    fill_kernel<<<(N_EDGES + 255) / 256, 256>>>(src, dst, ef);

    dim3 gG(2, (N_NODES + 127) / 128, 1);   // 2 x 79
    dim3 gG3(2, (N_NODES + 127) / 128, 3);  // 2 x 79 x 3

    for (int l = 0; l < NLAYERS; l++) {
        const float* W1 = mw1 + (size_t)l * 518 * HID;

        // xa = x@W1a, xb = x@W1b, t1 = x@U1a
        tgemm<<<gG3, 256, TG_SMEM>>>(px, pwt, l * 6 + 0, l * 6 + 1,
                                     l * 6 + 2, nullptr, nullptr, nullptr,
                                     pxa, pxb, pt1, N_NODES, 256, 0);

        // ragg[n] = sum relu(xa[src]+xb[n]+ef@W1c+b1)
        aggregate_kernel<<<N_NODES, 256>>>(pxa, pxb, W1 + 512 * HID,
                                           mb1 + (size_t)l * HID, pagg);

        // agg = ragg@W2 + deg*b2
        tgemm<<<gG, 256, TG_SMEM>>>(pagg, pwt, l * 6 + 3, 0, 0,
                                    mb2 + (size_t)l * HID, nullptr, pdegf,
                                    ph, nullptr, nullptr, N_NODES, 256, 8);

        // h = relu(agg@U1b + ub1 + t1)
        tgemm<<<gG, 256, TG_SMEM>>>(ph, pwt, l * 6 + 4, 0, 0,
                                    ub1 + (size_t)l * HID, pt1, nullptr,
                                    pagg, nullptr, nullptr, N_NODES, 256, 7);

        // x = h@U2 + ub2
        tgemm<<<gG, 256, TG_SMEM>>>(pagg, pwt, l * 6 + 5, 0, 0,
                                    ub2 + (size_t)l * HID, nullptr, nullptr,
                                    px, nullptr, nullptr, N_NODES, 256, 4);
    }

    // readout
    tgemm<<<gG, 256, TG_SMEM>>>(px, pwt, 36, 0, 0, rb1, nullptr,
                                nullptr, pt1, nullptr, nullptr, N_NODES, 256, 5);
    dim3 gR(1, (N_NODES + 127) / 128, 1);
    tgemm<<<gR, 256, TG_SMEM>>>(pt1, pwt, 37, 0, 0, rb2, nullptr,
                                nullptr, ph, nullptr, nullptr, N_NODES, 128, 5);

    cudaMemsetAsync(d_out, 0, sizeof(float));
    readout_final<<<(N_NODES + 255) / 256, 256>>>(ph, rw3, rb3, (float*)d_out);
}

// round 9
// speedup vs baseline: 5.5175x; 1.1332x over previous
#include <cuda_runtime.h>
#include <cuda_fp16.h>
#include <cstdint>

#define N_NODES 10000
#define N_EDGES 160000
#define HID 256
#define NBOND 6
#define NATOM 62
#define NLAYERS 6
#define NSLOTS 38

// ---------------- scratch (device globals; no allocation allowed) ----------
__device__ float g_x[N_NODES * HID];
__device__ float g_xa[N_NODES * HID];
__device__ float g_xb[N_NODES * HID];
__device__ float g_agg[N_NODES * HID];
__device__ float g_t1[N_NODES * HID];
__device__ float g_h[N_NODES * HID];

__device__ int   g_deg[N_NODES];
__device__ int   g_rowptr[N_NODES + 1];
__device__ int   g_cursor[N_NODES];
__device__ int   g_ssrc[N_EDGES];
__device__ float g_sef[N_EDGES * NBOND];
__device__ float g_degf[N_NODES];

// transposed fp16 weight pool: [slot][n][k], slot stride 256*256
__device__ __half g_wt[NSLOTS * 256 * 256];

// ---------------- helpers ---------------------------------------------------
__device__ __forceinline__ uint32_t smem_u32(const void* p) {
    uint32_t a;
    asm("{ .reg .u64 t; cvta.to.shared.u64 t, %1; cvt.u32.u64 %0, t; }"
        : "=r"(a) : "l"(p));
    return a;
}
__device__ __forceinline__ void ldm_x4(uint32_t* r, uint32_t addr) {
    asm volatile("ldmatrix.sync.aligned.m8n8.x4.shared.b16 {%0,%1,%2,%3}, [%4];"
                 : "=r"(r[0]), "=r"(r[1]), "=r"(r[2]), "=r"(r[3]) : "r"(addr));
}
__device__ __forceinline__ void mma_f16(float* c, const uint32_t* a,
                                        uint32_t b0, uint32_t b1) {
    asm volatile(
        "mma.sync.aligned.m16n8k16.row.col.f32.f16.f16.f32 "
        "{%0,%1,%2,%3}, {%4,%5,%6,%7}, {%8,%9}, {%0,%1,%2,%3};"
        : "+f"(c[0]), "+f"(c[1]), "+f"(c[2]), "+f"(c[3])
        : "r"(a[0]), "r"(a[1]), "r"(a[2]), "r"(a[3]), "r"(b0), "r"(b1));
}
__device__ __forceinline__ void cp16(uint32_t dst, const void* src) {
    asm volatile("cp.async.cg.shared.global [%0], [%1], 16;"
                 :: "r"(dst), "l"(src));
}
__device__ __forceinline__ void cp_commit() {
    asm volatile("cp.async.commit_group;" ::: "memory");
}
__device__ __forceinline__ void cp_wait0() {
    asm volatile("cp.async.wait_group 0;" ::: "memory");
}

// ---------------------------------------------------------------------------
// Weight transpose to fp16: pool[z][n][k] = fp16(W_z[k][n])
// grid (8, 8, 38), block (32, 8)
// ---------------------------------------------------------------------------
__global__ void wsplit_kernel(
    const float* __restrict__ mw1, const float* __restrict__ uw1,
    const float* __restrict__ mw2, const float* __restrict__ uw2,
    const float* __restrict__ rw1, const float* __restrict__ rw2,
    __half* __restrict__ wt)
{
    int z = blockIdx.z;
    const float* W;
    int N = 256;
    if (z < 36) {
        int l = z / 6, i = z % 6;
        switch (i) {
            case 0:  W = mw1 + (size_t)l * 518 * 256; break;
            case 1:  W = mw1 + (size_t)l * 518 * 256 + 256 * 256; break;
            case 2:  W = uw1 + (size_t)l * 512 * 256; break;
            case 3:  W = mw2 + (size_t)l * 256 * 256; break;
            case 4:  W = uw1 + (size_t)l * 512 * 256 + 256 * 256; break;
            default: W = uw2 + (size_t)l * 256 * 256; break;
        }
    } else if (z == 36) { W = rw1; }
    else { W = rw2; N = 128; }

    int k0 = blockIdx.x * 32, n0 = blockIdx.y * 32;
    if (n0 >= N) return;
    __shared__ float t[32][33];
    for (int i = threadIdx.y; i < 32; i += 8)
        t[i][threadIdx.x] = W[(size_t)(k0 + i) * N + n0 + threadIdx.x];
    __syncthreads();
    size_t base = (size_t)z * 65536;
    for (int i = threadIdx.y; i < 32; i += 8) {
        float v = t[threadIdx.x][i];  // = W[k0+tx][n0+i]
        wt[base + (size_t)(n0 + i) * 256 + k0 + threadIdx.x] = __float2half(v);
    }
}

// ---------------------------------------------------------------------------
// fp16 split-precision GEMM via mma.sync, templated M-tile:
//   C[M, N tile] = op(A[M,256] @ Wt_slot^T), 2-term: ah*w + al*w
// Tile: (MI*32) x 128 per CTA, BK=32, 8 warps (2 x 4), warp tile (MI*16) x 32.
//   MI=4 -> 128-row tile, 2 CTAs/SM (for the 3-slot batched launch, 474 CTAs)
//   MI=5 -> 160-row tile, 1 CTA/SM (63x2 = 126 CTAs <= 148 SMs, no 2nd wave)
// flags: 1=RELU 2=ADDC(Cprev, stride 256) 4=BIAS 8=ROWB(rowscale*bias)
// blockIdx.z selects (slot, C) among up to 3 (shared A).
// smem per buffer: AH [TM*80], AL [TM*80], W [128*80]; row stride 80 B.
// ---------------------------------------------------------------------------
template <int MI>
__global__ void __launch_bounds__(256, (MI == 4) ? 2 : 1) tgemm(
    const float* __restrict__ A,
    const __half* __restrict__ wt,
    int s0, int s1, int s2,
    const float* __restrict__ bias, const float* __restrict__ Cprev,
    const float* __restrict__ rowscale,
    float* C0, float* C1, float* C2,
    int M, int ldc, int flags)
{
    constexpr int TM = MI * 32;           // CTA rows
    constexpr int ABYTES = TM * 80;       // one A sub-buffer
    constexpr int WOFF = 2 * ABYTES;      // W region offset in buffer
    constexpr int BUFSZ = WOFF + 10240;   // full buffer

    extern __shared__ __align__(16) char smem[];

    int bz = blockIdx.z;
    int slot = (bz == 0) ? s0 : (bz == 1 ? s1 : s2);
    float* C = (bz == 0) ? C0 : (bz == 1 ? C1 : C2);
    const __half* Wp = wt + (size_t)slot * 65536;

    uint32_t sb = smem_u32(smem);
    int tid = threadIdx.x;
    int lane = tid & 31, wid = tid >> 5;
    int wr = wid >> 2, wc = wid & 3;           // warp grid 2 x 4
    int row0 = blockIdx.y * TM, col0 = blockIdx.x * 128;

    float acc[MI][4][4];
#pragma unroll
    for (int i = 0; i < MI; i++)
#pragma unroll
        for (int j = 0; j < 4; j++)
#pragma unroll
            for (int k = 0; k < 4; k++) acc[i][j][k] = 0.f;

    // ldmatrix lane address components
    int a_row = lane & 15;
    int a_kh = (lane >> 4) * 8;
    int bg = lane >> 3;
    int b_n = (lane & 7) + (bg >> 1) * 8;
    int b_kh = (bg & 1) * 8;

    // A load mapping: thread -> base row r0 = tid>>3, float4 col c4 = tid&7;
    // covers rows r0 + q*32 (q < MI), each row 32 floats = 8 float4.
    int r0 = tid >> 3;
    int c4 = tid & 7;
    // W load mapping: thread covers one row (128 rows, 2 threads/row)
    int lrow = tid >> 1;
    int lhalf = tid & 1;
    size_t wgoff = (size_t)(col0 + lrow) * 256 + lhalf * 16;
    uint32_t wsoff = (uint32_t)(lrow * 80 + lhalf * 32);

    float4 av[MI];

#define LOAD_A(ch)                                                          \
    do {                                                                    \
        _Pragma("unroll")                                                   \
        for (int q = 0; q < MI; q++) {                                      \
            int r_ = row0 + q * 32 + r0;                                    \
            av[q] = (r_ < M)                                                \
                ? *(const float4*)(A + (size_t)r_ * 256 + (ch) * 32 + c4 * 4) \
                : make_float4(0.f, 0.f, 0.f, 0.f);                          \
        }                                                                   \
    } while (0)

#define STORE_A(buf)                                                        \
    do {                                                                    \
        char* bp_ = smem + (buf) * BUFSZ + r0 * 80 + c4 * 8;                \
        _Pragma("unroll")                                                   \
        for (int q = 0; q < MI; q++) {                                      \
            float f_[4] = {av[q].x, av[q].y, av[q].z, av[q].w};             \
            union { __half b[4]; uint2 u; } ph_, pl_;                       \
            _Pragma("unroll")                                               \
            for (int j = 0; j < 4; j++) {                                   \
                __half h_ = __float2half(f_[j]);                            \
                ph_.b[j] = h_;                                              \
                pl_.b[j] = __float2half(f_[j] - __half2float(h_));          \
            }                                                               \
            *(uint2*)(bp_ + q * 2560) = ph_.u;                              \
            *(uint2*)(bp_ + ABYTES + q * 2560) = pl_.u;                     \
        }                                                                   \
    } while (0)

#define ISSUE_W(ch, buf)                                                    \
    do {                                                                    \
        uint32_t b_ = sb + (buf) * BUFSZ + WOFF + wsoff;                    \
        const __half* pw_ = Wp + wgoff + (ch) * 32;                         \
        cp16(b_, pw_);                                                      \
        cp16(b_ + 16, pw_ + 8);                                             \
    } while (0)

    // prologue: chunk 0 into buffer 0
    ISSUE_W(0, 0);
    cp_commit();
    LOAD_A(0);
    STORE_A(0);
    cp_wait0();
    __syncthreads();

#pragma unroll 2
    for (int ch = 0; ch < 8; ch++) {
        int buf = ch & 1;
        if (ch < 7) {
            ISSUE_W(ch + 1, buf ^ 1);
            cp_commit();
            LOAD_A(ch + 1);
        }
        // ---- compute on buf: 2 k16-steps, term-sequential ----
        uint32_t base = sb + buf * BUFSZ;
#pragma unroll
        for (int ks = 0; ks < 2; ks++) {
            uint32_t Af[MI][4], Bf[2][4];
            uint32_t acol = (uint32_t)((ks * 16 + a_kh) * 2);
            uint32_t bcol = (uint32_t)((ks * 16 + b_kh) * 2);
            // B fragments (W fp16)
#pragma unroll
            for (int nj = 0; nj < 2; nj++)
                ldm_x4(Bf[nj], base + WOFF +
                               (uint32_t)((wc * 32 + nj * 16 + b_n) * 80) + bcol);
            // term 1: Al x W
#pragma unroll
            for (int mi = 0; mi < MI; mi++)
                ldm_x4(Af[mi], base + ABYTES +
                               (uint32_t)((wr * (MI * 16) + mi * 16 + a_row) * 80) + acol);
#pragma unroll
            for (int mi = 0; mi < MI; mi++)
#pragma unroll
                for (int ni = 0; ni < 4; ni++) {
                    int nj = ni >> 1, off = (ni & 1) * 2;
                    mma_f16(acc[mi][ni], Af[mi], Bf[nj][off], Bf[nj][off + 1]);
                }
            // term 2: Ah x W (reload A hi over Af)
#pragma unroll
            for (int mi = 0; mi < MI; mi++)
                ldm_x4(Af[mi], base +
                               (uint32_t)((wr * (MI * 16) + mi * 16 + a_row) * 80) + acol);
#pragma unroll
            for (int mi = 0; mi < MI; mi++)
#pragma unroll
                for (int ni = 0; ni < 4; ni++) {
                    int nj = ni >> 1, off = (ni & 1) * 2;
                    mma_f16(acc[mi][ni], Af[mi], Bf[nj][off], Bf[nj][off + 1]);
                }
        }
        if (ch < 7) {
            STORE_A(buf ^ 1);
            cp_wait0();
            __syncthreads();
        }
    }

    // ---- epilogue: regs -> gmem with flags ----
#pragma unroll
    for (int mi = 0; mi < MI; mi++) {
        int m0 = row0 + wr * (MI * 16) + mi * 16 + (lane >> 2);
        int m1 = m0 + 8;
        float rs0 = 0.f, rs1 = 0.f;
        if (flags & 8) {
            if (m0 < M) rs0 = rowscale[m0];
            if (m1 < M) rs1 = rowscale[m1];
        }
#pragma unroll
        for (int ni = 0; ni < 4; ni++) {
            int nc = col0 + wc * 32 + ni * 8 + (lane & 3) * 2;
            float b0 = 0.f, b1 = 0.f;
            if (flags & 12) { b0 = bias[nc]; b1 = bias[nc + 1]; }
            float* a = acc[mi][ni];
            if (m0 < M) {
                float v0 = a[0], v1 = a[1];
                if (flags & 4) { v0 += b0; v1 += b1; }
                if (flags & 8) { v0 = fmaf(rs0, b0, v0); v1 = fmaf(rs0, b1, v1); }
                if (flags & 2) {
                    v0 += Cprev[(size_t)m0 * 256 + nc];
                    v1 += Cprev[(size_t)m0 * 256 + nc + 1];
                }
                if (flags & 1) { v0 = fmaxf(v0, 0.f); v1 = fmaxf(v1, 0.f); }
                *(float2*)(C + (size_t)m0 * ldc + nc) = make_float2(v0, v1);
            }
            if (m1 < M) {
                float v0 = a[2], v1 = a[3];
                if (flags & 4) { v0 += b0; v1 += b1; }
                if (flags & 8) { v0 = fmaf(rs1, b0, v0); v1 = fmaf(rs1, b1, v1); }
                if (flags & 2) {
                    v0 += Cprev[(size_t)m1 * 256 + nc];
                    v1 += Cprev[(size_t)m1 * 256 + nc + 1];
                }
                if (flags & 1) { v0 = fmaxf(v0, 0.f); v1 = fmaxf(v1, 0.f); }
                *(float2*)(C + (size_t)m1 * ldc + nc) = make_float2(v0, v1);
            }
        }
    }
#undef LOAD_A
#undef STORE_A
#undef ISSUE_W
}

// ---------------------------------------------------------------------------
// Embed: x = atom @ embed_w + embed_b
// ---------------------------------------------------------------------------
#define EMB_NODES 16
__global__ void __launch_bounds__(256) embed_kernel(
    const float* __restrict__ atom, const float* __restrict__ w,
    const float* __restrict__ b)
{
    __shared__ float s_af[EMB_NODES][NATOM];
    int n0 = blockIdx.x * EMB_NODES;
    int tid = threadIdx.x;
    for (int i = tid; i < EMB_NODES * NATOM; i += 256) {
        int r = i / NATOM, c = i % NATOM;
        int n = n0 + r;
        s_af[r][c] = (n < N_NODES) ? atom[(size_t)n * NATOM + c] : 0.f;
    }
    __syncthreads();
    int j = tid;
    float acc[EMB_NODES];
    float bj = b[j];
#pragma unroll
    for (int r = 0; r < EMB_NODES; r++) acc[r] = bj;
    for (int k = 0; k < NATOM; k++) {
        float wv = w[k * HID + j];
#pragma unroll
        for (int r = 0; r < EMB_NODES; r++) acc[r] = fmaf(s_af[r][k], wv, acc[r]);
    }
#pragma unroll
    for (int r = 0; r < EMB_NODES; r++) {
        int n = n0 + r;
        if (n < N_NODES) g_x[(size_t)n * HID + j] = acc[r];
    }
}

// ---------------------------------------------------------------------------
// CSR build
// ---------------------------------------------------------------------------
__global__ void count_kernel(const int* __restrict__ dst)
{
    int e = blockIdx.x * blockDim.x + threadIdx.x;
    if (e < N_EDGES) atomicAdd(&g_deg[dst[e]], 1);
}

// one block, 1024 threads, 10 elems/thread; coalesced smem staging + shuffle scan
__global__ void __launch_bounds__(1024) scan_kernel()
{
    __shared__ int sdeg[10240];
    __shared__ int warpsum[32];
    int tid = threadIdx.x;
#pragma unroll
    for (int i = 0; i < 10; i++) {
        int idx = i * 1024 + tid;
        sdeg[idx] = (idx < N_NODES) ? g_deg[idx] : 0;
    }
    __syncthreads();
    int base = tid * 10;
    int v[10];
    int tot = 0;
#pragma unroll
    for (int i = 0; i < 10; i++) {
        v[i] = sdeg[base + i];
        tot += v[i];
    }
    int lane = tid & 31, wid = tid >> 5;
    int x = tot;
#pragma unroll
    for (int off = 1; off < 32; off <<= 1) {
        int y = __shfl_up_sync(~0u, x, off);
        if (lane >= off) x += y;
    }
    if (lane == 31) warpsum[wid] = x;
    __syncthreads();
    if (wid == 0) {
        int w = warpsum[lane];
#pragma unroll
        for (int off = 1; off < 32; off <<= 1) {
            int y = __shfl_up_sync(~0u, w, off);
            if (lane >= off) w += y;
        }
        warpsum[lane] = w;
    }
    __syncthreads();
    int run = x - tot + (wid ? warpsum[wid - 1] : 0);
    if (tid == 0) g_rowptr[0] = 0;
#pragma unroll
    for (int i = 0; i < 10; i++) {
        int idx = base + i;
        if (idx < N_NODES) {
            g_cursor[idx] = run;
            run += v[i];
            g_rowptr[idx + 1] = run;
            g_degf[idx] = (float)v[i];
        }
    }
}

__global__ void fill_kernel(const int* __restrict__ src,
                            const int* __restrict__ dst,
                            const float* __restrict__ ef)
{
    int e = blockIdx.x * blockDim.x + threadIdx.x;
    if (e >= N_EDGES) return;
    int d = dst[e];
    int pos = atomicAdd(&g_cursor[d], 1);
    g_ssrc[pos] = src[e];
#pragma unroll
    for (int q = 0; q < NBOND; q++)
        g_sef[(size_t)pos * NBOND + q] = ef[(size_t)e * NBOND + q];
}

// ---------------------------------------------------------------------------
// Aggregate: ragg[n] = sum_{e in-edges} relu(xa[src_e] + xb[n] + ef_e@W1c + b1)
// ---------------------------------------------------------------------------
#define CH 16
__global__ void __launch_bounds__(256) aggregate_kernel(
    const float* __restrict__ xa, const float* __restrict__ xb,
    const float* __restrict__ w1c, const float* __restrict__ b1,
    float* __restrict__ ragg)
{
    __shared__ float s_w[NBOND][256];
    __shared__ float s_ef[CH][NBOND];
    __shared__ int s_src[CH];

    int n = blockIdx.x;
    int c = threadIdx.x;
    for (int i = c; i < NBOND * 256; i += 256)
        s_w[i >> 8][i & 255] = w1c[i];

    float base_v = b1[c] + xb[(size_t)n * HID + c];
    int beg = g_rowptr[n], end = g_rowptr[n + 1];
    float acc = 0.f;
    __syncthreads();

    for (int b0 = beg; b0 < end; b0 += CH) {
        int m = min(CH, end - b0);
        __syncthreads();
        if (c < m) s_src[c] = g_ssrc[b0 + c];
        if (c < m * NBOND) s_ef[c / NBOND][c % NBOND] = g_sef[(size_t)b0 * NBOND + c];
        __syncthreads();
        for (int j = 0; j < m; j++) {
            float t = base_v + xa[(size_t)s_src[j] * HID + c];
#pragma unroll
            for (int q = 0; q < NBOND; q++)
                t = fmaf(s_ef[j][q], s_w[q][c], t);
            acc += fmaxf(t, 0.f);
        }
    }
    ragg[(size_t)n * HID + c] = acc;
}

// ---------------------------------------------------------------------------
// Readout final: out = mean_n( r2[n,:] . w3 + b3 )
// ---------------------------------------------------------------------------
__global__ void __launch_bounds__(256) readout_final(
    const float* __restrict__ r2, const float* __restrict__ w3,
    const float* __restrict__ b3, float* __restrict__ out)
{
    __shared__ float sred[256];
    int n = blockIdx.x * 256 + threadIdx.x;
    float v = 0.f;
    if (n < N_NODES) {
        const float* row = r2 + (size_t)n * 128;
        float s = 0.f;
#pragma unroll
        for (int k = 0; k < 128; k += 4) {
            float4 rv = *(const float4*)(row + k);
            float4 wv = *(const float4*)(w3 + k);
            s += rv.x * wv.x + rv.y * wv.y + rv.z * wv.z + rv.w * wv.w;
        }
        v = (s + b3[0]) * (1.0f / N_NODES);
    }
    sred[threadIdx.x] = v;
    __syncthreads();
    for (int st = 128; st > 0; st >>= 1) {
        if (threadIdx.x < st) sred[threadIdx.x] += sred[threadIdx.x + st];
        __syncthreads();
    }
    if (threadIdx.x == 0) atomicAdd(out, sred[0]);
}

// ---------------------------------------------------------------------------
// Launch
// ---------------------------------------------------------------------------
extern "C" void kernel_launch(void* const* d_in, const int* in_sizes, int n_in,
                              void* d_out, int out_size)
{
    const float* atom = (const float*)d_in[0];
    const int*   eidx = (const int*)d_in[1];
    const float* ef   = (const float*)d_in[2];
    const float* embw = (const float*)d_in[3];
    const float* embb = (const float*)d_in[4];
    const float* mw1  = (const float*)d_in[5];
    const float* mb1  = (const float*)d_in[6];
    const float* mw2  = (const float*)d_in[7];
    const float* mb2  = (const float*)d_in[8];
    const float* uw1  = (const float*)d_in[9];
    const float* ub1  = (const float*)d_in[10];
    const float* uw2  = (const float*)d_in[11];
    const float* ub2  = (const float*)d_in[12];
    const float* rw1  = (const float*)d_in[13];
    const float* rb1  = (const float*)d_in[14];
    const float* rw2  = (const float*)d_in[15];
    const float* rb2  = (const float*)d_in[16];
    const float* rw3  = (const float*)d_in[17];
    const float* rb3  = (const float*)d_in[18];

    const int* src = eidx;
    const int* dst = eidx + N_EDGES;

    float *px, *pxa, *pxb, *pagg, *pt1, *ph, *pdegf;
    int* pdeg;
    __half* pwt;
    cudaGetSymbolAddress((void**)&px,    g_x);
    cudaGetSymbolAddress((void**)&pxa,   g_xa);
    cudaGetSymbolAddress((void**)&pxb,   g_xb);
    cudaGetSymbolAddress((void**)&pagg,  g_agg);
    cudaGetSymbolAddress((void**)&pt1,   g_t1);
    cudaGetSymbolAddress((void**)&ph,    g_h);
    cudaGetSymbolAddress((void**)&pdeg,  g_deg);
    cudaGetSymbolAddress((void**)&pdegf, g_degf);
    cudaGetSymbolAddress((void**)&pwt,   g_wt);

    const int SM4 = 2 * 30720;   // tgemm<4>: 61440
    const int SM5 = 2 * 35840;   // tgemm<5>: 71680
    cudaFuncSetAttribute(tgemm<4>, cudaFuncAttributeMaxDynamicSharedMemorySize,
                         SM4);
    cudaFuncSetAttribute(tgemm<5>, cudaFuncAttributeMaxDynamicSharedMemorySize,
                         SM5);

    // weight transform (once), embed, CSR
    wsplit_kernel<<<dim3(8, 8, NSLOTS), dim3(32, 8)>>>(mw1, uw1, mw2, uw2,
                                                       rw1, rw2, pwt);
    embed_kernel<<<(N_NODES + EMB_NODES - 1) / EMB_NODES, 256>>>(atom, embw, embb);
    cudaMemsetAsync(pdeg, 0, sizeof(int) * N_NODES);
    count_kernel<<<(N_EDGES + 255) / 256, 256>>>(dst);
    scan_kernel<<<1, 1024>>>();
    fill_kernel<<<(N_EDGES + 255) / 256, 256>>>(src, dst, ef);

    const int MT5 = (N_NODES + 159) / 160;     // 63
    dim3 gG3(2, (N_NODES + 127) / 128, 3);     // 2 x 79 x 3  (tgemm<4>)
    dim3 gS(2, MT5, 1);                        // 2 x 63      (tgemm<5>)

    for (int l = 0; l < NLAYERS; l++) {
        const float* W1 = mw1 + (size_t)l * 518 * HID;

        // xa = x@W1a, xb = x@W1b, t1 = x@U1a
        tgemm<4><<<gG3, 256, SM4>>>(px, pwt, l * 6 + 0, l * 6 + 1,
                                    l * 6 + 2, nullptr, nullptr, nullptr,
                                    pxa, pxb, pt1, N_NODES, 256, 0);

        // ragg[n] = sum relu(xa[src]+xb[n]+ef@W1c+b1)
        aggregate_kernel<<<N_NODES, 256>>>(pxa, pxb, W1 + 512 * HID,
                                           mb1 + (size_t)l * HID, pagg);

        // agg = ragg@W2 + deg*b2
        tgemm<5><<<gS, 256, SM5>>>(pagg, pwt, l * 6 + 3, 0, 0,
                                   mb2 + (size_t)l * HID, nullptr, pdegf,
                                   ph, nullptr, nullptr, N_NODES, 256, 8);

        // h = relu(agg@U1b + ub1 + t1)
        tgemm<5><<<gS, 256, SM5>>>(ph, pwt, l * 6 + 4, 0, 0,
                                   ub1 + (size_t)l * HID, pt1, nullptr,
                                   pagg, nullptr, nullptr, N_NODES, 256, 7);

        // x = h@U2 + ub2
        tgemm<5><<<gS, 256, SM5>>>(pagg, pwt, l * 6 + 5, 0, 0,
                                   ub2 + (size_t)l * HID, nullptr, nullptr,
                                   px, nullptr, nullptr, N_NODES, 256, 4);
    }

    // readout
    tgemm<5><<<gS, 256, SM5>>>(px, pwt, 36, 0, 0, rb1, nullptr,
                               nullptr, pt1, nullptr, nullptr, N_NODES, 256, 5);
    dim3 gR(1, MT5, 1);
    tgemm<5><<<gR, 256, SM5>>>(pt1, pwt, 37, 0, 0, rb2, nullptr,
                               nullptr, ph, nullptr, nullptr, N_NODES, 128, 5);

    cudaMemsetAsync(d_out, 0, sizeof(float));
    readout_final<<<(N_NODES + 255) / 256, 256>>>(ph, rw3, rb3, (float*)d_out);
}

// round 10
// speedup vs baseline: 6.3096x; 1.1436x over previous
#include <cuda_runtime.h>
#include <cuda_fp16.h>
#include <cstdint>

#define N_NODES 10000
#define N_EDGES 160000
#define HID 256
#define NBOND 6
#define NATOM 62
#define NLAYERS 6
#define NSLOTS 26
#define NCOMB 22

// ---------------- scratch (device globals; no allocation allowed) ----------
__device__ float g_x[N_NODES * HID];
__device__ float g_xa[N_NODES * HID];
__device__ float g_xb[N_NODES * HID];
__device__ float g_agg[N_NODES * HID];
__device__ float g_t1[N_NODES * HID];
__device__ float g_h[N_NODES * HID];

__device__ int   g_deg[N_NODES];
__device__ int   g_rowptr[N_NODES + 1];
__device__ int   g_cursor[N_NODES];
__device__ int   g_ssrc[N_EDGES];
__device__ float g_sef[N_EDGES * NBOND];
__device__ float g_degf[N_NODES];

// combined fp32 weight scratch (22 x 256x256) + combined bias vectors
__device__ float g_wcomb[NCOMB * 65536];
__device__ float g_vbias[NCOMB * 256];

// transposed fp16 weight pool: [slot][n][k], slot stride 256*256
__device__ __half g_wt[NSLOTS * 256 * 256];

// ---------------- helpers ---------------------------------------------------
__device__ __forceinline__ uint32_t smem_u32(const void* p) {
    uint32_t a;
    asm("{ .reg .u64 t; cvta.to.shared.u64 t, %1; cvt.u32.u64 %0, t; }"
        : "=r"(a) : "l"(p));
    return a;
}
__device__ __forceinline__ void ldm_x4(uint32_t* r, uint32_t addr) {
    asm volatile("ldmatrix.sync.aligned.m8n8.x4.shared.b16 {%0,%1,%2,%3}, [%4];"
                 : "=r"(r[0]), "=r"(r[1]), "=r"(r[2]), "=r"(r[3]) : "r"(addr));
}
__device__ __forceinline__ void mma_f16(float* c, const uint32_t* a,
                                        uint32_t b0, uint32_t b1) {
    asm volatile(
        "mma.sync.aligned.m16n8k16.row.col.f32.f16.f16.f32 "
        "{%0,%1,%2,%3}, {%4,%5,%6,%7}, {%8,%9}, {%0,%1,%2,%3};"
        : "+f"(c[0]), "+f"(c[1]), "+f"(c[2]), "+f"(c[3])
        : "r"(a[0]), "r"(a[1]), "r"(a[2]), "r"(a[3]), "r"(b0), "r"(b1));
}
__device__ __forceinline__ void cp16(uint32_t dst, const void* src) {
    asm volatile("cp.async.cg.shared.global [%0], [%1], 16;"
                 :: "r"(dst), "l"(src));
}
__device__ __forceinline__ void cp_commit() {
    asm volatile("cp.async.commit_group;" ::: "memory");
}
__device__ __forceinline__ void cp_wait0() {
    asm volatile("cp.async.wait_group 0;" ::: "memory");
}

// ---------------------------------------------------------------------------
// Combo source pointers (shared by combine_kernel / vbias_kernel):
//  c in [0,6):   P = W2_l (mw2),  Q = U1b_l          (WU_l = W2@U1b)
//  c in [6,21):  P = U2_m (uw2),  Q in {W1a,W1b,U1a} of layer m+1
//  c == 21:      P = U2_5,        Q = rw1
// ---------------------------------------------------------------------------
__device__ __forceinline__ const float* combo_Q(
    int c, const float* mw1, const float* uw1, const float* rw1)
{
    if (c < 6) return uw1 + (size_t)c * 131072 + 65536;
    if (c < 21) {
        int m = (c - 6) / 3, t = (c - 6) % 3;
        int l = m + 1;
        if (t == 0) return mw1 + (size_t)l * 518 * 256;
        if (t == 1) return mw1 + (size_t)l * 518 * 256 + 65536;
        return uw1 + (size_t)l * 131072;
    }
    return rw1;
}

// fp32 setup GEMM: g_wcomb[c] = P_c @ Q_c   (256x256x256), grid (2,2,22)
__global__ void __launch_bounds__(256) combine_kernel(
    const float* __restrict__ mw1, const float* __restrict__ uw1,
    const float* __restrict__ mw2, const float* __restrict__ uw2,
    const float* __restrict__ rw1)
{
    int c = blockIdx.z;
    const float* P = (c < 6) ? mw2 + (size_t)c * 65536
                   : (c < 21) ? uw2 + (size_t)((c - 6) / 3) * 65536
                              : uw2 + (size_t)5 * 65536;
    const float* Q = combo_Q(c, mw1, uw1, rw1);
    float* C = g_wcomb + (size_t)c * 65536;

    __shared__ float As[16][128];
    __shared__ float Ws[16][128];
    int col0 = blockIdx.x * 128, row0 = blockIdx.y * 128;
    int tid = threadIdx.x;
    int tx = tid & 15, ty = tid >> 4;

    float acc[8][8];
#pragma unroll
    for (int i = 0; i < 8; i++)
#pragma unroll
        for (int j = 0; j < 8; j++) acc[i][j] = 0.f;

    int ar = tid >> 2, ac = (tid & 3) << 2;
    int wr = tid >> 5, wc = (tid & 31) << 2;

    for (int kt = 0; kt < 256; kt += 16) {
#pragma unroll
        for (int i = 0; i < 2; i++) {
            int r = ar + i * 64;
            float4 v = *(const float4*)(P + (size_t)(row0 + r) * 256 + kt + ac);
            As[ac + 0][r] = v.x; As[ac + 1][r] = v.y;
            As[ac + 2][r] = v.z; As[ac + 3][r] = v.w;
        }
#pragma unroll
        for (int i = 0; i < 2; i++) {
            int r = wr + i * 8;
            *(float4*)&Ws[r][wc] =
                *(const float4*)(Q + (size_t)(kt + r) * 256 + col0 + wc);
        }
        __syncthreads();
#pragma unroll
        for (int kk = 0; kk < 16; kk++) {
            float4 a0 = *(const float4*)&As[kk][ty * 4];
            float4 a1 = *(const float4*)&As[kk][64 + ty * 4];
            float4 w0 = *(const float4*)&Ws[kk][tx * 4];
            float4 w1 = *(const float4*)&Ws[kk][64 + tx * 4];
            float af[8] = {a0.x, a0.y, a0.z, a0.w, a1.x, a1.y, a1.z, a1.w};
            float wf[8] = {w0.x, w0.y, w0.z, w0.w, w1.x, w1.y, w1.z, w1.w};
#pragma unroll
            for (int i = 0; i < 8; i++)
#pragma unroll
                for (int j = 0; j < 8; j++)
                    acc[i][j] = fmaf(af[i], wf[j], acc[i][j]);
        }
        __syncthreads();
    }
#pragma unroll
    for (int ih = 0; ih < 2; ih++)
#pragma unroll
        for (int i = 0; i < 4; i++) {
            int r = row0 + ih * 64 + ty * 4 + i;
#pragma unroll
            for (int jh = 0; jh < 2; jh++)
#pragma unroll
                for (int j = 0; j < 4; j++)
                    C[(size_t)r * 256 + col0 + jh * 64 + tx * 4 + j] =
                        acc[ih * 4 + i][jh * 4 + j];
        }
}

// combined bias vectors: g_vbias[c] = b_c @ Q_c (+ rb1 for c==21), grid (22)
__global__ void __launch_bounds__(256) vbias_kernel(
    const float* __restrict__ mw1, const float* __restrict__ uw1,
    const float* __restrict__ rw1, const float* __restrict__ mb2,
    const float* __restrict__ ub2, const float* __restrict__ rb1)
{
    int c = blockIdx.x;
    const float* b = (c < 6) ? mb2 + (size_t)c * 256
                   : (c < 21) ? ub2 + (size_t)((c - 6) / 3) * 256
                              : ub2 + (size_t)5 * 256;
    const float* Q = combo_Q(c, mw1, uw1, rw1);
    int n = threadIdx.x;
    float s = 0.f;
    for (int k = 0; k < 256; k++) s = fmaf(b[k], Q[(size_t)k * 256 + n], s);
    if (c == 21) s += rb1[n];
    g_vbias[(size_t)c * 256 + n] = s;
}

// ---------------------------------------------------------------------------
// Weight transpose to fp16: pool[z][n][k] = fp16(S_z[k][n])
//  z 0..1 : W1a_0, W1b_0 (mw1)    z 2 : U1a_0 (uw1)
//  z 3..24: g_wcomb combos 0..21  z 25: rw2 (N=128)
// grid (8, 8, 26), block (32, 8)
// ---------------------------------------------------------------------------
__global__ void wsplit_kernel(
    const float* __restrict__ mw1, const float* __restrict__ uw1,
    const float* __restrict__ rw2, __half* __restrict__ wt)
{
    int z = blockIdx.z;
    const float* W;
    int N = 256;
    if (z < 2)       W = mw1 + (size_t)z * 65536;
    else if (z == 2) W = uw1;
    else if (z < 25) W = g_wcomb + (size_t)(z - 3) * 65536;
    else { W = rw2; N = 128; }

    int k0 = blockIdx.x * 32, n0 = blockIdx.y * 32;
    if (n0 >= N) return;
    __shared__ float t[32][33];
    for (int i = threadIdx.y; i < 32; i += 8)
        t[i][threadIdx.x] = W[(size_t)(k0 + i) * N + n0 + threadIdx.x];
    __syncthreads();
    size_t base = (size_t)z * 65536;
    for (int i = threadIdx.y; i < 32; i += 8)
        wt[base + (size_t)(n0 + i) * 256 + k0 + threadIdx.x] =
            __float2half(t[threadIdx.x][i]);
}

// ---------------------------------------------------------------------------
// fp16 split-precision GEMM via mma.sync, templated M-tile:
//   C[M, N tile] = op(A[M,256] @ Wt_slot^T), 2-term: ah*w + al*w
// flags: 1=RELU 2=ADDC(Cprev) 4=BIAS(per-z bias ptr) 8=ROWB(rowscale*rbias)
// ---------------------------------------------------------------------------
template <int MI>
__global__ void __launch_bounds__(256, (MI == 4) ? 2 : 1) tgemm(
    const float* __restrict__ A,
    const __half* __restrict__ wt,
    int s0, int s1, int s2,
    const float* __restrict__ b0p, const float* __restrict__ b1p,
    const float* __restrict__ b2p,
    const float* __restrict__ rbias, const float* __restrict__ rowscale,
    const float* __restrict__ Cprev,
    float* C0, float* C1, float* C2,
    int M, int ldc, int flags)
{
    constexpr int TM = MI * 32;
    constexpr int ABYTES = TM * 80;
    constexpr int WOFF = 2 * ABYTES;
    constexpr int BUFSZ = WOFF + 10240;

    extern __shared__ __align__(16) char smem[];

    int bz = blockIdx.z;
    int slot = (bz == 0) ? s0 : (bz == 1 ? s1 : s2);
    float* C = (bz == 0) ? C0 : (bz == 1 ? C1 : C2);
    const float* bias = (bz == 0) ? b0p : (bz == 1 ? b1p : b2p);
    const __half* Wp = wt + (size_t)slot * 65536;

    uint32_t sb = smem_u32(smem);
    int tid = threadIdx.x;
    int lane = tid & 31, wid = tid >> 5;
    int wr = wid >> 2, wc = wid & 3;
    int row0 = blockIdx.y * TM, col0 = blockIdx.x * 128;

    float acc[MI][4][4];
#pragma unroll
    for (int i = 0; i < MI; i++)
#pragma unroll
        for (int j = 0; j < 4; j++)
#pragma unroll
            for (int k = 0; k < 4; k++) acc[i][j][k] = 0.f;

    int a_row = lane & 15;
    int a_kh = (lane >> 4) * 8;
    int bg = lane >> 3;
    int b_n = (lane & 7) + (bg >> 1) * 8;
    int b_kh = (bg & 1) * 8;

    int r0 = tid >> 3;
    int c4 = tid & 7;
    int lrow = tid >> 1;
    int lhalf = tid & 1;
    size_t wgoff = (size_t)(col0 + lrow) * 256 + lhalf * 16;
    uint32_t wsoff = (uint32_t)(lrow * 80 + lhalf * 32);

    float4 av[MI];

#define LOAD_A(ch)                                                          \
    do {                                                                    \
        _Pragma("unroll")                                                   \
        for (int q = 0; q < MI; q++) {                                      \
            int r_ = row0 + q * 32 + r0;                                    \
            av[q] = (r_ < M)                                                \
                ? *(const float4*)(A + (size_t)r_ * 256 + (ch) * 32 + c4 * 4) \
                : make_float4(0.f, 0.f, 0.f, 0.f);                          \
        }                                                                   \
    } while (0)

#define STORE_A(buf)                                                        \
    do {                                                                    \
        char* bp_ = smem + (buf) * BUFSZ + r0 * 80 + c4 * 8;                \
        _Pragma("unroll")                                                   \
        for (int q = 0; q < MI; q++) {                                      \
            float f_[4] = {av[q].x, av[q].y, av[q].z, av[q].w};             \
            union { __half b[4]; uint2 u; } ph_, pl_;                       \
            _Pragma("unroll")                                               \
            for (int j = 0; j < 4; j++) {                                   \
                __half h_ = __float2half(f_[j]);                            \
                ph_.b[j] = h_;                                              \
                pl_.b[j] = __float2half(f_[j] - __half2float(h_));          \
            }                                                               \
            *(uint2*)(bp_ + q * 2560) = ph_.u;                              \
            *(uint2*)(bp_ + ABYTES + q * 2560) = pl_.u;                     \
        }                                                                   \
    } while (0)

#define ISSUE_W(ch, buf)                                                    \
    do {                                                                    \
        uint32_t b_ = sb + (buf) * BUFSZ + WOFF + wsoff;                    \
        const __half* pw_ = Wp + wgoff + (ch) * 32;                         \
        cp16(b_, pw_);                                                      \
        cp16(b_ + 16, pw_ + 8);                                             \
    } while (0)

    ISSUE_W(0, 0);
    cp_commit();
    LOAD_A(0);
    STORE_A(0);
    cp_wait0();
    __syncthreads();

#pragma unroll 2
    for (int ch = 0; ch < 8; ch++) {
        int buf = ch & 1;
        if (ch < 7) {
            ISSUE_W(ch + 1, buf ^ 1);
            cp_commit();
            LOAD_A(ch + 1);
        }
        uint32_t base = sb + buf * BUFSZ;
#pragma unroll
        for (int ks = 0; ks < 2; ks++) {
            uint32_t Af[MI][4], Bf[2][4];
            uint32_t acol = (uint32_t)((ks * 16 + a_kh) * 2);
            uint32_t bcol = (uint32_t)((ks * 16 + b_kh) * 2);
#pragma unroll
            for (int nj = 0; nj < 2; nj++)
                ldm_x4(Bf[nj], base + WOFF +
                               (uint32_t)((wc * 32 + nj * 16 + b_n) * 80) + bcol);
#pragma unroll
            for (int mi = 0; mi < MI; mi++)
                ldm_x4(Af[mi], base + ABYTES +
                               (uint32_t)((wr * (MI * 16) + mi * 16 + a_row) * 80) + acol);
#pragma unroll
            for (int mi = 0; mi < MI; mi++)
#pragma unroll
                for (int ni = 0; ni < 4; ni++) {
                    int nj = ni >> 1, off = (ni & 1) * 2;
                    mma_f16(acc[mi][ni], Af[mi], Bf[nj][off], Bf[nj][off + 1]);
                }
#pragma unroll
            for (int mi = 0; mi < MI; mi++)
                ldm_x4(Af[mi], base +
                               (uint32_t)((wr * (MI * 16) + mi * 16 + a_row) * 80) + acol);
#pragma unroll
            for (int mi = 0; mi < MI; mi++)
#pragma unroll
                for (int ni = 0; ni < 4; ni++) {
                    int nj = ni >> 1, off = (ni & 1) * 2;
                    mma_f16(acc[mi][ni], Af[mi], Bf[nj][off], Bf[nj][off + 1]);
                }
        }
        if (ch < 7) {
            STORE_A(buf ^ 1);
            cp_wait0();
            __syncthreads();
        }
    }

    // ---- epilogue ----
#pragma unroll
    for (int mi = 0; mi < MI; mi++) {
        int m0 = row0 + wr * (MI * 16) + mi * 16 + (lane >> 2);
        int m1 = m0 + 8;
        float rs0 = 0.f, rs1 = 0.f;
        if (flags & 8) {
            if (m0 < M) rs0 = rowscale[m0];
            if (m1 < M) rs1 = rowscale[m1];
        }
#pragma unroll
        for (int ni = 0; ni < 4; ni++) {
            int nc = col0 + wc * 32 + ni * 8 + (lane & 3) * 2;
            float b0 = 0.f, b1 = 0.f, r0b = 0.f, r1b = 0.f;
            if (flags & 4) { b0 = bias[nc]; b1 = bias[nc + 1]; }
            if (flags & 8) { r0b = rbias[nc]; r1b = rbias[nc + 1]; }
            float* a = acc[mi][ni];
            if (m0 < M) {
                float v0 = a[0] + b0, v1 = a[1] + b1;
                if (flags & 8) { v0 = fmaf(rs0, r0b, v0); v1 = fmaf(rs0, r1b, v1); }
                if (flags & 2) {
                    v0 += Cprev[(size_t)m0 * 256 + nc];
                    v1 += Cprev[(size_t)m0 * 256 + nc + 1];
                }
                if (flags & 1) { v0 = fmaxf(v0, 0.f); v1 = fmaxf(v1, 0.f); }
                *(float2*)(C + (size_t)m0 * ldc + nc) = make_float2(v0, v1);
            }
            if (m1 < M) {
                float v0 = a[2] + b0, v1 = a[3] + b1;
                if (flags & 8) { v0 = fmaf(rs1, r0b, v0); v1 = fmaf(rs1, r1b, v1); }
                if (flags & 2) {
                    v0 += Cprev[(size_t)m1 * 256 + nc];
                    v1 += Cprev[(size_t)m1 * 256 + nc + 1];
                }
                if (flags & 1) { v0 = fmaxf(v0, 0.f); v1 = fmaxf(v1, 0.f); }
                *(float2*)(C + (size_t)m1 * ldc + nc) = make_float2(v0, v1);
            }
        }
    }
#undef LOAD_A
#undef STORE_A
#undef ISSUE_W
}

// ---------------------------------------------------------------------------
// Embed: x0 = atom @ embed_w + embed_b
// ---------------------------------------------------------------------------
#define EMB_NODES 16
__global__ void __launch_bounds__(256) embed_kernel(
    const float* __restrict__ atom, const float* __restrict__ w,
    const float* __restrict__ b)
{
    __shared__ float s_af[EMB_NODES][NATOM];
    int n0 = blockIdx.x * EMB_NODES;
    int tid = threadIdx.x;
    for (int i = tid; i < EMB_NODES * NATOM; i += 256) {
        int r = i / NATOM, c = i % NATOM;
        int n = n0 + r;
        s_af[r][c] = (n < N_NODES) ? atom[(size_t)n * NATOM + c] : 0.f;
    }
    __syncthreads();
    int j = tid;
    float acc[EMB_NODES];
    float bj = b[j];
#pragma unroll
    for (int r = 0; r < EMB_NODES; r++) acc[r] = bj;
    for (int k = 0; k < NATOM; k++) {
        float wv = w[k * HID + j];
#pragma unroll
        for (int r = 0; r < EMB_NODES; r++) acc[r] = fmaf(s_af[r][k], wv, acc[r]);
    }
#pragma unroll
    for (int r = 0; r < EMB_NODES; r++) {
        int n = n0 + r;
        if (n < N_NODES) g_x[(size_t)n * HID + j] = acc[r];
    }
}

// ---------------------------------------------------------------------------
// CSR build
// ---------------------------------------------------------------------------
__global__ void count_kernel(const int* __restrict__ dst)
{
    int e = blockIdx.x * blockDim.x + threadIdx.x;
    if (e < N_EDGES) atomicAdd(&g_deg[dst[e]], 1);
}

__global__ void __launch_bounds__(1024) scan_kernel()
{
    __shared__ int sdeg[10240];
    __shared__ int warpsum[32];
    int tid = threadIdx.x;
#pragma unroll
    for (int i = 0; i < 10; i++) {
        int idx = i * 1024 + tid;
        sdeg[idx] = (idx < N_NODES) ? g_deg[idx] : 0;
    }
    __syncthreads();
    int base = tid * 10;
    int v[10];
    int tot = 0;
#pragma unroll
    for (int i = 0; i < 10; i++) {
        v[i] = sdeg[base + i];
        tot += v[i];
    }
    int lane = tid & 31, wid = tid >> 5;
    int x = tot;
#pragma unroll
    for (int off = 1; off < 32; off <<= 1) {
        int y = __shfl_up_sync(~0u, x, off);
        if (lane >= off) x += y;
    }
    if (lane == 31) warpsum[wid] = x;
    __syncthreads();
    if (wid == 0) {
        int w = warpsum[lane];
#pragma unroll
        for (int off = 1; off < 32; off <<= 1) {
            int y = __shfl_up_sync(~0u, w, off);
            if (lane >= off) w += y;
        }
        warpsum[lane] = w;
    }
    __syncthreads();
    int run = x - tot + (wid ? warpsum[wid - 1] : 0);
    if (tid == 0) g_rowptr[0] = 0;
#pragma unroll
    for (int i = 0; i < 10; i++) {
        int idx = base + i;
        if (idx < N_NODES) {
            g_cursor[idx] = run;
            run += v[i];
            g_rowptr[idx + 1] = run;
            g_degf[idx] = (float)v[i];
        }
    }
}

__global__ void fill_kernel(const int* __restrict__ src,
                            const int* __restrict__ dst,
                            const float* __restrict__ ef)
{
    int e = blockIdx.x * blockDim.x + threadIdx.x;
    if (e >= N_EDGES) return;
    int d = dst[e];
    int pos = atomicAdd(&g_cursor[d], 1);
    g_ssrc[pos] = src[e];
#pragma unroll
    for (int q = 0; q < NBOND; q++)
        g_sef[(size_t)pos * NBOND + q] = ef[(size_t)e * NBOND + q];
}

// ---------------------------------------------------------------------------
// Aggregate: ragg[n] = sum_{e in-edges} relu(xa[src_e] + xb[n] + ef_e@W1c + b1)
// ---------------------------------------------------------------------------
#define CH 16
__global__ void __launch_bounds__(256) aggregate_kernel(
    const float* __restrict__ xa, const float* __restrict__ xb,
    const float* __restrict__ w1c, const float* __restrict__ b1,
    float* __restrict__ ragg)
{
    __shared__ float s_w[NBOND][256];
    __shared__ float s_ef[CH][NBOND];
    __shared__ int s_src[CH];

    int n = blockIdx.x;
    int c = threadIdx.x;
    for (int i = c; i < NBOND * 256; i += 256)
        s_w[i >> 8][i & 255] = w1c[i];

    float base_v = b1[c] + xb[(size_t)n * HID + c];
    int beg = g_rowptr[n], end = g_rowptr[n + 1];
    float acc = 0.f;
    __syncthreads();

    for (int b0 = beg; b0 < end; b0 += CH) {
        int m = min(CH, end - b0);
        __syncthreads();
        if (c < m) s_src[c] = g_ssrc[b0 + c];
        if (c < m * NBOND) s_ef[c / NBOND][c % NBOND] = g_sef[(size_t)b0 * NBOND + c];
        __syncthreads();
        for (int j = 0; j < m; j++) {
            float t = base_v + xa[(size_t)s_src[j] * HID + c];
#pragma unroll
            for (int q = 0; q < NBOND; q++)
                t = fmaf(s_ef[j][q], s_w[q][c], t);
            acc += fmaxf(t, 0.f);
        }
    }
    ragg[(size_t)n * HID + c] = acc;
}

// ---------------------------------------------------------------------------
// Readout final: out = mean_n( r2[n,:] . w3 + b3 )
// ---------------------------------------------------------------------------
__global__ void __launch_bounds__(256) readout_final(
    const float* __restrict__ r2, const float* __restrict__ w3,
    const float* __restrict__ b3, float* __restrict__ out)
{
    __shared__ float sred[256];
    int n = blockIdx.x * 256 + threadIdx.x;
    float v = 0.f;
    if (n < N_NODES) {
        const float* row = r2 + (size_t)n * 128;
        float s = 0.f;
#pragma unroll
        for (int k = 0; k < 128; k += 4) {
            float4 rv = *(const float4*)(row + k);
            float4 wv = *(const float4*)(w3 + k);
            s += rv.x * wv.x + rv.y * wv.y + rv.z * wv.z + rv.w * wv.w;
        }
        v = (s + b3[0]) * (1.0f / N_NODES);
    }
    sred[threadIdx.x] = v;
    __syncthreads();
    for (int st = 128; st > 0; st >>= 1) {
        if (threadIdx.x < st) sred[threadIdx.x] += sred[threadIdx.x + st];
        __syncthreads();
    }
    if (threadIdx.x == 0) atomicAdd(out, sred[0]);
}

// ---------------------------------------------------------------------------
// Launch
// ---------------------------------------------------------------------------
extern "C" void kernel_launch(void* const* d_in, const int* in_sizes, int n_in,
                              void* d_out, int out_size)
{
    const float* atom = (const float*)d_in[0];
    const int*   eidx = (const int*)d_in[1];
    const float* ef   = (const float*)d_in[2];
    const float* embw = (const float*)d_in[3];
    const float* embb = (const float*)d_in[4];
    const float* mw1  = (const float*)d_in[5];
    const float* mb1  = (const float*)d_in[6];
    const float* mw2  = (const float*)d_in[7];
    const float* mb2  = (const float*)d_in[8];
    const float* uw1  = (const float*)d_in[9];
    const float* ub1  = (const float*)d_in[10];
    const float* uw2  = (const float*)d_in[11];
    const float* ub2  = (const float*)d_in[12];
    const float* rw1  = (const float*)d_in[13];
    const float* rb1  = (const float*)d_in[14];
    const float* rw2  = (const float*)d_in[15];
    const float* rb2  = (const float*)d_in[16];
    const float* rw3  = (const float*)d_in[17];
    const float* rb3  = (const float*)d_in[18];

    const int* src = eidx;
    const int* dst = eidx + N_EDGES;

    float *px, *pxa, *pxb, *pagg, *pt1, *ph, *pdegf, *pvb;
    int* pdeg;
    __half* pwt;
    cudaGetSymbolAddress((void**)&px,    g_x);
    cudaGetSymbolAddress((void**)&pxa,   g_xa);
    cudaGetSymbolAddress((void**)&pxb,   g_xb);
    cudaGetSymbolAddress((void**)&pagg,  g_agg);
    cudaGetSymbolAddress((void**)&pt1,   g_t1);
    cudaGetSymbolAddress((void**)&ph,    g_h);
    cudaGetSymbolAddress((void**)&pdeg,  g_deg);
    cudaGetSymbolAddress((void**)&pdegf, g_degf);
    cudaGetSymbolAddress((void**)&pvb,   g_vbias);
    cudaGetSymbolAddress((void**)&pwt,   g_wt);

    const int SM4 = 2 * 30720;
    const int SM5 = 2 * 35840;
    cudaFuncSetAttribute(tgemm<4>, cudaFuncAttributeMaxDynamicSharedMemorySize,
                         SM4);
    cudaFuncSetAttribute(tgemm<5>, cudaFuncAttributeMaxDynamicSharedMemorySize,
                         SM5);

    // setup: combined weights, bias vectors, fp16 pool, embed, CSR
    combine_kernel<<<dim3(2, 2, NCOMB), 256>>>(mw1, uw1, mw2, uw2, rw1);
    vbias_kernel<<<NCOMB, 256>>>(mw1, uw1, rw1, mb2, ub2, rb1);
    wsplit_kernel<<<dim3(8, 8, NSLOTS), dim3(32, 8)>>>(mw1, uw1, rw2, pwt);
    embed_kernel<<<(N_NODES + EMB_NODES - 1) / EMB_NODES, 256>>>(atom, embw, embb);
    cudaMemsetAsync(pdeg, 0, sizeof(int) * N_NODES);
    count_kernel<<<(N_EDGES + 255) / 256, 256>>>(dst);
    scan_kernel<<<1, 1024>>>();
    fill_kernel<<<(N_EDGES + 255) / 256, 256>>>(src, dst, ef);

    const int MT5 = (N_NODES + 159) / 160;     // 63
    dim3 gG3(2, (N_NODES + 127) / 128, 3);     // tgemm<4>, 474 CTAs
    dim3 gS(2, MT5, 1);                        // tgemm<5>, 126 CTAs

    // layer 0 inputs: xa,xb,t1 from x0 (no bias; b1 handled in aggregate)
    tgemm<4><<<gG3, 256, SM4>>>(px, pwt, 0, 1, 2,
                                nullptr, nullptr, nullptr,
                                nullptr, nullptr, nullptr,
                                pxa, pxb, pt1, N_NODES, 256, 0);

    for (int l = 0; l < NLAYERS; l++) {
        const float* W1c = mw1 + (size_t)l * 518 * HID + 512 * HID;

        // ragg[n] = sum relu(xa[src]+xb[n]+ef@W1c+b1)
        aggregate_kernel<<<N_NODES, 256>>>(pxa, pxb, W1c,
                                           mb1 + (size_t)l * HID, pagg);

        // h = relu(ragg@(W2@U1b) + deg*(b2@U1b) + ub1 + t1)
        tgemm<5><<<gS, 256, SM5>>>(pagg, pwt, 3 + l, 0, 0,
                                   ub1 + (size_t)l * HID, nullptr, nullptr,
                                   pvb + (size_t)l * 256, pdegf, pt1,
                                   ph, nullptr, nullptr, N_NODES, 256,
                                   1 | 2 | 4 | 8);

        if (l < NLAYERS - 1) {
            // next xa,xb,t1 directly from h with combined U2@{W1a,W1b,U1a}
            int cb = 6 + 3 * l;
            tgemm<4><<<gG3, 256, SM4>>>(ph, pwt, 9 + 3 * l, 10 + 3 * l,
                                        11 + 3 * l,
                                        pvb + (size_t)cb * 256,
                                        pvb + (size_t)(cb + 1) * 256,
                                        pvb + (size_t)(cb + 2) * 256,
                                        nullptr, nullptr, nullptr,
                                        pxa, pxb, pt1, N_NODES, 256, 4);
        }
    }

    // readout r1 = relu(h@(U2_5@rw1) + (ub2_5@rw1 + rb1))
    tgemm<5><<<gS, 256, SM5>>>(ph, pwt, 24, 0, 0,
                               pvb + (size_t)21 * 256, nullptr, nullptr,
                               nullptr, nullptr, nullptr,
                               pt1, nullptr, nullptr, N_NODES, 256, 1 | 4);
    // r2 = relu(r1@rw2 + rb2)
    dim3 gR(1, MT5, 1);
    tgemm<5><<<gR, 256, SM5>>>(pt1, pwt, 25, 0, 0,
                               rb2, nullptr, nullptr,
                               nullptr, nullptr, nullptr,
                               pxa, nullptr, nullptr, N_NODES, 128, 1 | 4);

    cudaMemsetAsync(d_out, 0, sizeof(float));
    readout_final<<<(N_NODES + 255) / 256, 256>>>(pxa, rw3, rb3, (float*)d_out);
}

// round 11
// speedup vs baseline: 6.3798x; 1.0111x over previous
#include <cuda_runtime.h>
#include <cuda_fp16.h>
#include <cstdint>

#define N_NODES 10000
#define N_EDGES 160000
#define HID 256
#define NBOND 6
#define NATOM 62
#define NLAYERS 6
#define NSLOTS 26
#define NCOMB 22

// ---------------- scratch (device globals; no allocation allowed) ----------
__device__ float g_x[N_NODES * HID];
__device__ float g_xa[N_NODES * HID];   // used as __half[N*HID] for xa
__device__ float g_xb[N_NODES * HID];
__device__ float g_agg[N_NODES * HID];
__device__ float g_t1[N_NODES * HID];
__device__ float g_h[N_NODES * HID];

__device__ int   g_deg[N_NODES];
__device__ int   g_rowptr[N_NODES + 1];
__device__ int   g_cursor[N_NODES];
__device__ int   g_ssrc[N_EDGES];
__device__ float g_sef[N_EDGES * NBOND];
__device__ float g_degf[N_NODES];

// combined fp32 weight scratch (22 x 256x256) + combined bias vectors
__device__ float g_wcomb[NCOMB * 65536];
__device__ float g_vbias[NCOMB * 256];

// transposed fp16 weight pool: [slot][n][k], slot stride 256*256
__device__ __half g_wt[NSLOTS * 256 * 256];

// ---------------- helpers ---------------------------------------------------
__device__ __forceinline__ uint32_t smem_u32(const void* p) {
    uint32_t a;
    asm("{ .reg .u64 t; cvta.to.shared.u64 t, %1; cvt.u32.u64 %0, t; }"
        : "=r"(a) : "l"(p));
    return a;
}
__device__ __forceinline__ void ldm_x4(uint32_t* r, uint32_t addr) {
    asm volatile("ldmatrix.sync.aligned.m8n8.x4.shared.b16 {%0,%1,%2,%3}, [%4];"
                 : "=r"(r[0]), "=r"(r[1]), "=r"(r[2]), "=r"(r[3]) : "r"(addr));
}
__device__ __forceinline__ void mma_f16(float* c, const uint32_t* a,
                                        uint32_t b0, uint32_t b1) {
    asm volatile(
        "mma.sync.aligned.m16n8k16.row.col.f32.f16.f16.f32 "
        "{%0,%1,%2,%3}, {%4,%5,%6,%7}, {%8,%9}, {%0,%1,%2,%3};"
        : "+f"(c[0]), "+f"(c[1]), "+f"(c[2]), "+f"(c[3])
        : "r"(a[0]), "r"(a[1]), "r"(a[2]), "r"(a[3]), "r"(b0), "r"(b1));
}
__device__ __forceinline__ void cp16(uint32_t dst, const void* src) {
    asm volatile("cp.async.cg.shared.global [%0], [%1], 16;"
                 :: "r"(dst), "l"(src));
}
__device__ __forceinline__ void cp_commit() {
    asm volatile("cp.async.commit_group;" ::: "memory");
}
__device__ __forceinline__ void cp_wait0() {
    asm volatile("cp.async.wait_group 0;" ::: "memory");
}

// ---------------------------------------------------------------------------
// Combo source pointers:
//  c in [0,6):   P = W2_l (mw2),  Q = U1b_l          (WU_l = W2@U1b)
//  c in [6,21):  P = U2_m (uw2),  Q in {W1a,W1b,U1a} of layer m+1
//  c == 21:      P = U2_5,        Q = rw1
// ---------------------------------------------------------------------------
__device__ __forceinline__ const float* combo_Q(
    int c, const float* mw1, const float* uw1, const float* rw1)
{
    if (c < 6) return uw1 + (size_t)c * 131072 + 65536;
    if (c < 21) {
        int m = (c - 6) / 3, t = (c - 6) % 3;
        int l = m + 1;
        if (t == 0) return mw1 + (size_t)l * 518 * 256;
        if (t == 1) return mw1 + (size_t)l * 518 * 256 + 65536;
        return uw1 + (size_t)l * 131072;
    }
    return rw1;
}

// fp32 setup GEMM: g_wcomb[c] = P_c @ Q_c   (256x256x256), grid (2,2,22)
__global__ void __launch_bounds__(256) combine_kernel(
    const float* __restrict__ mw1, const float* __restrict__ uw1,
    const float* __restrict__ mw2, const float* __restrict__ uw2,
    const float* __restrict__ rw1)
{
    int c = blockIdx.z;
    const float* P = (c < 6) ? mw2 + (size_t)c * 65536
                   : (c < 21) ? uw2 + (size_t)((c - 6) / 3) * 65536
                              : uw2 + (size_t)5 * 65536;
    const float* Q = combo_Q(c, mw1, uw1, rw1);
    float* C = g_wcomb + (size_t)c * 65536;

    __shared__ float As[16][128];
    __shared__ float Ws[16][128];
    int col0 = blockIdx.x * 128, row0 = blockIdx.y * 128;
    int tid = threadIdx.x;
    int tx = tid & 15, ty = tid >> 4;

    float acc[8][8];
#pragma unroll
    for (int i = 0; i < 8; i++)
#pragma unroll
        for (int j = 0; j < 8; j++) acc[i][j] = 0.f;

    int ar = tid >> 2, ac = (tid & 3) << 2;
    int wr = tid >> 5, wc = (tid & 31) << 2;

    for (int kt = 0; kt < 256; kt += 16) {
#pragma unroll
        for (int i = 0; i < 2; i++) {
            int r = ar + i * 64;
            float4 v = *(const float4*)(P + (size_t)(row0 + r) * 256 + kt + ac);
            As[ac + 0][r] = v.x; As[ac + 1][r] = v.y;
            As[ac + 2][r] = v.z; As[ac + 3][r] = v.w;
        }
#pragma unroll
        for (int i = 0; i < 2; i++) {
            int r = wr + i * 8;
            *(float4*)&Ws[r][wc] =
                *(const float4*)(Q + (size_t)(kt + r) * 256 + col0 + wc);
        }
        __syncthreads();
#pragma unroll
        for (int kk = 0; kk < 16; kk++) {
            float4 a0 = *(const float4*)&As[kk][ty * 4];
            float4 a1 = *(const float4*)&As[kk][64 + ty * 4];
            float4 w0 = *(const float4*)&Ws[kk][tx * 4];
            float4 w1 = *(const float4*)&Ws[kk][64 + tx * 4];
            float af[8] = {a0.x, a0.y, a0.z, a0.w, a1.x, a1.y, a1.z, a1.w};
            float wf[8] = {w0.x, w0.y, w0.z, w0.w, w1.x, w1.y, w1.z, w1.w};
#pragma unroll
            for (int i = 0; i < 8; i++)
#pragma unroll
                for (int j = 0; j < 8; j++)
                    acc[i][j] = fmaf(af[i], wf[j], acc[i][j]);
        }
        __syncthreads();
    }
#pragma unroll
    for (int ih = 0; ih < 2; ih++)
#pragma unroll
        for (int i = 0; i < 4; i++) {
            int r = row0 + ih * 64 + ty * 4 + i;
#pragma unroll
            for (int jh = 0; jh < 2; jh++)
#pragma unroll
                for (int j = 0; j < 4; j++)
                    C[(size_t)r * 256 + col0 + jh * 64 + tx * 4 + j] =
                        acc[ih * 4 + i][jh * 4 + j];
        }
}

// combined bias vectors: g_vbias[c] = b_c @ Q_c (+ rb1 for c==21), grid (22)
__global__ void __launch_bounds__(256) vbias_kernel(
    const float* __restrict__ mw1, const float* __restrict__ uw1,
    const float* __restrict__ rw1, const float* __restrict__ mb2,
    const float* __restrict__ ub2, const float* __restrict__ rb1)
{
    int c = blockIdx.x;
    const float* b = (c < 6) ? mb2 + (size_t)c * 256
                   : (c < 21) ? ub2 + (size_t)((c - 6) / 3) * 256
                              : ub2 + (size_t)5 * 256;
    const float* Q = combo_Q(c, mw1, uw1, rw1);
    int n = threadIdx.x;
    float s = 0.f;
    for (int k = 0; k < 256; k++) s = fmaf(b[k], Q[(size_t)k * 256 + n], s);
    if (c == 21) s += rb1[n];
    g_vbias[(size_t)c * 256 + n] = s;
}

// ---------------------------------------------------------------------------
// Weight transpose to fp16: pool[z][n][k] = fp16(S_z[k][n])
//  z 0..1 : W1a_0, W1b_0 (mw1)    z 2 : U1a_0 (uw1)
//  z 3..24: g_wcomb combos 0..21  z 25: rw2 (N=128)
// ---------------------------------------------------------------------------
__global__ void wsplit_kernel(
    const float* __restrict__ mw1, const float* __restrict__ uw1,
    const float* __restrict__ rw2, __half* __restrict__ wt)
{
    int z = blockIdx.z;
    const float* W;
    int N = 256;
    if (z < 2)       W = mw1 + (size_t)z * 65536;
    else if (z == 2) W = uw1;
    else if (z < 25) W = g_wcomb + (size_t)(z - 3) * 65536;
    else { W = rw2; N = 128; }

    int k0 = blockIdx.x * 32, n0 = blockIdx.y * 32;
    if (n0 >= N) return;
    __shared__ float t[32][33];
    for (int i = threadIdx.y; i < 32; i += 8)
        t[i][threadIdx.x] = W[(size_t)(k0 + i) * N + n0 + threadIdx.x];
    __syncthreads();
    size_t base = (size_t)z * 65536;
    for (int i = threadIdx.y; i < 32; i += 8)
        wt[base + (size_t)(n0 + i) * 256 + k0 + threadIdx.x] =
            __float2half(t[threadIdx.x][i]);
}

// ---------------------------------------------------------------------------
// fp16 split-precision GEMM via mma.sync, templated M-tile:
//   C[M, N tile] = op(A[M,256] @ Wt_slot^T), 2-term: ah*w + al*w
// flags: 1=RELU 2=ADDC(Cprev) 4=BIAS 8=ROWB(rowscale*rbias) 16=HALF_OUT(bz0)
// ---------------------------------------------------------------------------
template <int MI>
__global__ void __launch_bounds__(256, (MI == 4) ? 2 : 1) tgemm(
    const float* __restrict__ A,
    const __half* __restrict__ wt,
    int s0, int s1, int s2,
    const float* __restrict__ b0p, const float* __restrict__ b1p,
    const float* __restrict__ b2p,
    const float* __restrict__ rbias, const float* __restrict__ rowscale,
    const float* __restrict__ Cprev,
    float* C0, float* C1, float* C2,
    int M, int ldc, int flags)
{
    constexpr int TM = MI * 32;
    constexpr int ABYTES = TM * 80;
    constexpr int WOFF = 2 * ABYTES;
    constexpr int BUFSZ = WOFF + 10240;

    extern __shared__ __align__(16) char smem[];

    int bz = blockIdx.z;
    int slot = (bz == 0) ? s0 : (bz == 1 ? s1 : s2);
    float* C = (bz == 0) ? C0 : (bz == 1 ? C1 : C2);
    const float* bias = (bz == 0) ? b0p : (bz == 1 ? b1p : b2p);
    const __half* Wp = wt + (size_t)slot * 65536;
    bool half_out = (flags & 16) && (bz == 0);

    uint32_t sb = smem_u32(smem);
    int tid = threadIdx.x;
    int lane = tid & 31, wid = tid >> 5;
    int wr = wid >> 2, wc = wid & 3;
    int row0 = blockIdx.y * TM, col0 = blockIdx.x * 128;

    float acc[MI][4][4];
#pragma unroll
    for (int i = 0; i < MI; i++)
#pragma unroll
        for (int j = 0; j < 4; j++)
#pragma unroll
            for (int k = 0; k < 4; k++) acc[i][j][k] = 0.f;

    int a_row = lane & 15;
    int a_kh = (lane >> 4) * 8;
    int bg = lane >> 3;
    int b_n = (lane & 7) + (bg >> 1) * 8;
    int b_kh = (bg & 1) * 8;

    int r0 = tid >> 3;
    int c4 = tid & 7;
    int lrow = tid >> 1;
    int lhalf = tid & 1;
    size_t wgoff = (size_t)(col0 + lrow) * 256 + lhalf * 16;
    uint32_t wsoff = (uint32_t)(lrow * 80 + lhalf * 32);

    float4 av[MI];

#define LOAD_A(ch)                                                          \
    do {                                                                    \
        _Pragma("unroll")                                                   \
        for (int q = 0; q < MI; q++) {                                      \
            int r_ = row0 + q * 32 + r0;                                    \
            av[q] = (r_ < M)                                                \
                ? *(const float4*)(A + (size_t)r_ * 256 + (ch) * 32 + c4 * 4) \
                : make_float4(0.f, 0.f, 0.f, 0.f);                          \
        }                                                                   \
    } while (0)

#define STORE_A(buf)                                                        \
    do {                                                                    \
        char* bp_ = smem + (buf) * BUFSZ + r0 * 80 + c4 * 8;                \
        _Pragma("unroll")                                                   \
        for (int q = 0; q < MI; q++) {                                      \
            float f_[4] = {av[q].x, av[q].y, av[q].z, av[q].w};             \
            union { __half b[4]; uint2 u; } ph_, pl_;                       \
            _Pragma("unroll")                                               \
            for (int j = 0; j < 4; j++) {                                   \
                __half h_ = __float2half(f_[j]);                            \
                ph_.b[j] = h_;                                              \
                pl_.b[j] = __float2half(f_[j] - __half2float(h_));          \
            }                                                               \
            *(uint2*)(bp_ + q * 2560) = ph_.u;                              \
            *(uint2*)(bp_ + ABYTES + q * 2560) = pl_.u;                     \
        }                                                                   \
    } while (0)

#define ISSUE_W(ch, buf)                                                    \
    do {                                                                    \
        uint32_t b_ = sb + (buf) * BUFSZ + WOFF + wsoff;                    \
        const __half* pw_ = Wp + wgoff + (ch) * 32;                         \
        cp16(b_, pw_);                                                      \
        cp16(b_ + 16, pw_ + 8);                                             \
    } while (0)

    ISSUE_W(0, 0);
    cp_commit();
    LOAD_A(0);
    STORE_A(0);
    cp_wait0();
    __syncthreads();

#pragma unroll 2
    for (int ch = 0; ch < 8; ch++) {
        int buf = ch & 1;
        if (ch < 7) {
            ISSUE_W(ch + 1, buf ^ 1);
            cp_commit();
            LOAD_A(ch + 1);
        }
        uint32_t base = sb + buf * BUFSZ;
#pragma unroll
        for (int ks = 0; ks < 2; ks++) {
            uint32_t Af[MI][4], Bf[2][4];
            uint32_t acol = (uint32_t)((ks * 16 + a_kh) * 2);
            uint32_t bcol = (uint32_t)((ks * 16 + b_kh) * 2);
#pragma unroll
            for (int nj = 0; nj < 2; nj++)
                ldm_x4(Bf[nj], base + WOFF +
                               (uint32_t)((wc * 32 + nj * 16 + b_n) * 80) + bcol);
#pragma unroll
            for (int mi = 0; mi < MI; mi++)
                ldm_x4(Af[mi], base + ABYTES +
                               (uint32_t)((wr * (MI * 16) + mi * 16 + a_row) * 80) + acol);
#pragma unroll
            for (int mi = 0; mi < MI; mi++)
#pragma unroll
                for (int ni = 0; ni < 4; ni++) {
                    int nj = ni >> 1, off = (ni & 1) * 2;
                    mma_f16(acc[mi][ni], Af[mi], Bf[nj][off], Bf[nj][off + 1]);
                }
#pragma unroll
            for (int mi = 0; mi < MI; mi++)
                ldm_x4(Af[mi], base +
                               (uint32_t)((wr * (MI * 16) + mi * 16 + a_row) * 80) + acol);
#pragma unroll
            for (int mi = 0; mi < MI; mi++)
#pragma unroll
                for (int ni = 0; ni < 4; ni++) {
                    int nj = ni >> 1, off = (ni & 1) * 2;
                    mma_f16(acc[mi][ni], Af[mi], Bf[nj][off], Bf[nj][off + 1]);
                }
        }
        if (ch < 7) {
            STORE_A(buf ^ 1);
            cp_wait0();
            __syncthreads();
        }
    }

    // ---- epilogue ----
#pragma unroll
    for (int mi = 0; mi < MI; mi++) {
        int m0 = row0 + wr * (MI * 16) + mi * 16 + (lane >> 2);
        int m1 = m0 + 8;
        float rs0 = 0.f, rs1 = 0.f;
        if (flags & 8) {
            if (m0 < M) rs0 = rowscale[m0];
            if (m1 < M) rs1 = rowscale[m1];
        }
#pragma unroll
        for (int ni = 0; ni < 4; ni++) {
            int nc = col0 + wc * 32 + ni * 8 + (lane & 3) * 2;
            float b0 = 0.f, b1 = 0.f, r0b = 0.f, r1b = 0.f;
            if (flags & 4) { b0 = bias[nc]; b1 = bias[nc + 1]; }
            if (flags & 8) { r0b = rbias[nc]; r1b = rbias[nc + 1]; }
            float* a = acc[mi][ni];
            if (m0 < M) {
                float v0 = a[0] + b0, v1 = a[1] + b1;
                if (flags & 8) { v0 = fmaf(rs0, r0b, v0); v1 = fmaf(rs0, r1b, v1); }
                if (flags & 2) {
                    v0 += Cprev[(size_t)m0 * 256 + nc];
                    v1 += Cprev[(size_t)m0 * 256 + nc + 1];
                }
                if (flags & 1) { v0 = fmaxf(v0, 0.f); v1 = fmaxf(v1, 0.f); }
                if (half_out)
                    *(__half2*)((__half*)C + (size_t)m0 * ldc + nc) =
                        __floats2half2_rn(v0, v1);
                else
                    *(float2*)(C + (size_t)m0 * ldc + nc) = make_float2(v0, v1);
            }
            if (m1 < M) {
                float v0 = a[2] + b0, v1 = a[3] + b1;
                if (flags & 8) { v0 = fmaf(rs1, r0b, v0); v1 = fmaf(rs1, r1b, v1); }
                if (flags & 2) {
                    v0 += Cprev[(size_t)m1 * 256 + nc];
                    v1 += Cprev[(size_t)m1 * 256 + nc + 1];
                }
                if (flags & 1) { v0 = fmaxf(v0, 0.f); v1 = fmaxf(v1, 0.f); }
                if (half_out)
                    *(__half2*)((__half*)C + (size_t)m1 * ldc + nc) =
                        __floats2half2_rn(v0, v1);
                else
                    *(float2*)(C + (size_t)m1 * ldc + nc) = make_float2(v0, v1);
            }
        }
    }
#undef LOAD_A
#undef STORE_A
#undef ISSUE_W
}

// ---------------------------------------------------------------------------
// Embed: x0 = atom @ embed_w + embed_b
// ---------------------------------------------------------------------------
#define EMB_NODES 16
__global__ void __launch_bounds__(256) embed_kernel(
    const float* __restrict__ atom, const float* __restrict__ w,
    const float* __restrict__ b)
{
    __shared__ float s_af[EMB_NODES][NATOM];
    int n0 = blockIdx.x * EMB_NODES;
    int tid = threadIdx.x;
    for (int i = tid; i < EMB_NODES * NATOM; i += 256) {
        int r = i / NATOM, c = i % NATOM;
        int n = n0 + r;
        s_af[r][c] = (n < N_NODES) ? atom[(size_t)n * NATOM + c] : 0.f;
    }
    __syncthreads();
    int j = tid;
    float acc[EMB_NODES];
    float bj = b[j];
#pragma unroll
    for (int r = 0; r < EMB_NODES; r++) acc[r] = bj;
    for (int k = 0; k < NATOM; k++) {
        float wv = w[k * HID + j];
#pragma unroll
        for (int r = 0; r < EMB_NODES; r++) acc[r] = fmaf(s_af[r][k], wv, acc[r]);
    }
#pragma unroll
    for (int r = 0; r < EMB_NODES; r++) {
        int n = n0 + r;
        if (n < N_NODES) g_x[(size_t)n * HID + j] = acc[r];
    }
}

// ---------------------------------------------------------------------------
// CSR build
// ---------------------------------------------------------------------------
__global__ void count_kernel(const int* __restrict__ dst)
{
    int e = blockIdx.x * blockDim.x + threadIdx.x;
    if (e < N_EDGES) atomicAdd(&g_deg[dst[e]], 1);
}

__global__ void __launch_bounds__(1024) scan_kernel()
{
    __shared__ int sdeg[10240];
    __shared__ int warpsum[32];
    int tid = threadIdx.x;
#pragma unroll
    for (int i = 0; i < 10; i++) {
        int idx = i * 1024 + tid;
        sdeg[idx] = (idx < N_NODES) ? g_deg[idx] : 0;
    }
    __syncthreads();
    int base = tid * 10;
    int v[10];
    int tot = 0;
#pragma unroll
    for (int i = 0; i < 10; i++) {
        v[i] = sdeg[base + i];
        tot += v[i];
    }
    int lane = tid & 31, wid = tid >> 5;
    int x = tot;
#pragma unroll
    for (int off = 1; off < 32; off <<= 1) {
        int y = __shfl_up_sync(~0u, x, off);
        if (lane >= off) x += y;
    }
    if (lane == 31) warpsum[wid] = x;
    __syncthreads();
    if (wid == 0) {
        int w = warpsum[lane];
#pragma unroll
        for (int off = 1; off < 32; off <<= 1) {
            int y = __shfl_up_sync(~0u, w, off);
            if (lane >= off) w += y;
        }
        warpsum[lane] = w;
    }
    __syncthreads();
    int run = x - tot + (wid ? warpsum[wid - 1] : 0);
    if (tid == 0) g_rowptr[0] = 0;
#pragma unroll
    for (int i = 0; i < 10; i++) {
        int idx = base + i;
        if (idx < N_NODES) {
            g_cursor[idx] = run;
            run += v[i];
            g_rowptr[idx + 1] = run;
            g_degf[idx] = (float)v[i];
        }
    }
}

__global__ void fill_kernel(const int* __restrict__ src,
                            const int* __restrict__ dst,
                            const float* __restrict__ ef)
{
    int e = blockIdx.x * blockDim.x + threadIdx.x;
    if (e >= N_EDGES) return;
    int d = dst[e];
    int pos = atomicAdd(&g_cursor[d], 1);
    g_ssrc[pos] = src[e];
#pragma unroll
    for (int q = 0; q < NBOND; q++)
        g_sef[(size_t)pos * NBOND + q] = ef[(size_t)e * NBOND + q];
}

// ---------------------------------------------------------------------------
// Aggregate: ragg[n] = sum_{e in-edges} relu(xa16[src_e] + xb[n] + ef_e@W1c + b1)
// NPC nodes per CTA; w1c column in registers; xa gathered as fp16.
// ---------------------------------------------------------------------------
#define NPC 8
#define CHE 32
__global__ void __launch_bounds__(256) aggregate_kernel(
    const __half* __restrict__ xa16, const float* __restrict__ xb,
    const float* __restrict__ w1c, const float* __restrict__ b1,
    float* __restrict__ ragg)
{
    __shared__ int   s_src[CHE];
    __shared__ float s_ef[CHE][NBOND];

    int n0 = blockIdx.x * NPC;
    int c = threadIdx.x;

    float wreg[NBOND];
#pragma unroll
    for (int q = 0; q < NBOND; q++) wreg[q] = w1c[q * 256 + c];
    float b1c = b1[c];

    for (int ni = 0; ni < NPC; ni++) {
        int n = n0 + ni;
        if (n >= N_NODES) break;
        float base_v = b1c + xb[(size_t)n * HID + c];
        int beg = g_rowptr[n], end = g_rowptr[n + 1];
        float acc = 0.f;
        for (int b0 = beg; b0 < end; b0 += CHE) {
            int m = min(CHE, end - b0);
            __syncthreads();
            if (c < m) s_src[c] = g_ssrc[b0 + c];
            if (c < m * NBOND)
                s_ef[c / NBOND][c % NBOND] = g_sef[(size_t)b0 * NBOND + c];
            __syncthreads();
            for (int j = 0; j < m; j++) {
                float t = base_v +
                          __half2float(xa16[(size_t)s_src[j] * HID + c]);
#pragma unroll
                for (int q = 0; q < NBOND; q++)
                    t = fmaf(s_ef[j][q], wreg[q], t);
                acc += fmaxf(t, 0.f);
            }
        }
        ragg[(size_t)n * HID + c] = acc;
    }
}

// ---------------------------------------------------------------------------
// Readout final: out = mean_n( r2[n,:] . w3 + b3 )
// ---------------------------------------------------------------------------
__global__ void __launch_bounds__(256) readout_final(
    const float* __restrict__ r2, const float* __restrict__ w3,
    const float* __restrict__ b3, float* __restrict__ out)
{
    __shared__ float sred[256];
    int n = blockIdx.x * 256 + threadIdx.x;
    float v = 0.f;
    if (n < N_NODES) {
        const float* row = r2 + (size_t)n * 128;
        float s = 0.f;
#pragma unroll
        for (int k = 0; k < 128; k += 4) {
            float4 rv = *(const float4*)(row + k);
            float4 wv = *(const float4*)(w3 + k);
            s += rv.x * wv.x + rv.y * wv.y + rv.z * wv.z + rv.w * wv.w;
        }
        v = (s + b3[0]) * (1.0f / N_NODES);
    }
    sred[threadIdx.x] = v;
    __syncthreads();
    for (int st = 128; st > 0; st >>= 1) {
        if (threadIdx.x < st) sred[threadIdx.x] += sred[threadIdx.x + st];
        __syncthreads();
    }
    if (threadIdx.x == 0) atomicAdd(out, sred[0]);
}

// ---------------------------------------------------------------------------
// Launch
// ---------------------------------------------------------------------------
extern "C" void kernel_launch(void* const* d_in, const int* in_sizes, int n_in,
                              void* d_out, int out_size)
{
    const float* atom = (const float*)d_in[0];
    const int*   eidx = (const int*)d_in[1];
    const float* ef   = (const float*)d_in[2];
    const float* embw = (const float*)d_in[3];
    const float* embb = (const float*)d_in[4];
    const float* mw1  = (const float*)d_in[5];
    const float* mb1  = (const float*)d_in[6];
    const float* mw2  = (const float*)d_in[7];
    const float* mb2  = (const float*)d_in[8];
    const float* uw1  = (const float*)d_in[9];
    const float* ub1  = (const float*)d_in[10];
    const float* uw2  = (const float*)d_in[11];
    const float* ub2  = (const float*)d_in[12];
    const float* rw1  = (const float*)d_in[13];
    const float* rb1  = (const float*)d_in[14];
    const float* rw2  = (const float*)d_in[15];
    const float* rb2  = (const float*)d_in[16];
    const float* rw3  = (const float*)d_in[17];
    const float* rb3  = (const float*)d_in[18];

    const int* src = eidx;
    const int* dst = eidx + N_EDGES;

    float *px, *pxa, *pxb, *pagg, *pt1, *ph, *pdegf, *pvb;
    int* pdeg;
    __half* pwt;
    cudaGetSymbolAddress((void**)&px,    g_x);
    cudaGetSymbolAddress((void**)&pxa,   g_xa);
    cudaGetSymbolAddress((void**)&pxb,   g_xb);
    cudaGetSymbolAddress((void**)&pagg,  g_agg);
    cudaGetSymbolAddress((void**)&pt1,   g_t1);
    cudaGetSymbolAddress((void**)&ph,    g_h);
    cudaGetSymbolAddress((void**)&pdeg,  g_deg);
    cudaGetSymbolAddress((void**)&pdegf, g_degf);
    cudaGetSymbolAddress((void**)&pvb,   g_vbias);
    cudaGetSymbolAddress((void**)&pwt,   g_wt);

    const int SM4 = 2 * 30720;
    const int SM5 = 2 * 35840;
    cudaFuncSetAttribute(tgemm<4>, cudaFuncAttributeMaxDynamicSharedMemorySize,
                         SM4);
    cudaFuncSetAttribute(tgemm<5>, cudaFuncAttributeMaxDynamicSharedMemorySize,
                         SM5);

    // setup: combined weights, bias vectors, fp16 pool, embed, CSR
    combine_kernel<<<dim3(2, 2, NCOMB), 256>>>(mw1, uw1, mw2, uw2, rw1);
    vbias_kernel<<<NCOMB, 256>>>(mw1, uw1, rw1, mb2, ub2, rb1);
    wsplit_kernel<<<dim3(8, 8, NSLOTS), dim3(32, 8)>>>(mw1, uw1, rw2, pwt);
    embed_kernel<<<(N_NODES + EMB_NODES - 1) / EMB_NODES, 256>>>(atom, embw, embb);
    cudaMemsetAsync(pdeg, 0, sizeof(int) * N_NODES);
    count_kernel<<<(N_EDGES + 255) / 256, 256>>>(dst);
    scan_kernel<<<1, 1024>>>();
    fill_kernel<<<(N_EDGES + 255) / 256, 256>>>(src, dst, ef);

    const int MT5 = (N_NODES + 159) / 160;     // 63
    dim3 gG3(2, (N_NODES + 127) / 128, 3);     // tgemm<4>, 474 CTAs
    dim3 gS(2, MT5, 1);                        // tgemm<5>, 126 CTAs
    const int AGG_BLK = (N_NODES + NPC - 1) / NPC;  // 1250

    // layer 0 inputs: xa(fp16),xb,t1 from x0
    tgemm<4><<<gG3, 256, SM4>>>(px, pwt, 0, 1, 2,
                                nullptr, nullptr, nullptr,
                                nullptr, nullptr, nullptr,
                                pxa, pxb, pt1, N_NODES, 256, 16);

    for (int l = 0; l < NLAYERS; l++) {
        const float* W1c = mw1 + (size_t)l * 518 * HID + 512 * HID;

        // ragg[n] = sum relu(xa16[src]+xb[n]+ef@W1c+b1)
        aggregate_kernel<<<AGG_BLK, 256>>>((const __half*)pxa, pxb, W1c,
                                           mb1 + (size_t)l * HID, pagg);

        // h = relu(ragg@(W2@U1b) + deg*(b2@U1b) + ub1 + t1)
        tgemm<5><<<gS, 256, SM5>>>(pagg, pwt, 3 + l, 0, 0,
                                   ub1 + (size_t)l * HID, nullptr, nullptr,
                                   pvb + (size_t)l * 256, pdegf, pt1,
                                   ph, nullptr, nullptr, N_NODES, 256,
                                   1 | 2 | 4 | 8);

        if (l < NLAYERS - 1) {
            // next xa(fp16),xb,t1 directly from h with combined weights
            int cb = 6 + 3 * l;
            tgemm<4><<<gG3, 256, SM4>>>(ph, pwt, 9 + 3 * l, 10 + 3 * l,
                                        11 + 3 * l,
                                        pvb + (size_t)cb * 256,
                                        pvb + (size_t)(cb + 1) * 256,
                                        pvb + (size_t)(cb + 2) * 256,
                                        nullptr, nullptr, nullptr,
                                        pxa, pxb, pt1, N_NODES, 256, 4 | 16);
        }
    }

    // readout r1 = relu(h@(U2_5@rw1) + (ub2_5@rw1 + rb1))
    tgemm<5><<<gS, 256, SM5>>>(ph, pwt, 24, 0, 0,
                               pvb + (size_t)21 * 256, nullptr, nullptr,
                               nullptr, nullptr, nullptr,
                               pt1, nullptr, nullptr, N_NODES, 256, 1 | 4);
    // r2 = relu(r1@rw2 + rb2)
    dim3 gR(1, MT5, 1);
    tgemm<5><<<gR, 256, SM5>>>(pt1, pwt, 25, 0, 0,
                               rb2, nullptr, nullptr,
                               nullptr, nullptr, nullptr,
                               pagg, nullptr, nullptr, N_NODES, 128, 1 | 4);

    cudaMemsetAsync(d_out, 0, sizeof(float));
    readout_final<<<(N_NODES + 255) / 256, 256>>>(pagg, rw3, rb3, (float*)d_out);
}

// round 12
// speedup vs baseline: 7.8244x; 1.2264x over previous
#include <cuda_runtime.h>
#include <cuda_fp16.h>
#include <cstdint>

#define N_NODES 10000
#define N_EDGES 160000
#define HID 256
#define NBOND 6
#define NATOM 62
#define NLAYERS 6
#define NSLOTS 26
#define NCOMB 22

// ---------------- scratch (device globals; no allocation allowed) ----------
// fp32-sized buffers; several are reinterpreted as __half (half the bytes).
__device__ float g_x[N_NODES * HID];    // x0 as __half
__device__ float g_xa[N_NODES * HID];   // xa as __half
__device__ float g_xb[N_NODES * HID];   // xb fp32 (also final r2 fp32)
__device__ float g_agg[N_NODES * HID];  // ragg as __half
__device__ float g_t1[N_NODES * HID];   // t1 fp32 / r1 as __half
__device__ float g_h[N_NODES * HID];    // h as __half

__device__ int   g_deg[N_NODES];
__device__ int   g_rowptr[N_NODES + 1];
__device__ int   g_cursor[N_NODES];
__device__ int   g_ssrc[N_EDGES];
__device__ float g_sef[N_EDGES * NBOND];
__device__ float g_degf[N_NODES];

// combined fp32 weight scratch (22 x 256x256) + combined bias vectors
__device__ float g_wcomb[NCOMB * 65536];
__device__ float g_vbias[NCOMB * 256];

// transposed fp16 weight pool: [slot][n][k], slot stride 256*256
__device__ __half g_wt[NSLOTS * 256 * 256];

// ---------------- helpers ---------------------------------------------------
__device__ __forceinline__ uint32_t smem_u32(const void* p) {
    uint32_t a;
    asm("{ .reg .u64 t; cvta.to.shared.u64 t, %1; cvt.u32.u64 %0, t; }"
        : "=r"(a) : "l"(p));
    return a;
}
__device__ __forceinline__ void ldm_x4(uint32_t* r, uint32_t addr) {
    asm volatile("ldmatrix.sync.aligned.m8n8.x4.shared.b16 {%0,%1,%2,%3}, [%4];"
                 : "=r"(r[0]), "=r"(r[1]), "=r"(r[2]), "=r"(r[3]) : "r"(addr));
}
__device__ __forceinline__ void mma_f16(float* c, const uint32_t* a,
                                        uint32_t b0, uint32_t b1) {
    asm volatile(
        "mma.sync.aligned.m16n8k16.row.col.f32.f16.f16.f32 "
        "{%0,%1,%2,%3}, {%4,%5,%6,%7}, {%8,%9}, {%0,%1,%2,%3};"
        : "+f"(c[0]), "+f"(c[1]), "+f"(c[2]), "+f"(c[3])
        : "r"(a[0]), "r"(a[1]), "r"(a[2]), "r"(a[3]), "r"(b0), "r"(b1));
}
__device__ __forceinline__ void cp16(uint32_t dst, const void* src) {
    asm volatile("cp.async.cg.shared.global [%0], [%1], 16;"
                 :: "r"(dst), "l"(src));
}
__device__ __forceinline__ void cp_commit() {
    asm volatile("cp.async.commit_group;" ::: "memory");
}
__device__ __forceinline__ void cp_wait0() {
    asm volatile("cp.async.wait_group 0;" ::: "memory");
}

// ---------------------------------------------------------------------------
// Combo source pointers:
//  c in [0,6):   P = W2_l (mw2),  Q = U1b_l          (WU_l = W2@U1b)
//  c in [6,21):  P = U2_m (uw2),  Q in {W1a,W1b,U1a} of layer m+1
//  c == 21:      P = U2_5,        Q = rw1
// ---------------------------------------------------------------------------
__device__ __forceinline__ const float* combo_Q(
    int c, const float* mw1, const float* uw1, const float* rw1)
{
    if (c < 6) return uw1 + (size_t)c * 131072 + 65536;
    if (c < 21) {
        int m = (c - 6) / 3, t = (c - 6) % 3;
        int l = m + 1;
        if (t == 0) return mw1 + (size_t)l * 518 * 256;
        if (t == 1) return mw1 + (size_t)l * 518 * 256 + 65536;
        return uw1 + (size_t)l * 131072;
    }
    return rw1;
}

// fp32 setup GEMM: g_wcomb[c] = P_c @ Q_c   (256x256x256), grid (2,2,22)
__global__ void __launch_bounds__(256) combine_kernel(
    const float* __restrict__ mw1, const float* __restrict__ uw1,
    const float* __restrict__ mw2, const float* __restrict__ uw2,
    const float* __restrict__ rw1)
{
    int c = blockIdx.z;
    const float* P = (c < 6) ? mw2 + (size_t)c * 65536
                   : (c < 21) ? uw2 + (size_t)((c - 6) / 3) * 65536
                              : uw2 + (size_t)5 * 65536;
    const float* Q = combo_Q(c, mw1, uw1, rw1);
    float* C = g_wcomb + (size_t)c * 65536;

    __shared__ float As[16][128];
    __shared__ float Ws[16][128];
    int col0 = blockIdx.x * 128, row0 = blockIdx.y * 128;
    int tid = threadIdx.x;
    int tx = tid & 15, ty = tid >> 4;

    float acc[8][8];
#pragma unroll
    for (int i = 0; i < 8; i++)
#pragma unroll
        for (int j = 0; j < 8; j++) acc[i][j] = 0.f;

    int ar = tid >> 2, ac = (tid & 3) << 2;
    int wr = tid >> 5, wc = (tid & 31) << 2;

    for (int kt = 0; kt < 256; kt += 16) {
#pragma unroll
        for (int i = 0; i < 2; i++) {
            int r = ar + i * 64;
            float4 v = *(const float4*)(P + (size_t)(row0 + r) * 256 + kt + ac);
            As[ac + 0][r] = v.x; As[ac + 1][r] = v.y;
            As[ac + 2][r] = v.z; As[ac + 3][r] = v.w;
        }
#pragma unroll
        for (int i = 0; i < 2; i++) {
            int r = wr + i * 8;
            *(float4*)&Ws[r][wc] =
                *(const float4*)(Q + (size_t)(kt + r) * 256 + col0 + wc);
        }
        __syncthreads();
#pragma unroll
        for (int kk = 0; kk < 16; kk++) {
            float4 a0 = *(const float4*)&As[kk][ty * 4];
            float4 a1 = *(const float4*)&As[kk][64 + ty * 4];
            float4 w0 = *(const float4*)&Ws[kk][tx * 4];
            float4 w1 = *(const float4*)&Ws[kk][64 + tx * 4];
            float af[8] = {a0.x, a0.y, a0.z, a0.w, a1.x, a1.y, a1.z, a1.w};
            float wf[8] = {w0.x, w0.y, w0.z, w0.w, w1.x, w1.y, w1.z, w1.w};
#pragma unroll
            for (int i = 0; i < 8; i++)
#pragma unroll
                for (int j = 0; j < 8; j++)
                    acc[i][j] = fmaf(af[i], wf[j], acc[i][j]);
        }
        __syncthreads();
    }
#pragma unroll
    for (int ih = 0; ih < 2; ih++)
#pragma unroll
        for (int i = 0; i < 4; i++) {
            int r = row0 + ih * 64 + ty * 4 + i;
#pragma unroll
            for (int jh = 0; jh < 2; jh++)
#pragma unroll
                for (int j = 0; j < 4; j++)
                    C[(size_t)r * 256 + col0 + jh * 64 + tx * 4 + j] =
                        acc[ih * 4 + i][jh * 4 + j];
        }
}

// combined bias vectors: g_vbias[c] = b_c @ Q_c (+ rb1 for c==21), grid (22)
__global__ void __launch_bounds__(256) vbias_kernel(
    const float* __restrict__ mw1, const float* __restrict__ uw1,
    const float* __restrict__ rw1, const float* __restrict__ mb2,
    const float* __restrict__ ub2, const float* __restrict__ rb1)
{
    int c = blockIdx.x;
    const float* b = (c < 6) ? mb2 + (size_t)c * 256
                   : (c < 21) ? ub2 + (size_t)((c - 6) / 3) * 256
                              : ub2 + (size_t)5 * 256;
    const float* Q = combo_Q(c, mw1, uw1, rw1);
    int n = threadIdx.x;
    float s = 0.f;
    for (int k = 0; k < 256; k++) s = fmaf(b[k], Q[(size_t)k * 256 + n], s);
    if (c == 21) s += rb1[n];
    g_vbias[(size_t)c * 256 + n] = s;
}

// ---------------------------------------------------------------------------
// Weight transpose to fp16: pool[z][n][k] = fp16(S_z[k][n])
//  z 0..1 : W1a_0, W1b_0 (mw1)    z 2 : U1a_0 (uw1)
//  z 3..24: g_wcomb combos 0..21  z 25: rw2 (N=128)
// ---------------------------------------------------------------------------
__global__ void wsplit_kernel(
    const float* __restrict__ mw1, const float* __restrict__ uw1,
    const float* __restrict__ rw2, __half* __restrict__ wt)
{
    int z = blockIdx.z;
    const float* W;
    int N = 256;
    if (z < 2)       W = mw1 + (size_t)z * 65536;
    else if (z == 2) W = uw1;
    else if (z < 25) W = g_wcomb + (size_t)(z - 3) * 65536;
    else { W = rw2; N = 128; }

    int k0 = blockIdx.x * 32, n0 = blockIdx.y * 32;
    if (n0 >= N) return;
    __shared__ float t[32][33];
    for (int i = threadIdx.y; i < 32; i += 8)
        t[i][threadIdx.x] = W[(size_t)(k0 + i) * N + n0 + threadIdx.x];
    __syncthreads();
    size_t base = (size_t)z * 65536;
    for (int i = threadIdx.y; i < 32; i += 8)
        wt[base + (size_t)(n0 + i) * 256 + k0 + threadIdx.x] =
            __float2half(t[threadIdx.x][i]);
}

// ---------------------------------------------------------------------------
// fp16 GEMM via mma.sync, 1-term (A already fp16), double-buffered cp.async:
//   C[M, N tile] = op(A16[M,256] @ Wt_slot^T)
// Tile (MI*32) x 128, 8 warps (2 x 4). MI=4: 2 CTAs/SM; MI=5: 1 CTA/SM.
// flags: 1=RELU 2=ADDC(Cprev fp32) 4=BIAS 8=ROWB(rowscale*rbias)
//        16=HALF_OUT on bz==0
// OOB A rows (row>=M) read garbage inside the scratch buffer — harmless:
// they only feed accumulators whose stores are masked by m<M.
// smem/buffer: A [TM*80 B] then W [10240 B]; row stride 80 B.
// ---------------------------------------------------------------------------
template <int MI>
__global__ void __launch_bounds__(256, (MI == 4) ? 2 : 1) tgemm(
    const __half* __restrict__ A,
    const __half* __restrict__ wt,
    int s0, int s1, int s2,
    const float* __restrict__ b0p, const float* __restrict__ b1p,
    const float* __restrict__ b2p,
    const float* __restrict__ rbias, const float* __restrict__ rowscale,
    const float* __restrict__ Cprev,
    float* C0, float* C1, float* C2,
    int M, int ldc, int flags)
{
    constexpr int TM = MI * 32;
    constexpr int WBASE = TM * 80;
    constexpr int BUFSZ = WBASE + 10240;

    extern __shared__ __align__(16) char smem[];

    int bz = blockIdx.z;
    int slot = (bz == 0) ? s0 : (bz == 1 ? s1 : s2);
    float* C = (bz == 0) ? C0 : (bz == 1 ? C1 : C2);
    const float* bias = (bz == 0) ? b0p : (bz == 1 ? b1p : b2p);
    const __half* Wp = wt + (size_t)slot * 65536;
    bool half_out = (flags & 16) && (bz == 0);

    uint32_t sb = smem_u32(smem);
    int tid = threadIdx.x;
    int lane = tid & 31, wid = tid >> 5;
    int wr = wid >> 2, wc = wid & 3;
    int row0 = blockIdx.y * TM, col0 = blockIdx.x * 128;

    float acc[MI][4][4];
#pragma unroll
    for (int i = 0; i < MI; i++)
#pragma unroll
        for (int j = 0; j < 4; j++)
#pragma unroll
            for (int k = 0; k < 4; k++) acc[i][j][k] = 0.f;

    int a_row = lane & 15;
    int a_kh = (lane >> 4) * 8;
    int bg = lane >> 3;
    int b_n = (lane & 7) + (bg >> 1) * 8;
    int b_kh = (bg & 1) * 8;

    // W load mapping: 2 threads/row
    int lrow = tid >> 1;
    int lhalf = tid & 1;
    size_t wgoff = (size_t)(col0 + lrow) * 256 + lhalf * 16;
    uint32_t wsoff = (uint32_t)(lrow * 80 + lhalf * 32);

#define ISSUE_AW(ch, buf)                                                   \
    do {                                                                    \
        uint32_t bb_ = sb + (buf) * BUFSZ;                                  \
        for (int idx = tid; idx < TM * 4; idx += 256) {                     \
            int r_ = idx >> 2, seg_ = idx & 3;                              \
            cp16(bb_ + (uint32_t)(r_ * 80 + seg_ * 16),                     \
                 A + (size_t)(row0 + r_) * 256 + (ch) * 32 + seg_ * 8);     \
        }                                                                   \
        const __half* pw_ = Wp + wgoff + (ch) * 32;                         \
        cp16(bb_ + WBASE + wsoff, pw_);                                     \
        cp16(bb_ + WBASE + wsoff + 16, pw_ + 8);                            \
    } while (0)

    ISSUE_AW(0, 0);
    cp_commit();
    cp_wait0();
    __syncthreads();

#pragma unroll 2
    for (int ch = 0; ch < 8; ch++) {
        int buf = ch & 1;
        if (ch < 7) {
            ISSUE_AW(ch + 1, buf ^ 1);
            cp_commit();
        }
        uint32_t base = sb + buf * BUFSZ;
#pragma unroll
        for (int ks = 0; ks < 2; ks++) {
            uint32_t Af[MI][4], Bf[2][4];
            uint32_t acol = (uint32_t)((ks * 16 + a_kh) * 2);
            uint32_t bcol = (uint32_t)((ks * 16 + b_kh) * 2);
#pragma unroll
            for (int nj = 0; nj < 2; nj++)
                ldm_x4(Bf[nj], base + WBASE +
                               (uint32_t)((wc * 32 + nj * 16 + b_n) * 80) + bcol);
#pragma unroll
            for (int mi = 0; mi < MI; mi++)
                ldm_x4(Af[mi], base +
                               (uint32_t)((wr * (MI * 16) + mi * 16 + a_row) * 80) + acol);
#pragma unroll
            for (int mi = 0; mi < MI; mi++)
#pragma unroll
                for (int ni = 0; ni < 4; ni++) {
                    int nj = ni >> 1, off = (ni & 1) * 2;
                    mma_f16(acc[mi][ni], Af[mi], Bf[nj][off], Bf[nj][off + 1]);
                }
        }
        if (ch < 7) {
            cp_wait0();
            __syncthreads();
        }
    }

    // ---- epilogue ----
#pragma unroll
    for (int mi = 0; mi < MI; mi++) {
        int m0 = row0 + wr * (MI * 16) + mi * 16 + (lane >> 2);
        int m1 = m0 + 8;
        float rs0 = 0.f, rs1 = 0.f;
        if (flags & 8) {
            if (m0 < M) rs0 = rowscale[m0];
            if (m1 < M) rs1 = rowscale[m1];
        }
#pragma unroll
        for (int ni = 0; ni < 4; ni++) {
            int nc = col0 + wc * 32 + ni * 8 + (lane & 3) * 2;
            float b0 = 0.f, b1 = 0.f, r0b = 0.f, r1b = 0.f;
            if (flags & 4) { b0 = bias[nc]; b1 = bias[nc + 1]; }
            if (flags & 8) { r0b = rbias[nc]; r1b = rbias[nc + 1]; }
            float* a = acc[mi][ni];
            if (m0 < M) {
                float v0 = a[0] + b0, v1 = a[1] + b1;
                if (flags & 8) { v0 = fmaf(rs0, r0b, v0); v1 = fmaf(rs0, r1b, v1); }
                if (flags & 2) {
                    v0 += Cprev[(size_t)m0 * 256 + nc];
                    v1 += Cprev[(size_t)m0 * 256 + nc + 1];
                }
                if (flags & 1) { v0 = fmaxf(v0, 0.f); v1 = fmaxf(v1, 0.f); }
                if (half_out)
                    *(__half2*)((__half*)C + (size_t)m0 * ldc + nc) =
                        __floats2half2_rn(v0, v1);
                else
                    *(float2*)(C + (size_t)m0 * ldc + nc) = make_float2(v0, v1);
            }
            if (m1 < M) {
                float v0 = a[2] + b0, v1 = a[3] + b1;
                if (flags & 8) { v0 = fmaf(rs1, r0b, v0); v1 = fmaf(rs1, r1b, v1); }
                if (flags & 2) {
                    v0 += Cprev[(size_t)m1 * 256 + nc];
                    v1 += Cprev[(size_t)m1 * 256 + nc + 1];
                }
                if (flags & 1) { v0 = fmaxf(v0, 0.f); v1 = fmaxf(v1, 0.f); }
                if (half_out)
                    *(__half2*)((__half*)C + (size_t)m1 * ldc + nc) =
                        __floats2half2_rn(v0, v1);
                else
                    *(float2*)(C + (size_t)m1 * ldc + nc) = make_float2(v0, v1);
            }
        }
    }
#undef ISSUE_AW
}

// ---------------------------------------------------------------------------
// Embed: x0 = fp16(atom @ embed_w + embed_b)
// ---------------------------------------------------------------------------
#define EMB_NODES 16
__global__ void __launch_bounds__(256) embed_kernel(
    const float* __restrict__ atom, const float* __restrict__ w,
    const float* __restrict__ b, __half* __restrict__ x16)
{
    __shared__ float s_af[EMB_NODES][NATOM];
    int n0 = blockIdx.x * EMB_NODES;
    int tid = threadIdx.x;
    for (int i = tid; i < EMB_NODES * NATOM; i += 256) {
        int r = i / NATOM, c = i % NATOM;
        int n = n0 + r;
        s_af[r][c] = (n < N_NODES) ? atom[(size_t)n * NATOM + c] : 0.f;
    }
    __syncthreads();
    int j = tid;
    float acc[EMB_NODES];
    float bj = b[j];
#pragma unroll
    for (int r = 0; r < EMB_NODES; r++) acc[r] = bj;
    for (int k = 0; k < NATOM; k++) {
        float wv = w[k * HID + j];
#pragma unroll
        for (int r = 0; r < EMB_NODES; r++) acc[r] = fmaf(s_af[r][k], wv, acc[r]);
    }
#pragma unroll
    for (int r = 0; r < EMB_NODES; r++) {
        int n = n0 + r;
        if (n < N_NODES) x16[(size_t)n * HID + j] = __float2half(acc[r]);
    }
}

// ---------------------------------------------------------------------------
// CSR build
// ---------------------------------------------------------------------------
__global__ void count_kernel(const int* __restrict__ dst)
{
    int e = blockIdx.x * blockDim.x + threadIdx.x;
    if (e < N_EDGES) atomicAdd(&g_deg[dst[e]], 1);
}

__global__ void __launch_bounds__(1024) scan_kernel()
{
    __shared__ int sdeg[10240];
    __shared__ int warpsum[32];
    int tid = threadIdx.x;
#pragma unroll
    for (int i = 0; i < 10; i++) {
        int idx = i * 1024 + tid;
        sdeg[idx] = (idx < N_NODES) ? g_deg[idx] : 0;
    }
    __syncthreads();
    int base = tid * 10;
    int v[10];
    int tot = 0;
#pragma unroll
    for (int i = 0; i < 10; i++) {
        v[i] = sdeg[base + i];
        tot += v[i];
    }
    int lane = tid & 31, wid = tid >> 5;
    int x = tot;
#pragma unroll
    for (int off = 1; off < 32; off <<= 1) {
        int y = __shfl_up_sync(~0u, x, off);
        if (lane >= off) x += y;
    }
    if (lane == 31) warpsum[wid] = x;
    __syncthreads();
    if (wid == 0) {
        int w = warpsum[lane];
#pragma unroll
        for (int off = 1; off < 32; off <<= 1) {
            int y = __shfl_up_sync(~0u, w, off);
            if (lane >= off) w += y;
        }
        warpsum[lane] = w;
    }
    __syncthreads();
    int run = x - tot + (wid ? warpsum[wid - 1] : 0);
    if (tid == 0) g_rowptr[0] = 0;
#pragma unroll
    for (int i = 0; i < 10; i++) {
        int idx = base + i;
        if (idx < N_NODES) {
            g_cursor[idx] = run;
            run += v[i];
            g_rowptr[idx + 1] = run;
            g_degf[idx] = (float)v[i];
        }
    }
}

__global__ void fill_kernel(const int* __restrict__ src,
                            const int* __restrict__ dst,
                            const float* __restrict__ ef)
{
    int e = blockIdx.x * blockDim.x + threadIdx.x;
    if (e >= N_EDGES) return;
    int d = dst[e];
    int pos = atomicAdd(&g_cursor[d], 1);
    g_ssrc[pos] = src[e];
#pragma unroll
    for (int q = 0; q < NBOND; q++)
        g_sef[(size_t)pos * NBOND + q] = ef[(size_t)e * NBOND + q];
}

// ---------------------------------------------------------------------------
// Aggregate: ragg16[n] = fp16( sum_in-edges relu(xa16[src]+xb[n]+ef@W1c+b1) )
// ---------------------------------------------------------------------------
#define NPC 8
#define CHE 32
__global__ void __launch_bounds__(256) aggregate_kernel(
    const __half* __restrict__ xa16, const float* __restrict__ xb,
    const float* __restrict__ w1c, const float* __restrict__ b1,
    __half* __restrict__ ragg16)
{
    __shared__ int   s_src[CHE];
    __shared__ float s_ef[CHE][NBOND];

    int n0 = blockIdx.x * NPC;
    int c = threadIdx.x;

    float wreg[NBOND];
#pragma unroll
    for (int q = 0; q < NBOND; q++) wreg[q] = w1c[q * 256 + c];
    float b1c = b1[c];

    for (int ni = 0; ni < NPC; ni++) {
        int n = n0 + ni;
        if (n >= N_NODES) break;
        float base_v = b1c + xb[(size_t)n * HID + c];
        int beg = g_rowptr[n], end = g_rowptr[n + 1];
        float acc = 0.f;
        for (int b0 = beg; b0 < end; b0 += CHE) {
            int m = min(CHE, end - b0);
            __syncthreads();
            if (c < m) s_src[c] = g_ssrc[b0 + c];
            if (c < m * NBOND)
                s_ef[c / NBOND][c % NBOND] = g_sef[(size_t)b0 * NBOND + c];
            __syncthreads();
            for (int j = 0; j < m; j++) {
                float t = base_v +
                          __half2float(xa16[(size_t)s_src[j] * HID + c]);
#pragma unroll
                for (int q = 0; q < NBOND; q++)
                    t = fmaf(s_ef[j][q], wreg[q], t);
                acc += fmaxf(t, 0.f);
            }
        }
        ragg16[(size_t)n * HID + c] = __float2half(acc);
    }
}

// ---------------------------------------------------------------------------
// Readout final: out = mean_n( r2[n,:] . w3 + b3 )
// ---------------------------------------------------------------------------
__global__ void __launch_bounds__(256) readout_final(
    const float* __restrict__ r2, const float* __restrict__ w3,
    const float* __restrict__ b3, float* __restrict__ out)
{
    __shared__ float sred[256];
    int n = blockIdx.x * 256 + threadIdx.x;
    float v = 0.f;
    if (n < N_NODES) {
        const float* row = r2 + (size_t)n * 128;
        float s = 0.f;
#pragma unroll
        for (int k = 0; k < 128; k += 4) {
            float4 rv = *(const float4*)(row + k);
            float4 wv = *(const float4*)(w3 + k);
            s += rv.x * wv.x + rv.y * wv.y + rv.z * wv.z + rv.w * wv.w;
        }
        v = (s + b3[0]) * (1.0f / N_NODES);
    }
    sred[threadIdx.x] = v;
    __syncthreads();
    for (int st = 128; st > 0; st >>= 1) {
        if (threadIdx.x < st) sred[threadIdx.x] += sred[threadIdx.x + st];
        __syncthreads();
    }
    if (threadIdx.x == 0) atomicAdd(out, sred[0]);
}

// ---------------------------------------------------------------------------
// Launch
// ---------------------------------------------------------------------------
extern "C" void kernel_launch(void* const* d_in, const int* in_sizes, int n_in,
                              void* d_out, int out_size)
{
    const float* atom = (const float*)d_in[0];
    const int*   eidx = (const int*)d_in[1];
    const float* ef   = (const float*)d_in[2];
    const float* embw = (const float*)d_in[3];
    const float* embb = (const float*)d_in[4];
    const float* mw1  = (const float*)d_in[5];
    const float* mb1  = (const float*)d_in[6];
    const float* mw2  = (const float*)d_in[7];
    const float* mb2  = (const float*)d_in[8];
    const float* uw1  = (const float*)d_in[9];
    const float* ub1  = (const float*)d_in[10];
    const float* uw2  = (const float*)d_in[11];
    const float* ub2  = (const float*)d_in[12];
    const float* rw1  = (const float*)d_in[13];
    const float* rb1  = (const float*)d_in[14];
    const float* rw2  = (const float*)d_in[15];
    const float* rb2  = (const float*)d_in[16];
    const float* rw3  = (const float*)d_in[17];
    const float* rb3  = (const float*)d_in[18];

    const int* src = eidx;
    const int* dst = eidx + N_EDGES;

    float *px, *pxa, *pxb, *pagg, *pt1, *ph, *pdegf, *pvb;
    int* pdeg;
    __half* pwt;
    cudaGetSymbolAddress((void**)&px,    g_x);
    cudaGetSymbolAddress((void**)&pxa,   g_xa);
    cudaGetSymbolAddress((void**)&pxb,   g_xb);
    cudaGetSymbolAddress((void**)&pagg,  g_agg);
    cudaGetSymbolAddress((void**)&pt1,   g_t1);
    cudaGetSymbolAddress((void**)&ph,    g_h);
    cudaGetSymbolAddress((void**)&pdeg,  g_deg);
    cudaGetSymbolAddress((void**)&pdegf, g_degf);
    cudaGetSymbolAddress((void**)&pvb,   g_vbias);
    cudaGetSymbolAddress((void**)&pwt,   g_wt);

    const int SM4 = 2 * (4 * 32 * 80 + 10240);   // 40960
    const int SM5 = 2 * (5 * 32 * 80 + 10240);   // 46080
    static bool attr_done = false;
    if (!attr_done) {
        cudaFuncSetAttribute(tgemm<4>,
                             cudaFuncAttributeMaxDynamicSharedMemorySize, SM4);
        cudaFuncSetAttribute(tgemm<5>,
                             cudaFuncAttributeMaxDynamicSharedMemorySize, SM5);
        attr_done = true;
    }

    // streams/events for forked setup (created once, outside capture)
    static bool inited = false;
    static cudaStream_t sA, sB;
    static cudaEvent_t evRoot, evA, evB;
    if (!inited) {
        cudaStreamCreateWithFlags(&sA, cudaStreamNonBlocking);
        cudaStreamCreateWithFlags(&sB, cudaStreamNonBlocking);
        cudaEventCreateWithFlags(&evRoot, cudaEventDisableTiming);
        cudaEventCreateWithFlags(&evA, cudaEventDisableTiming);
        cudaEventCreateWithFlags(&evB, cudaEventDisableTiming);
        inited = true;
    }

    // fork
    cudaEventRecord(evRoot, 0);
    cudaStreamWaitEvent(sA, evRoot, 0);
    cudaStreamWaitEvent(sB, evRoot, 0);

    // stream A: weight pipeline (combine -> wsplit), vbias
    combine_kernel<<<dim3(2, 2, NCOMB), 256, 0, sA>>>(mw1, uw1, mw2, uw2, rw1);
    vbias_kernel<<<NCOMB, 256, 0, sA>>>(mw1, uw1, rw1, mb2, ub2, rb1);
    wsplit_kernel<<<dim3(8, 8, NSLOTS), dim3(32, 8), 0, sA>>>(mw1, uw1, rw2, pwt);
    cudaEventRecord(evA, sA);

    // stream B: CSR pipeline
    cudaMemsetAsync(pdeg, 0, sizeof(int) * N_NODES, sB);
    count_kernel<<<(N_EDGES + 255) / 256, 256, 0, sB>>>(dst);
    scan_kernel<<<1, 1024, 0, sB>>>();
    fill_kernel<<<(N_EDGES + 255) / 256, 256, 0, sB>>>(src, dst, ef);
    cudaEventRecord(evB, sB);

    // main stream: embed, then join weight pipeline before first GEMM
    embed_kernel<<<(N_NODES + EMB_NODES - 1) / EMB_NODES, 256>>>(
        atom, embw, embb, (__half*)px);
    cudaStreamWaitEvent(0, evA, 0);

    const int MT5 = (N_NODES + 159) / 160;     // 63
    dim3 gG3(2, (N_NODES + 127) / 128, 3);     // tgemm<4>, 474 CTAs
    dim3 gS(2, MT5, 1);                        // tgemm<5>, 126 CTAs
    const int AGG_BLK = (N_NODES + NPC - 1) / NPC;  // 1250

    // layer 0 inputs: xa(fp16),xb,t1 from x0(fp16)
    tgemm<4><<<gG3, 256, SM4>>>((const __half*)px, pwt, 0, 1, 2,
                                nullptr, nullptr, nullptr,
                                nullptr, nullptr, nullptr,
                                pxa, pxb, pt1, N_NODES, 256, 16);

    // join CSR pipeline before first aggregate
    cudaStreamWaitEvent(0, evB, 0);

    for (int l = 0; l < NLAYERS; l++) {
        const float* W1c = mw1 + (size_t)l * 518 * HID + 512 * HID;

        // ragg16[n] = fp16( sum relu(xa16[src]+xb[n]+ef@W1c+b1) )
        aggregate_kernel<<<AGG_BLK, 256>>>((const __half*)pxa, pxb, W1c,
                                           mb1 + (size_t)l * HID,
                                           (__half*)pagg);

        // h(fp16) = relu(ragg@(W2@U1b) + deg*(b2@U1b) + ub1 + t1)
        tgemm<5><<<gS, 256, SM5>>>((const __half*)pagg, pwt, 3 + l, 0, 0,
                                   ub1 + (size_t)l * HID, nullptr, nullptr,
                                   pvb + (size_t)l * 256, pdegf, pt1,
                                   ph, nullptr, nullptr, N_NODES, 256,
                                   1 | 2 | 4 | 8 | 16);

        if (l < NLAYERS - 1) {
            // next xa(fp16),xb,t1 directly from h(fp16) with combined weights
            int cb = 6 + 3 * l;
            tgemm<4><<<gG3, 256, SM4>>>((const __half*)ph, pwt,
                                        9 + 3 * l, 10 + 3 * l, 11 + 3 * l,
                                        pvb + (size_t)cb * 256,
                                        pvb + (size_t)(cb + 1) * 256,
                                        pvb + (size_t)(cb + 2) * 256,
                                        nullptr, nullptr, nullptr,
                                        pxa, pxb, pt1, N_NODES, 256, 4 | 16);
        }
    }

    // readout r1(fp16) = relu(h@(U2_5@rw1) + (ub2_5@rw1 + rb1))
    tgemm<5><<<gS, 256, SM5>>>((const __half*)ph, pwt, 24, 0, 0,
                               pvb + (size_t)21 * 256, nullptr, nullptr,
                               nullptr, nullptr, nullptr,
                               pt1, nullptr, nullptr, N_NODES, 256, 1 | 4 | 16);
    // r2(fp32) = relu(r1@rw2 + rb2)
    dim3 gR(1, MT5, 1);
    tgemm<5><<<gR, 256, SM5>>>((const __half*)pt1, pwt, 25, 0, 0,
                               rb2, nullptr, nullptr,
                               nullptr, nullptr, nullptr,
                               pxb, nullptr, nullptr, N_NODES, 128, 1 | 4);

    cudaMemsetAsync(d_out, 0, sizeof(float));
    readout_final<<<(N_NODES + 255) / 256, 256>>>(pxb, rw3, rb3, (float*)d_out);
}